// round 3
// baseline (speedup 1.0000x reference)
#include <cuda_runtime.h>
#include <math.h>

// ---------------------------------------------------------------------------
// Problem dims
// ---------------------------------------------------------------------------
static constexpr int B_  = 2;
static constexpr int T_  = 1024;
static constexpr int E_  = 512;
static constexpr int H_  = 8;
static constexpr int L_  = 4;
static constexpr int NT_ = 32000;
static constexpr int FF_ = 2048;
static constexpr int BT_ = B_ * T_;        // 2048
static constexpr int HE_ = H_ * E_;        // 4096
static constexpr long LOGITS_N = (long)BT_ * NT_;  // 65,536,000
static constexpr long BNT_T    = (long)NT_ * T_;   // 32,768,000 (per-batch logits block)

// ---------------------------------------------------------------------------
// Scratch (device globals; no allocation allowed)
// ---------------------------------------------------------------------------
__device__ float g_h   [BT_ * E_];
__device__ float g_tmp [BT_ * E_];
__device__ float g_q   [BT_ * HE_];
__device__ float g_k   [BT_ * HE_];
__device__ float g_v   [BT_ * HE_];
__device__ float g_o   [BT_ * HE_];
__device__ float g_att [(size_t)B_ * H_ * T_ * T_];   // 16.8M floats
__device__ float g_ff  [BT_ * FF_];
__device__ float g_logits[(size_t)BT_ * NT_];          // 262 MB
__device__ float g_pm  [BT_ * 4];
__device__ float g_ps  [BT_ * 4];
__device__ float g_z   [BT_];

// ---------------------------------------------------------------------------
// Generic tiled SGEMM: C = alpha * A @ op(B) + bias, optional relu.
// 128x128 block tile, BK=16, 256 threads, 8x8 per thread, register prefetch.
// Batched via blockIdx.z with (outer, inner) stride decomposition:
//   offset = (bz / innerCnt) * sOuter + (bz % innerCnt) * sInner
// Requires M%128==0, N%128==0, K%16==0, all leading dims %4==0.
// causal!=0 skips tiles strictly above the diagonal (BM==BN==128).
// ---------------------------------------------------------------------------
template<bool TRANSB>
__global__ __launch_bounds__(256)
void gemm_f32(int M, int N, int K,
              const float* __restrict__ A, int lda,
              const float* __restrict__ Bm, int ldb,
              float* __restrict__ C, int ldc,
              const float* __restrict__ bias,
              float alpha, int doRelu, int causal,
              int innerCnt,
              long aO, long aI, long bO, long bI, long cO, long cI)
{
    const int bx = blockIdx.x, by = blockIdx.y;
    if (causal && bx > by) return;
    {
        const int bz = blockIdx.z;
        const int oz = bz / innerCnt;
        const int iz = bz - oz * innerCnt;
        A  += (long)oz * aO + (long)iz * aI;
        Bm += (long)oz * bO + (long)iz * bI;
        C  += (long)oz * cO + (long)iz * cI;
    }

    __shared__ float As[16][132];
    __shared__ float Bs[16][132];

    const int tid  = threadIdx.x;
    const int arow = tid >> 2;           // 0..63 (second vector: +64)
    const int akv  = (tid & 3) << 2;     // k offset 0,4,8,12
    const float* Ap = A + (long)(by * 128 + arow) * lda + akv;

    const float* Bp;
    int b_r0, b_c0;
    if (TRANSB) {            // B is (N x K) row-major; need Bs[k][n]
        b_r0 = tid >> 2;             // n-row 0..63 (+64)
        b_c0 = (tid & 3) << 2;       // k offset
        Bp = Bm + (long)(bx * 128 + b_r0) * ldb + b_c0;
    } else {                 // B is (K x N) row-major
        b_r0 = tid >> 5;             // k-row 0..7 (+8)
        b_c0 = (tid & 31) << 2;      // n offset 0..124
        Bp = Bm + (long)b_r0 * ldb + (bx * 128 + b_c0);
    }

    float acc[8][8];
#pragma unroll
    for (int i = 0; i < 8; ++i)
#pragma unroll
        for (int j = 0; j < 8; ++j) acc[i][j] = 0.f;

    float4 ra0, ra1, rb0, rb1;

    auto g_load = [&]() {
        ra0 = *(const float4*)(Ap);
        ra1 = *(const float4*)(Ap + (long)64 * lda);
        if (TRANSB) {
            rb0 = *(const float4*)(Bp);
            rb1 = *(const float4*)(Bp + (long)64 * ldb);
        } else {
            rb0 = *(const float4*)(Bp);
            rb1 = *(const float4*)(Bp + (long)8 * ldb);
        }
    };
    auto s_store = [&]() {
        As[akv + 0][arow]      = ra0.x;
        As[akv + 1][arow]      = ra0.y;
        As[akv + 2][arow]      = ra0.z;
        As[akv + 3][arow]      = ra0.w;
        As[akv + 0][arow + 64] = ra1.x;
        As[akv + 1][arow + 64] = ra1.y;
        As[akv + 2][arow + 64] = ra1.z;
        As[akv + 3][arow + 64] = ra1.w;
        if (TRANSB) {
            Bs[b_c0 + 0][b_r0]      = rb0.x;
            Bs[b_c0 + 1][b_r0]      = rb0.y;
            Bs[b_c0 + 2][b_r0]      = rb0.z;
            Bs[b_c0 + 3][b_r0]      = rb0.w;
            Bs[b_c0 + 0][b_r0 + 64] = rb1.x;
            Bs[b_c0 + 1][b_r0 + 64] = rb1.y;
            Bs[b_c0 + 2][b_r0 + 64] = rb1.z;
            Bs[b_c0 + 3][b_r0 + 64] = rb1.w;
        } else {
            *(float4*)&Bs[b_r0][b_c0]     = rb0;
            *(float4*)&Bs[b_r0 + 8][b_c0] = rb1;
        }
    };

    const int tx = tid & 15, ty = tid >> 4;
    const int m0 = ty << 2, n0 = tx << 2;

    auto compute = [&]() {
#pragma unroll
        for (int k = 0; k < 16; ++k) {
            float4 a0 = *(const float4*)&As[k][m0];
            float4 a1 = *(const float4*)&As[k][m0 + 64];
            float4 b0 = *(const float4*)&Bs[k][n0];
            float4 b1 = *(const float4*)&Bs[k][n0 + 64];
            float av[8] = {a0.x, a0.y, a0.z, a0.w, a1.x, a1.y, a1.z, a1.w};
            float bv[8] = {b0.x, b0.y, b0.z, b0.w, b1.x, b1.y, b1.z, b1.w};
#pragma unroll
            for (int i = 0; i < 8; ++i)
#pragma unroll
                for (int j = 0; j < 8; ++j)
                    acc[i][j] = fmaf(av[i], bv[j], acc[i][j]);
        }
    };

    g_load();
    s_store();
    __syncthreads();

    const int ntiles = K >> 4;
    for (int t = 1; t < ntiles; ++t) {
        Ap += 16;
        if (TRANSB) Bp += 16; else Bp += (long)16 * ldb;
        g_load();            // prefetch next tile into registers
        compute();           // compute on current smem tile
        __syncthreads();
        s_store();
        __syncthreads();
    }
    compute();

    // epilogue
    float bvv[8];
#pragma unroll
    for (int j = 0; j < 8; ++j) {
        int n = bx * 128 + n0 + ((j < 4) ? j : (64 + j - 4));
        bvv[j] = bias ? bias[n] : 0.f;
    }
#pragma unroll
    for (int i = 0; i < 8; ++i) {
        int m = by * 128 + m0 + ((i < 4) ? i : (64 + i - 4));
        float vals[8];
#pragma unroll
        for (int j = 0; j < 8; ++j) {
            float v = fmaf(acc[i][j], alpha, bvv[j]);
            vals[j] = doRelu ? fmaxf(v, 0.f) : v;
        }
        float* Cp = C + (long)m * ldc + bx * 128;
        *(float4*)(Cp + n0)      = make_float4(vals[0], vals[1], vals[2], vals[3]);
        *(float4*)(Cp + n0 + 64) = make_float4(vals[4], vals[5], vals[6], vals[7]);
    }
}

// ---------------------------------------------------------------------------
// Embedding: h[bt,e] = tok_emb[x[bt],e] + pos_emb[t,e]
// ---------------------------------------------------------------------------
__global__ void embed_kernel(const int* __restrict__ x,
                             const float* __restrict__ tok,
                             const float* __restrict__ pos,
                             float* __restrict__ h)
{
    int idx = blockIdx.x * 256 + threadIdx.x;   // over BT_*E_ = 1,048,576
    int bt  = idx >> 9;
    int e   = idx & 511;
    int token = x[bt];
    h[idx] = tok[(long)token * E_ + e] + pos[((bt & (T_ - 1)) << 9) + e];
}

// ---------------------------------------------------------------------------
// Causal softmax over attention scores, in place.
// One block (128 thr) per row (bh, i). Writes zeros for j > i.
// ---------------------------------------------------------------------------
__global__ void softmax_causal_kernel(float* __restrict__ att)
{
    const int i = blockIdx.x & (T_ - 1);
    float* row = att + (long)blockIdx.x * T_;
    const int n = i + 1;
    const int tid = threadIdx.x, lane = tid & 31, w = tid >> 5;
    __shared__ float redm[4], reds[4];

    float mx = -INFINITY;
    for (int j = tid; j < n; j += 128) mx = fmaxf(mx, row[j]);
#pragma unroll
    for (int o = 16; o > 0; o >>= 1) mx = fmaxf(mx, __shfl_xor_sync(0xffffffffu, mx, o));
    if (lane == 0) redm[w] = mx;
    __syncthreads();
    mx = fmaxf(fmaxf(redm[0], redm[1]), fmaxf(redm[2], redm[3]));

    float s = 0.f;
    for (int j = tid; j < n; j += 128) s += expf(row[j] - mx);
#pragma unroll
    for (int o = 16; o > 0; o >>= 1) s += __shfl_xor_sync(0xffffffffu, s, o);
    if (lane == 0) reds[w] = s;
    __syncthreads();
    s = reds[0] + reds[1] + reds[2] + reds[3];

    const float inv = 1.f / s;
    for (int j = tid; j < T_; j += 128)
        row[j] = (j < n) ? expf(row[j] - mx) * inv : 0.f;
}

// ---------------------------------------------------------------------------
// Residual add + LayerNorm, writes back into h. One block (128 thr) per row.
// ---------------------------------------------------------------------------
__global__ void add_ln_kernel(const float* __restrict__ a,
                              float* __restrict__ h,
                              const float* __restrict__ gam,
                              const float* __restrict__ bet)
{
    const long row = blockIdx.x;
    const float* ar = a + row * E_;
    float* hr = h + row * E_;
    const int tid = threadIdx.x, lane = tid & 31, w = tid >> 5;
    __shared__ float r1[4], r2[4];

    float x[4];
    float s = 0.f;
#pragma unroll
    for (int i = 0; i < 4; ++i) {
        int e = tid + i * 128;
        x[i] = ar[e] + hr[e];
        s += x[i];
    }
#pragma unroll
    for (int o = 16; o > 0; o >>= 1) s += __shfl_xor_sync(0xffffffffu, s, o);
    if (lane == 0) r1[w] = s;
    __syncthreads();
    const float m = (r1[0] + r1[1] + r1[2] + r1[3]) * (1.f / E_);

    float d2 = 0.f;
#pragma unroll
    for (int i = 0; i < 4; ++i) { float d = x[i] - m; d2 += d * d; }
#pragma unroll
    for (int o = 16; o > 0; o >>= 1) d2 += __shfl_xor_sync(0xffffffffu, d2, o);
    if (lane == 0) r2[w] = d2;
    __syncthreads();
    const float var = (r2[0] + r2[1] + r2[2] + r2[3]) * (1.f / E_);
    const float r = rsqrtf(var + 1e-5f);

#pragma unroll
    for (int i = 0; i < 4; ++i) {
        int e = tid + i * 128;
        hr[e] = (x[i] - m) * r * gam[e] + bet[e];
    }
}

// ---------------------------------------------------------------------------
// emb_mean / emb_max over T. Grid (B_, E_/32), block 256 (32 lanes x 8).
// ---------------------------------------------------------------------------
__global__ void emb_stats_kernel(const float* __restrict__ h,
                                 float* __restrict__ omean,
                                 float* __restrict__ omax)
{
    const int b = blockIdx.x, e = blockIdx.y * 32 + (threadIdx.x & 31);
    const int lane = threadIdx.x & 31, wy = threadIdx.x >> 5;
    __shared__ float ss[8][32], sm[8][32];
    float s = 0.f, m = -INFINITY;
    for (int t = wy; t < T_; t += 8) {
        float v = h[((long)(b * T_ + t)) * E_ + e];
        s += v; m = fmaxf(m, v);
    }
    ss[wy][lane] = s; sm[wy][lane] = m;
    __syncthreads();
    if (wy == 0) {
        float S = 0.f, M = -INFINITY;
#pragma unroll
        for (int w = 0; w < 8; ++w) { S += ss[w][lane]; M = fmaxf(M, sm[w][lane]); }
        omean[b * E_ + e] = S * (1.f / T_);
        omax [b * E_ + e] = M;
    }
}

// ---------------------------------------------------------------------------
// log_softmax over axis-1 of the raw-reshaped (B, NT, T) view:
// group (b,t) walks flat index b*NT*T + n*T + t, n = 0..NT-1.
// Stage 1: partial (max, sum) over n-quarters, lanes coalesced along t.
// ---------------------------------------------------------------------------
__global__ void ls_partial_kernel(const float* __restrict__ logits,
                                  float* __restrict__ pm,
                                  float* __restrict__ ps)
{
    const int split = blockIdx.x & 3;
    const int tcol  = blockIdx.x >> 2;                 // 0..63
    const int b     = tcol >> 5;
    const int lane  = threadIdx.x & 31, wy = threadIdx.x >> 5;
    const int t     = ((tcol & 31) << 5) + lane;
    const long base = (long)b * BNT_T + t;

    float mx = -INFINITY, s = 0.f;
    const int n0 = split * (NT_ / 4);
#pragma unroll 4
    for (int n = n0 + wy; n < n0 + NT_ / 4; n += 8) {
        float v = logits[base + (long)n * T_];
        if (v > mx) { s = s * __expf(mx - v) + 1.f; mx = v; }
        else        { s += __expf(v - mx); }
    }
    __shared__ float shm[8][32], shs[8][32];
    shm[wy][lane] = mx; shs[wy][lane] = s;
    __syncthreads();
    if (wy == 0) {
        float M = -INFINITY, S = 0.f;
#pragma unroll
        for (int w = 0; w < 8; ++w) {
            float m2 = shm[w][lane], s2 = shs[w][lane];
            if (m2 > M) { S = S * __expf(M - m2) + s2; M = m2; }
            else        { S += s2 * __expf(m2 - M); }
        }
        int idx = b * T_ + t;
        pm[idx * 4 + split] = M;
        ps[idx * 4 + split] = S;
    }
}

__global__ void ls_combine_kernel(const float* __restrict__ pm,
                                  const float* __restrict__ ps,
                                  float* __restrict__ z)
{
    int idx = blockIdx.x * 256 + threadIdx.x;
    if (idx >= BT_) return;
    float M = -INFINITY, S = 0.f;
#pragma unroll
    for (int k = 0; k < 4; ++k) {
        float m2 = pm[idx * 4 + k], s2 = ps[idx * 4 + k];
        if (m2 > M) { S = S * expf(M - m2) + s2; M = m2; }
        else        { S += s2 * expf(m2 - M); }
    }
    z[idx] = M + logf(S);
}

__global__ void ls_write_kernel(const float* __restrict__ logits,
                                const float* __restrict__ z,
                                float* __restrict__ out)
{
    long i4 = (long)blockIdx.x * 256 + threadIdx.x;   // float4 index
    long f  = i4 << 2;
    int  t  = (int)(f & (T_ - 1));                    // BNT_T % T_ == 0
    int  b  = (f >= BNT_T) ? 1 : 0;
    float4 v  = *(const float4*)(logits + f);
    float4 zz = *(const float4*)(z + b * T_ + t);
    float4 o;
    o.x = v.x - zz.x; o.y = v.y - zz.y; o.z = v.z - zz.z; o.w = v.w - zz.w;
    *(float4*)(out + f) = o;
}

// ---------------------------------------------------------------------------
// Host-side launch helper
// ---------------------------------------------------------------------------
static inline void gemm(bool transB, int M, int N, int K,
                        const float* A, int lda, const float* Bm, int ldb,
                        float* C, int ldc, const float* bias,
                        float alpha, int relu, int causal,
                        int batches = 1, int innerCnt = 1,
                        long aO = 0, long aI = 0, long bO = 0, long bI = 0,
                        long cO = 0, long cI = 0)
{
    dim3 grid(N / 128, M / 128, batches), blk(256);
    if (transB)
        gemm_f32<true><<<grid, blk>>>(M, N, K, A, lda, Bm, ldb, C, ldc, bias,
                                      alpha, relu, causal, innerCnt,
                                      aO, aI, bO, bI, cO, cI);
    else
        gemm_f32<false><<<grid, blk>>>(M, N, K, A, lda, Bm, ldb, C, ldc, bias,
                                       alpha, relu, causal, innerCnt,
                                       aO, aI, bO, bI, cO, cI);
}

extern "C" void kernel_launch(void* const* d_in, const int* in_sizes, int n_in,
                              void* d_out, int out_size)
{
    const int*   x    = (const int*)  d_in[0];
    const float* tok  = (const float*)d_in[1];
    const float* pos  = (const float*)d_in[2];
    const float* Wq   = (const float*)d_in[3];
    const float* Wk   = (const float*)d_in[4];
    const float* Wv   = (const float*)d_in[5];
    const float* Wu   = (const float*)d_in[6];
    const float* bu   = (const float*)d_in[7];
    const float* g1   = (const float*)d_in[8];
    const float* b1n  = (const float*)d_in[9];
    const float* g2   = (const float*)d_in[10];
    const float* b2n  = (const float*)d_in[11];
    const float* W1   = (const float*)d_in[12];
    const float* bf1  = (const float*)d_in[13];
    const float* W2   = (const float*)d_in[14];
    const float* bf2  = (const float*)d_in[15];
    const float* Wp   = (const float*)d_in[16];
    const float* bp   = (const float*)d_in[17];
    float* out = (float*)d_out;

    float *h, *tmp, *q, *k, *v, *o, *att, *ff, *logits, *pm, *ps, *z;
    cudaGetSymbolAddress((void**)&h,      g_h);
    cudaGetSymbolAddress((void**)&tmp,    g_tmp);
    cudaGetSymbolAddress((void**)&q,      g_q);
    cudaGetSymbolAddress((void**)&k,      g_k);
    cudaGetSymbolAddress((void**)&v,      g_v);
    cudaGetSymbolAddress((void**)&o,      g_o);
    cudaGetSymbolAddress((void**)&att,    g_att);
    cudaGetSymbolAddress((void**)&ff,     g_ff);
    cudaGetSymbolAddress((void**)&logits, g_logits);
    cudaGetSymbolAddress((void**)&pm,     g_pm);
    cudaGetSymbolAddress((void**)&ps,     g_ps);
    cudaGetSymbolAddress((void**)&z,      g_z);

    embed_kernel<<<(BT_ * E_) / 256, 256>>>(x, tok, pos, h);

    const float qs = 0.21022410381342863f;   // 512^(-1/4): q and k each scaled

    for (int l = 0; l < L_; ++l) {
        const float* Wq_l  = Wq  + (long)l * E_ * HE_;
        const float* Wk_l  = Wk  + (long)l * E_ * HE_;
        const float* Wv_l  = Wv  + (long)l * E_ * HE_;
        const float* Wu_l  = Wu  + (long)l * HE_ * E_;
        const float* bu_l  = bu  + (long)l * E_;
        const float* g1_l  = g1  + (long)l * E_;
        const float* b1_l  = b1n + (long)l * E_;
        const float* g2_l  = g2  + (long)l * E_;
        const float* b2_l  = b2n + (long)l * E_;
        const float* W1_l  = W1  + (long)l * E_ * FF_;
        const float* bf1_l = bf1 + (long)l * FF_;
        const float* W2_l  = W2  + (long)l * FF_ * E_;
        const float* bf2_l = bf2 + (long)l * E_;

        // q, k (scaled), v projections: (2048,512)@(512,4096)
        gemm(false, BT_, HE_, E_, h, E_, Wq_l, HE_, q, HE_, nullptr, qs,  0, 0);
        gemm(false, BT_, HE_, E_, h, E_, Wk_l, HE_, k, HE_, nullptr, qs,  0, 0);
        gemm(false, BT_, HE_, E_, h, E_, Wv_l, HE_, v, HE_, nullptr, 1.f, 0, 0);

        // scores: per (b,h): S = q_bh @ k_bh^T, causal tiles only
        gemm(true, T_, T_, E_, q, HE_, k, HE_, att, T_, nullptr, 1.f, 0, 1,
             B_ * H_, H_,
             (long)T_ * HE_, E_,           // A: per-b, per-h offsets into q
             (long)T_ * HE_, E_,           // B: same for k
             (long)H_ * T_ * T_, (long)T_ * T_);

        softmax_causal_kernel<<<B_ * H_ * T_, 128>>>(att);

        // o = att @ v (per head, zeros above diagonal make full GEMM exact)
        gemm(false, T_, E_, T_, att, T_, v, HE_, o, HE_, nullptr, 1.f, 0, 0,
             B_ * H_, H_,
             (long)H_ * T_ * T_, (long)T_ * T_,
             (long)T_ * HE_, E_,
             (long)T_ * HE_, E_);

        // unify heads + bias
        gemm(false, BT_, E_, HE_, o, HE_, Wu_l, E_, tmp, E_, bu_l, 1.f, 0, 0);
        add_ln_kernel<<<BT_, 128>>>(tmp, h, g1_l, b1_l);

        // FFN
        gemm(false, BT_, FF_, E_, h, E_, W1_l, FF_, ff, FF_, bf1_l, 1.f, 1, 0);
        gemm(false, BT_, E_, FF_, ff, FF_, W2_l, E_, tmp, E_, bf2_l, 1.f, 0, 0);
        add_ln_kernel<<<BT_, 128>>>(tmp, h, g2_l, b2_l);
    }

    // emb_mean / emb_max (flattened after the log_softmax block)
    if ((long)out_size >= LOGITS_N + 2L * B_ * E_) {
        emb_stats_kernel<<<dim3(B_, E_ / 32), 256>>>(
            h, out + LOGITS_N, out + LOGITS_N + B_ * E_);
    }

    // vocab projection: (2048,512)@(512,32000) + bp
    gemm(false, BT_, NT_, E_, h, E_, Wp, NT_, logits, NT_, bp, 1.f, 0, 0);

    // log_softmax over axis 1 of the raw (B, NT, T) reshape
    ls_partial_kernel<<<256, 256>>>(logits, pm, ps);
    ls_combine_kernel<<<(BT_ + 255) / 256, 256>>>(pm, ps, z);
    ls_write_kernel<<<(int)(LOGITS_N / 4 / 256), 256>>>(logits, z, out);
}

// round 5
// speedup vs baseline: 1.2992x; 1.2992x over previous
#include <cuda_runtime.h>
#include <math.h>
#include <stdint.h>

// Arch-specific gate: tcgen05 PTX is only legal on sm_103a (the 'a' target).
// The harness also compiles a portable compute_103 pass; that pass gets the
// FFMA fallback below instead.
#if defined(__CUDA_ARCH__) && (__CUDA_ARCH__ >= 1000) && \
    (defined(__CUDA_ARCH_FEAT_SM103_ALL) || defined(__CUDA_ARCH_SPECIFIC__) || \
     defined(__CUDA_ARCH_FEAT_SM100_ALL))
#define TC_OK 1
#else
#define TC_OK 0
#endif

// ---------------------------------------------------------------------------
// Problem dims
// ---------------------------------------------------------------------------
static constexpr int B_  = 2;
static constexpr int T_  = 1024;
static constexpr int E_  = 512;
static constexpr int H_  = 8;
static constexpr int L_  = 4;
static constexpr int NT_ = 32000;
static constexpr int FF_ = 2048;
static constexpr int BT_ = B_ * T_;        // 2048
static constexpr int HE_ = H_ * E_;        // 4096
static constexpr long LOGITS_N = (long)BT_ * NT_;  // 65,536,000
static constexpr long BNT_T    = (long)NT_ * T_;   // per-batch logits block

// ---------------------------------------------------------------------------
// Scratch (device globals; no allocation allowed)
// ---------------------------------------------------------------------------
__device__ float g_h   [BT_ * E_];
__device__ float g_tmp [BT_ * E_];
__device__ float g_q   [BT_ * HE_];
__device__ float g_k   [BT_ * HE_];
__device__ float g_vt  [(size_t)HE_ * BT_];           // V transposed (HE x BT)
__device__ float g_o   [BT_ * HE_];
__device__ float g_att [(size_t)B_ * H_ * T_ * T_];
__device__ float g_ff  [BT_ * FF_];
__device__ float g_logits[(size_t)BT_ * NT_];
__device__ float g_pm  [BT_ * 4];
__device__ float g_ps  [BT_ * 4];
__device__ float g_z   [BT_];

// Transposed weights (recomputed every launch; deterministic)
__device__ float g_WqT[(size_t)L_ * HE_ * E_];
__device__ float g_WkT[(size_t)L_ * HE_ * E_];
__device__ float g_WvT[(size_t)L_ * HE_ * E_];
__device__ float g_WuT[(size_t)L_ * E_ * HE_];
__device__ float g_W1T[(size_t)L_ * FF_ * E_];
__device__ float g_W2T[(size_t)L_ * E_ * FF_];
__device__ float g_WpT[(size_t)NT_ * E_];

// ---------------------------------------------------------------------------
// PTX helpers (tcgen05 ones only referenced inside the TC_OK branch)
// ---------------------------------------------------------------------------
__device__ __forceinline__ uint32_t smem_u32(const void* p) {
    uint32_t a;
    asm("{ .reg .u64 t; cvta.to.shared.u64 t, %1; cvt.u32.u64 %0, t; }"
        : "=r"(a) : "l"(p));
    return a;
}

#if TC_OK
__device__ __forceinline__ int elect1() {
    uint32_t p;
    asm volatile("{\n .reg .pred p;\n elect.sync _|p, 0xFFFFFFFF;\n selp.b32 %0,1,0,p;\n}"
                 : "=r"(p));
    return (int)p;
}
__device__ __forceinline__ float tf32r(float x) {
    uint32_t u; asm("cvt.rna.tf32.f32 %0, %1;" : "=r"(u) : "f"(x));
    return __uint_as_float(u);
}
__device__ __forceinline__ uint64_t mkdesc(uint32_t addr) {
    // SW128, version=1 (Blackwell), SBO=64, LBO=1 : K-major 128B-row tiles
    const uint64_t base = (uint64_t(2) << 61) | (uint64_t(1) << 46)
                        | (uint64_t(64) << 32) | (uint64_t(1) << 16);
    return base | ((uint64_t)(addr >> 4) & 0x3FFF);
}
__device__ __forceinline__ void mbar_wait(uint32_t mbar, int parity) {
    asm volatile(
        "{\n\t.reg .pred P;\n\t"
        "W_%=:\n\t"
        "mbarrier.try_wait.parity.acquire.cta.shared::cta.b64 P, [%0], %1, 0x989680;\n\t"
        "@P bra.uni D_%=;\n\t"
        "bra.uni W_%=;\n\t"
        "D_%=:\n\t}"
        :: "r"(mbar), "r"(parity) : "memory");
}
__device__ __forceinline__ void mma_tf32(uint32_t d, uint64_t ad, uint64_t bd,
                                         uint32_t idesc, uint32_t en) {
    asm volatile(
        "{\n .reg .pred p;\n setp.ne.u32 p, %4, 0;\n"
        " tcgen05.mma.cta_group::1.kind::tf32 [%0], %1, %2, %3, {%5,%5,%5,%5}, p;\n}"
        :: "r"(d), "l"(ad), "l"(bd), "r"(idesc), "r"(en), "r"(0u) : "memory");
}

#define LDTM_X32(r, addr) \
    asm volatile( \
        "tcgen05.ld.sync.aligned.32x32b.x32.b32 " \
        "{%0, %1, %2, %3, %4, %5, %6, %7, " \
        " %8, %9, %10, %11, %12, %13, %14, %15, " \
        " %16, %17, %18, %19, %20, %21, %22, %23, " \
        " %24, %25, %26, %27, %28, %29, %30, %31}, [%32];" \
        : "=r"((r)[0]),  "=r"((r)[1]),  "=r"((r)[2]),  "=r"((r)[3]), \
          "=r"((r)[4]),  "=r"((r)[5]),  "=r"((r)[6]),  "=r"((r)[7]), \
          "=r"((r)[8]),  "=r"((r)[9]),  "=r"((r)[10]), "=r"((r)[11]), \
          "=r"((r)[12]), "=r"((r)[13]), "=r"((r)[14]), "=r"((r)[15]), \
          "=r"((r)[16]), "=r"((r)[17]), "=r"((r)[18]), "=r"((r)[19]), \
          "=r"((r)[20]), "=r"((r)[21]), "=r"((r)[22]), "=r"((r)[23]), \
          "=r"((r)[24]), "=r"((r)[25]), "=r"((r)[26]), "=r"((r)[27]), \
          "=r"((r)[28]), "=r"((r)[29]), "=r"((r)[30]), "=r"((r)[31]) \
        : "r"(addr))
#endif  // TC_OK

// idesc: dtype=F32(1<<4), atype=TF32(2<<7), btype=TF32(2<<10), N=128(16<<17), M=128(8<<24)
static constexpr uint32_t IDESC_TF32 =
    (1u << 4) | (2u << 7) | (2u << 10) | (16u << 17) | (8u << 24);

// SMEM layout (tcgen05 path): [0] tmem ptr, [16]/[24] mbarriers,
// A tiles at 1024 (+ (s*2+part)*16KB), B tiles at 66560.
static constexpr int SM_A = 1024;
static constexpr int SM_B = 1024 + 4 * 16384;         // 66560
static constexpr int SMEM_BYTES = SM_B + 4 * 16384;   // 132096

// ---------------------------------------------------------------------------
// NT-GEMM: C[m][n] = alpha * sum_k A[m][k] * B[n][k] + bias[n]  (+relu)
// A: (M x K) row-major, B: (N x K) row-major. 128x128 tile per CTA.
// tcgen05 tf32 3x-split path on sm_103a; FFMA fallback otherwise.
// Requires M,N % 128 == 0, K % 32 == 0 (fallback: K % 16 == 0).
// causal!=0 skips tiles strictly above the diagonal.
// Batched via blockIdx.z: offset = (bz/innerCnt)*sO + (bz%innerCnt)*sI.
// ---------------------------------------------------------------------------
__global__ __launch_bounds__(256, 1)
void gemm_tc(int K,
             const float* __restrict__ A, int lda,
             const float* __restrict__ Bm, int ldb,
             float* __restrict__ C, int ldc,
             const float* __restrict__ bias,
             float alpha, int doRelu, int causal, int innerCnt,
             long aO, long aI, long bO, long bI, long cO, long cI)
{
    const int bx = blockIdx.x, by = blockIdx.y;
    if (causal && bx > by) return;
    {
        const int bz = blockIdx.z;
        const int oz = bz / innerCnt, iz = bz - oz * innerCnt;
        A  += (long)oz * aO + (long)iz * aI;
        Bm += (long)oz * bO + (long)iz * bI;
        C  += (long)oz * cO + (long)iz * cI;
    }
    extern __shared__ char smem[];
    const int tid = threadIdx.x;

#if TC_OK
    const uint32_t sb = smem_u32(smem);
    const int wid = tid >> 5, lane = tid & 31;

    if (wid == 0) {
        asm volatile("tcgen05.alloc.cta_group::1.sync.aligned.shared::cta.b32 [%0], %1;"
                     :: "r"(sb), "r"(128u) : "memory");
        asm volatile("tcgen05.relinquish_alloc_permit.cta_group::1.sync.aligned;");
    }
    if (tid == 0) {
        asm volatile("mbarrier.init.shared.b64 [%0], 1;" :: "r"(sb + 16) : "memory");
        asm volatile("mbarrier.init.shared.b64 [%0], 1;" :: "r"(sb + 24) : "memory");
    }
    __syncthreads();
    uint32_t tmem;
    asm volatile("ld.shared.b32 %0, [%1];" : "=r"(tmem) : "r"(sb));

    const float* Ap = A  + (long)(by * 128) * lda;
    const float* Bp = Bm + (long)(bx * 128) * ldb;

    int ph0 = 0, ph1 = 0;
    const int nch = K >> 5;
    for (int c2 = 0; c2 < nch; ++c2) {
        const int s = c2 & 1;
        if (c2 >= 2) {
            if (s == 0) { mbar_wait(sb + 16, ph0); ph0 ^= 1; }
            else        { mbar_wait(sb + 24, ph1); ph1 ^= 1; }
        }
        const long kc = (long)c2 << 5;
        const uint32_t aoff = (uint32_t)SM_A + (uint32_t)(s * 2) * 16384u;
        const uint32_t boff = (uint32_t)SM_B + (uint32_t)(s * 2) * 16384u;

        float4 va[4], vb[4];
        int rr[4], cc[4];
#pragma unroll
        for (int i = 0; i < 4; ++i) {
            int f = tid + i * 256;
            rr[i] = f >> 3;
            cc[i] = (f & 7) << 2;
            va[i] = *(const float4*)(Ap + (long)rr[i] * lda + kc + cc[i]);
            vb[i] = *(const float4*)(Bp + (long)rr[i] * ldb + kc + cc[i]);
        }
#pragma unroll
        for (int i = 0; i < 4; ++i) {
            uint32_t off = (uint32_t)(rr[i] * 128 + cc[i] * 4);
            uint32_t sw  = off ^ ((off >> 3) & 0x70u);
            float4 h4, l4;
            h4.x = tf32r(va[i].x); l4.x = tf32r(va[i].x - h4.x);
            h4.y = tf32r(va[i].y); l4.y = tf32r(va[i].y - h4.y);
            h4.z = tf32r(va[i].z); l4.z = tf32r(va[i].z - h4.z);
            h4.w = tf32r(va[i].w); l4.w = tf32r(va[i].w - h4.w);
            *(float4*)(smem + aoff + sw)         = h4;
            *(float4*)(smem + aoff + 16384 + sw) = l4;
            h4.x = tf32r(vb[i].x); l4.x = tf32r(vb[i].x - h4.x);
            h4.y = tf32r(vb[i].y); l4.y = tf32r(vb[i].y - h4.y);
            h4.z = tf32r(vb[i].z); l4.z = tf32r(vb[i].z - h4.z);
            h4.w = tf32r(vb[i].w); l4.w = tf32r(vb[i].w - h4.w);
            *(float4*)(smem + boff + sw)         = h4;
            *(float4*)(smem + boff + 16384 + sw) = l4;
        }
        asm volatile("fence.proxy.async.shared::cta;" ::: "memory");
        __syncthreads();

        if (wid == 0 && elect1()) {
            uint64_t dAh = mkdesc(sb + aoff), dBh = mkdesc(sb + boff);
            uint64_t dAl = dAh + 1024, dBl = dBh + 1024;   // +16384B in 16B units
#pragma unroll
            for (int ks = 0; ks < 4; ++ks) {
                uint64_t o = (uint64_t)(ks * 2);           // +32B per K=8 step
                mma_tf32(tmem, dAh + o, dBh + o, IDESC_TF32, (c2 == 0 && ks == 0) ? 0u : 1u);
                mma_tf32(tmem, dAh + o, dBl + o, IDESC_TF32, 1u);
                mma_tf32(tmem, dAl + o, dBh + o, IDESC_TF32, 1u);
            }
            asm volatile(
                "tcgen05.commit.cta_group::1.mbarrier::arrive::one.shared::cluster.b64 [%0];"
                :: "r"(sb + 16 + 8 * s) : "memory");
        }
    }
    {
        const int s = (nch - 1) & 1;
        if (s == 0) mbar_wait(sb + 16, ph0);
        else        mbar_wait(sb + 24, ph1);
    }
    asm volatile("tcgen05.fence::after_thread_sync;" ::: "memory");

    // Epilogue: warps 0-3 read D cols 0..63, warps 4-7 cols 64..127.
    const int sub = wid & 3, half = wid >> 2;
    const uint32_t woff = (uint32_t)sub << 21;
    const int m = by * 128 + sub * 32 + lane;
    const float* bp2 = bias ? (bias + (long)bx * 128) : nullptr;
#pragma unroll
    for (int blk = 0; blk < 2; ++blk) {
        const int c0 = half * 64 + blk * 32;
        uint32_t r[32];
        LDTM_X32(r, tmem + woff + (uint32_t)c0);
        asm volatile("tcgen05.wait::ld.sync.aligned;" ::: "memory");
        float* Cp = C + (long)m * ldc + bx * 128 + c0;
#pragma unroll
        for (int j = 0; j < 8; ++j) {
            float4 bv = make_float4(0.f, 0.f, 0.f, 0.f);
            if (bp2) bv = *(const float4*)(bp2 + c0 + j * 4);
            float4 o;
            o.x = fmaf(__uint_as_float(r[j * 4 + 0]), alpha, bv.x);
            o.y = fmaf(__uint_as_float(r[j * 4 + 1]), alpha, bv.y);
            o.z = fmaf(__uint_as_float(r[j * 4 + 2]), alpha, bv.z);
            o.w = fmaf(__uint_as_float(r[j * 4 + 3]), alpha, bv.w);
            if (doRelu) {
                o.x = fmaxf(o.x, 0.f); o.y = fmaxf(o.y, 0.f);
                o.z = fmaxf(o.z, 0.f); o.w = fmaxf(o.w, 0.f);
            }
            *(float4*)(Cp + j * 4) = o;
        }
    }
    __syncthreads();
    if (wid == 0) {
        asm volatile("tcgen05.dealloc.cta_group::1.sync.aligned.b32 %0, %1;"
                     :: "r"(tmem), "r"(128u));
    }

#else  // ------- FFMA fallback (portable target): round-3 NT SGEMM -------

    float (*As)[132] = (float(*)[132])(smem);
    float (*Bs)[132] = (float(*)[132])(smem + 16 * 132 * sizeof(float));

    const int arow = tid >> 2;           // 0..63 (second vector: +64)
    const int akv  = (tid & 3) << 2;     // k offset 0,4,8,12
    const float* Ap = A  + (long)(by * 128 + arow) * lda + akv;
    const float* Bp = Bm + (long)(bx * 128 + arow) * ldb + akv;

    float acc[8][8];
#pragma unroll
    for (int i = 0; i < 8; ++i)
#pragma unroll
        for (int j = 0; j < 8; ++j) acc[i][j] = 0.f;

    float4 ra0, ra1, rb0, rb1;
    auto g_load = [&]() {
        ra0 = *(const float4*)(Ap);
        ra1 = *(const float4*)(Ap + (long)64 * lda);
        rb0 = *(const float4*)(Bp);
        rb1 = *(const float4*)(Bp + (long)64 * ldb);
    };
    auto s_store = [&]() {
        As[akv + 0][arow]      = ra0.x; As[akv + 1][arow]      = ra0.y;
        As[akv + 2][arow]      = ra0.z; As[akv + 3][arow]      = ra0.w;
        As[akv + 0][arow + 64] = ra1.x; As[akv + 1][arow + 64] = ra1.y;
        As[akv + 2][arow + 64] = ra1.z; As[akv + 3][arow + 64] = ra1.w;
        Bs[akv + 0][arow]      = rb0.x; Bs[akv + 1][arow]      = rb0.y;
        Bs[akv + 2][arow]      = rb0.z; Bs[akv + 3][arow]      = rb0.w;
        Bs[akv + 0][arow + 64] = rb1.x; Bs[akv + 1][arow + 64] = rb1.y;
        Bs[akv + 2][arow + 64] = rb1.z; Bs[akv + 3][arow + 64] = rb1.w;
    };

    const int tx = tid & 15, ty = tid >> 4;
    const int m0 = ty << 2, n0 = tx << 2;
    auto compute = [&]() {
#pragma unroll
        for (int k = 0; k < 16; ++k) {
            float4 a0 = *(const float4*)&As[k][m0];
            float4 a1 = *(const float4*)&As[k][m0 + 64];
            float4 b0 = *(const float4*)&Bs[k][n0];
            float4 b1 = *(const float4*)&Bs[k][n0 + 64];
            float av[8] = {a0.x, a0.y, a0.z, a0.w, a1.x, a1.y, a1.z, a1.w};
            float bv[8] = {b0.x, b0.y, b0.z, b0.w, b1.x, b1.y, b1.z, b1.w};
#pragma unroll
            for (int i = 0; i < 8; ++i)
#pragma unroll
                for (int j = 0; j < 8; ++j)
                    acc[i][j] = fmaf(av[i], bv[j], acc[i][j]);
        }
    };

    g_load(); s_store();
    __syncthreads();
    const int ntiles = K >> 4;
    for (int t = 1; t < ntiles; ++t) {
        Ap += 16; Bp += 16;
        g_load();
        compute();
        __syncthreads();
        s_store();
        __syncthreads();
    }
    compute();

    float bvv[8];
#pragma unroll
    for (int j = 0; j < 8; ++j) {
        int n = bx * 128 + n0 + ((j < 4) ? j : (64 + j - 4));
        bvv[j] = bias ? bias[n] : 0.f;
    }
#pragma unroll
    for (int i = 0; i < 8; ++i) {
        int m = by * 128 + m0 + ((i < 4) ? i : (64 + i - 4));
        float vals[8];
#pragma unroll
        for (int j = 0; j < 8; ++j) {
            float v = fmaf(acc[i][j], alpha, bvv[j]);
            vals[j] = doRelu ? fmaxf(v, 0.f) : v;
        }
        float* Cp = C + (long)m * ldc + bx * 128;
        *(float4*)(Cp + n0)      = make_float4(vals[0], vals[1], vals[2], vals[3]);
        *(float4*)(Cp + n0 + 64) = make_float4(vals[4], vals[5], vals[6], vals[7]);
    }
#endif  // TC_OK
}

// ---------------------------------------------------------------------------
// 32x32 tiled transpose: out (C x R) = in (R x C)^T
// ---------------------------------------------------------------------------
__global__ void transpose_k(const float* __restrict__ in, float* __restrict__ out,
                            int R, int Cc)
{
    __shared__ float t[32][33];
    const int c0 = blockIdx.x * 32, r0 = blockIdx.y * 32;
    const int x = threadIdx.x, y = threadIdx.y;
#pragma unroll
    for (int i = 0; i < 32; i += 8)
        t[y + i][x] = in[(long)(r0 + y + i) * Cc + c0 + x];
    __syncthreads();
#pragma unroll
    for (int i = 0; i < 32; i += 8)
        out[(long)(c0 + y + i) * R + r0 + x] = t[x][y + i];
}

// ---------------------------------------------------------------------------
// Elementwise kernels
// ---------------------------------------------------------------------------
__global__ void embed_kernel(const int* __restrict__ x,
                             const float* __restrict__ tok,
                             const float* __restrict__ pos,
                             float* __restrict__ h)
{
    int idx = blockIdx.x * 256 + threadIdx.x;
    int bt  = idx >> 9;
    int e   = idx & 511;
    int token = x[bt];
    h[idx] = tok[(long)token * E_ + e] + pos[((bt & (T_ - 1)) << 9) + e];
}

__global__ void softmax_causal_kernel(float* __restrict__ att)
{
    const int i = blockIdx.x & (T_ - 1);
    float* row = att + (long)blockIdx.x * T_;
    const int n = i + 1;
    const int tid = threadIdx.x, lane = tid & 31, w = tid >> 5;
    __shared__ float redm[4], reds[4];

    float mx = -INFINITY;
    for (int j = tid; j < n; j += 128) mx = fmaxf(mx, row[j]);
#pragma unroll
    for (int o = 16; o > 0; o >>= 1) mx = fmaxf(mx, __shfl_xor_sync(0xffffffffu, mx, o));
    if (lane == 0) redm[w] = mx;
    __syncthreads();
    mx = fmaxf(fmaxf(redm[0], redm[1]), fmaxf(redm[2], redm[3]));

    float s = 0.f;
    for (int j = tid; j < n; j += 128) s += expf(row[j] - mx);
#pragma unroll
    for (int o = 16; o > 0; o >>= 1) s += __shfl_xor_sync(0xffffffffu, s, o);
    if (lane == 0) reds[w] = s;
    __syncthreads();
    s = reds[0] + reds[1] + reds[2] + reds[3];

    const float inv = 1.f / s;
    for (int j = tid; j < T_; j += 128)
        row[j] = (j < n) ? expf(row[j] - mx) * inv : 0.f;
}

__global__ void add_ln_kernel(const float* __restrict__ a,
                              float* __restrict__ h,
                              const float* __restrict__ gam,
                              const float* __restrict__ bet)
{
    const long row = blockIdx.x;
    const float* ar = a + row * E_;
    float* hr = h + row * E_;
    const int tid = threadIdx.x, lane = tid & 31, w = tid >> 5;
    __shared__ float r1[4], r2[4];

    float x[4];
    float s = 0.f;
#pragma unroll
    for (int i = 0; i < 4; ++i) {
        int e = tid + i * 128;
        x[i] = ar[e] + hr[e];
        s += x[i];
    }
#pragma unroll
    for (int o = 16; o > 0; o >>= 1) s += __shfl_xor_sync(0xffffffffu, s, o);
    if (lane == 0) r1[w] = s;
    __syncthreads();
    const float m = (r1[0] + r1[1] + r1[2] + r1[3]) * (1.f / E_);

    float d2 = 0.f;
#pragma unroll
    for (int i = 0; i < 4; ++i) { float d = x[i] - m; d2 += d * d; }
#pragma unroll
    for (int o = 16; o > 0; o >>= 1) d2 += __shfl_xor_sync(0xffffffffu, d2, o);
    if (lane == 0) r2[w] = d2;
    __syncthreads();
    const float var = (r2[0] + r2[1] + r2[2] + r2[3]) * (1.f / E_);
    const float r = rsqrtf(var + 1e-5f);

#pragma unroll
    for (int i = 0; i < 4; ++i) {
        int e = tid + i * 128;
        hr[e] = (x[i] - m) * r * gam[e] + bet[e];
    }
}

__global__ void emb_stats_kernel(const float* __restrict__ h,
                                 float* __restrict__ omean,
                                 float* __restrict__ omax)
{
    const int b = blockIdx.x, e = blockIdx.y * 32 + (threadIdx.x & 31);
    const int lane = threadIdx.x & 31, wy = threadIdx.x >> 5;
    __shared__ float ss[8][32], sm[8][32];
    float s = 0.f, m = -INFINITY;
    for (int t = wy; t < T_; t += 8) {
        float v = h[((long)(b * T_ + t)) * E_ + e];
        s += v; m = fmaxf(m, v);
    }
    ss[wy][lane] = s; sm[wy][lane] = m;
    __syncthreads();
    if (wy == 0) {
        float S = 0.f, M = -INFINITY;
#pragma unroll
        for (int w = 0; w < 8; ++w) { S += ss[w][lane]; M = fmaxf(M, sm[w][lane]); }
        omean[b * E_ + e] = S * (1.f / T_);
        omax [b * E_ + e] = M;
    }
}

__global__ void ls_partial_kernel(const float* __restrict__ logits,
                                  float* __restrict__ pm,
                                  float* __restrict__ ps)
{
    const int split = blockIdx.x & 3;
    const int tcol  = blockIdx.x >> 2;
    const int b     = tcol >> 5;
    const int lane  = threadIdx.x & 31, wy = threadIdx.x >> 5;
    const int t     = ((tcol & 31) << 5) + lane;
    const long base = (long)b * BNT_T + t;

    float mx = -INFINITY, s = 0.f;
    const int n0 = split * (NT_ / 4);
#pragma unroll 4
    for (int n = n0 + wy; n < n0 + NT_ / 4; n += 8) {
        float v = logits[base + (long)n * T_];
        if (v > mx) { s = s * __expf(mx - v) + 1.f; mx = v; }
        else        { s += __expf(v - mx); }
    }
    __shared__ float shm[8][32], shs[8][32];
    shm[wy][lane] = mx; shs[wy][lane] = s;
    __syncthreads();
    if (wy == 0) {
        float M = -INFINITY, S = 0.f;
#pragma unroll
        for (int w = 0; w < 8; ++w) {
            float m2 = shm[w][lane], s2 = shs[w][lane];
            if (m2 > M) { S = S * __expf(M - m2) + s2; M = m2; }
            else        { S += s2 * __expf(m2 - M); }
        }
        int idx = b * T_ + t;
        pm[idx * 4 + split] = M;
        ps[idx * 4 + split] = S;
    }
}

__global__ void ls_combine_kernel(const float* __restrict__ pm,
                                  const float* __restrict__ ps,
                                  float* __restrict__ z)
{
    int idx = blockIdx.x * 256 + threadIdx.x;
    if (idx >= BT_) return;
    float M = -INFINITY, S = 0.f;
#pragma unroll
    for (int k = 0; k < 4; ++k) {
        float m2 = pm[idx * 4 + k], s2 = ps[idx * 4 + k];
        if (m2 > M) { S = S * expf(M - m2) + s2; M = m2; }
        else        { S += s2 * expf(m2 - M); }
    }
    z[idx] = M + logf(S);
}

__global__ void ls_write_kernel(const float* __restrict__ logits,
                                const float* __restrict__ z,
                                float* __restrict__ out)
{
    long i4 = (long)blockIdx.x * 256 + threadIdx.x;
    long f  = i4 << 2;
    int  t  = (int)(f & (T_ - 1));
    int  b  = (f >= BNT_T) ? 1 : 0;
    float4 v  = *(const float4*)(logits + f);
    float4 zz = *(const float4*)(z + b * T_ + t);
    float4 o;
    o.x = v.x - zz.x; o.y = v.y - zz.y; o.z = v.z - zz.z; o.w = v.w - zz.w;
    *(float4*)(out + f) = o;
}

// ---------------------------------------------------------------------------
// Host-side launch helpers
// ---------------------------------------------------------------------------
static inline void gemm(int Mtiles, int Ntiles, int K,
                        const float* A, int lda, const float* Bm, int ldb,
                        float* C, int ldc, const float* bias,
                        float alpha, int relu, int causal,
                        int batches = 1, int innerCnt = 1,
                        long aO = 0, long aI = 0, long bO = 0, long bI = 0,
                        long cO = 0, long cI = 0)
{
    dim3 grid(Ntiles, Mtiles, batches), blk(256);
    gemm_tc<<<grid, blk, SMEM_BYTES>>>(K, A, lda, Bm, ldb, C, ldc, bias,
                                       alpha, relu, causal, innerCnt,
                                       aO, aI, bO, bI, cO, cI);
}

static inline void transp(const float* in, float* out, int R, int C)
{
    dim3 g(C / 32, R / 32), b(32, 8);
    transpose_k<<<g, b>>>(in, out, R, C);
}

extern "C" void kernel_launch(void* const* d_in, const int* in_sizes, int n_in,
                              void* d_out, int out_size)
{
    const int*   x    = (const int*)  d_in[0];
    const float* tok  = (const float*)d_in[1];
    const float* pos  = (const float*)d_in[2];
    const float* Wq   = (const float*)d_in[3];
    const float* Wk   = (const float*)d_in[4];
    const float* Wv   = (const float*)d_in[5];
    const float* Wu   = (const float*)d_in[6];
    const float* bu   = (const float*)d_in[7];
    const float* g1   = (const float*)d_in[8];
    const float* b1n  = (const float*)d_in[9];
    const float* g2   = (const float*)d_in[10];
    const float* b2n  = (const float*)d_in[11];
    const float* W1   = (const float*)d_in[12];
    const float* bf1  = (const float*)d_in[13];
    const float* W2   = (const float*)d_in[14];
    const float* bf2  = (const float*)d_in[15];
    const float* Wp   = (const float*)d_in[16];
    const float* bp   = (const float*)d_in[17];
    float* out = (float*)d_out;

    cudaFuncSetAttribute(gemm_tc, cudaFuncAttributeMaxDynamicSharedMemorySize,
                         SMEM_BYTES);

    float *h, *tmp, *q, *k, *vt, *o, *att, *ff, *logits, *pm, *ps, *z;
    float *WqT, *WkT, *WvT, *WuT, *W1T, *W2T, *WpT;
    cudaGetSymbolAddress((void**)&h,      g_h);
    cudaGetSymbolAddress((void**)&tmp,    g_tmp);
    cudaGetSymbolAddress((void**)&q,      g_q);
    cudaGetSymbolAddress((void**)&k,      g_k);
    cudaGetSymbolAddress((void**)&vt,     g_vt);
    cudaGetSymbolAddress((void**)&o,      g_o);
    cudaGetSymbolAddress((void**)&att,    g_att);
    cudaGetSymbolAddress((void**)&ff,     g_ff);
    cudaGetSymbolAddress((void**)&logits, g_logits);
    cudaGetSymbolAddress((void**)&pm,     g_pm);
    cudaGetSymbolAddress((void**)&ps,     g_ps);
    cudaGetSymbolAddress((void**)&z,      g_z);
    cudaGetSymbolAddress((void**)&WqT,    g_WqT);
    cudaGetSymbolAddress((void**)&WkT,    g_WkT);
    cudaGetSymbolAddress((void**)&WvT,    g_WvT);
    cudaGetSymbolAddress((void**)&WuT,    g_WuT);
    cudaGetSymbolAddress((void**)&W1T,    g_W1T);
    cudaGetSymbolAddress((void**)&W2T,    g_W2T);
    cudaGetSymbolAddress((void**)&WpT,    g_WpT);

    // Weight transposes (all GEMMs become NT form with K-major operands)
    for (int l = 0; l < L_; ++l) {
        transp(Wq + (long)l * E_ * HE_, WqT + (long)l * HE_ * E_, E_,  HE_);
        transp(Wk + (long)l * E_ * HE_, WkT + (long)l * HE_ * E_, E_,  HE_);
        transp(Wv + (long)l * E_ * HE_, WvT + (long)l * HE_ * E_, E_,  HE_);
        transp(Wu + (long)l * HE_ * E_, WuT + (long)l * E_ * HE_, HE_, E_);
        transp(W1 + (long)l * E_ * FF_, W1T + (long)l * FF_ * E_, E_,  FF_);
        transp(W2 + (long)l * FF_ * E_, W2T + (long)l * E_ * FF_, FF_, E_);
    }
    transp(Wp, WpT, E_, NT_);

    embed_kernel<<<(BT_ * E_) / 256, 256>>>(x, tok, pos, h);

    const float qs = 0.21022410381342863f;   // 512^(-1/4)

    for (int l = 0; l < L_; ++l) {
        const float* WqT_l = WqT + (long)l * HE_ * E_;
        const float* WkT_l = WkT + (long)l * HE_ * E_;
        const float* WvT_l = WvT + (long)l * HE_ * E_;
        const float* WuT_l = WuT + (long)l * E_ * HE_;
        const float* W1T_l = W1T + (long)l * FF_ * E_;
        const float* W2T_l = W2T + (long)l * E_ * FF_;
        const float* bu_l  = bu  + (long)l * E_;
        const float* g1_l  = g1  + (long)l * E_;
        const float* b1_l  = b1n + (long)l * E_;
        const float* g2_l  = g2  + (long)l * E_;
        const float* b2_l  = b2n + (long)l * E_;
        const float* bf1_l = bf1 + (long)l * FF_;
        const float* bf2_l = bf2 + (long)l * E_;

        // q = qs * h @ Wq ; k = qs * h @ Wk   (2048 x 4096, K=512)
        gemm(16, 32, E_, h, E_, WqT_l, E_, q, HE_, nullptr, qs, 0, 0);
        gemm(16, 32, E_, h, E_, WkT_l, E_, k, HE_, nullptr, qs, 0, 0);
        // Vt (HE x BT) = Wv^T @ h^T  => NT: A=WvT (HE x E), B=h (BT x E)
        gemm(32, 16, E_, WvT_l, E_, h, E_, vt, BT_, nullptr, 1.f, 0, 0);

        // scores: per (b,h): att = q_bh @ k_bh^T  (causal tile skip)
        gemm(8, 8, E_, q, HE_, k, HE_, att, T_, nullptr, 1.f, 0, 1,
             B_ * H_, H_,
             (long)T_ * HE_, (long)E_,
             (long)T_ * HE_, (long)E_,
             (long)H_ * T_ * T_, (long)T_ * T_);

        softmax_causal_kernel<<<B_ * H_ * T_, 128>>>(att);

        // o = att @ V : NT with B = Vt head slice (E x T per (b,h))
        gemm(8, 4, T_, att, T_, vt, BT_, o, HE_, nullptr, 1.f, 0, 0,
             B_ * H_, H_,
             (long)H_ * T_ * T_, (long)T_ * T_,
             (long)T_,           (long)E_ * BT_,
             (long)T_ * HE_,     (long)E_);

        // unify heads + bias
        gemm(16, 4, HE_, o, HE_, WuT_l, HE_, tmp, E_, bu_l, 1.f, 0, 0);
        add_ln_kernel<<<BT_, 128>>>(tmp, h, g1_l, b1_l);

        // FFN
        gemm(16, 16, E_, h, E_, W1T_l, E_, ff, FF_, bf1_l, 1.f, 1, 0);
        gemm(16, 4, FF_, ff, FF_, W2T_l, FF_, tmp, E_, bf2_l, 1.f, 0, 0);
        add_ln_kernel<<<BT_, 128>>>(tmp, h, g2_l, b2_l);
    }

    // emb_mean / emb_max (flattened after the log_softmax block)
    if ((long)out_size >= LOGITS_N + 2L * B_ * E_) {
        emb_stats_kernel<<<dim3(B_, E_ / 32), 256>>>(
            h, out + LOGITS_N, out + LOGITS_N + B_ * E_);
    }

    // vocab projection: (2048,512) @ (512,32000) + bp
    gemm(16, NT_ / 128, E_, h, E_, WpT, E_, logits, NT_, bp, 1.f, 0, 0);

    // log_softmax over axis 1 of the raw (B, NT, T) reshape
    ls_partial_kernel<<<256, 256>>>(logits, pm, ps);
    ls_combine_kernel<<<(BT_ + 255) / 256, 256>>>(pm, ps, z);
    ls_write_kernel<<<(int)(LOGITS_N / 4 / 256), 256>>>(logits, z, out);
}

// round 6
// speedup vs baseline: 1.6671x; 1.2832x over previous
#include <cuda_runtime.h>
#include <math.h>
#include <stdint.h>

// Arch gate: tcgen05 PTX is only legal on the sm_103a arch-specific target.
#if defined(__CUDA_ARCH__) && (__CUDA_ARCH__ >= 1000) && \
    (defined(__CUDA_ARCH_FEAT_SM103_ALL) || defined(__CUDA_ARCH_SPECIFIC__) || \
     defined(__CUDA_ARCH_FEAT_SM100_ALL))
#define TC_OK 1
#else
#define TC_OK 0
#endif

// ---------------------------------------------------------------------------
// Problem dims
// ---------------------------------------------------------------------------
static constexpr int B_  = 2;
static constexpr int T_  = 1024;
static constexpr int E_  = 512;
static constexpr int H_  = 8;
static constexpr int L_  = 4;
static constexpr int NT_ = 32000;
static constexpr int FF_ = 2048;
static constexpr int BT_ = B_ * T_;        // 2048
static constexpr int HE_ = H_ * E_;        // 4096
static constexpr long LOGITS_N = (long)BT_ * NT_;
static constexpr long BNT_T    = (long)NT_ * T_;

// ---------------------------------------------------------------------------
// Scratch (device globals; no allocation allowed).
// GEMM operands live as pre-split hi/lo planes (identical layouts).
// ---------------------------------------------------------------------------
__device__ float g_h    [BT_ * E_];
__device__ float g_h_hi [BT_ * E_];
__device__ float g_h_lo [BT_ * E_];
__device__ float g_tmp  [BT_ * E_];
__device__ float g_q_hi [BT_ * HE_];
__device__ float g_q_lo [BT_ * HE_];
__device__ float g_k_hi [BT_ * HE_];
__device__ float g_k_lo [BT_ * HE_];
__device__ float g_vt_hi[(size_t)HE_ * BT_];
__device__ float g_vt_lo[(size_t)HE_ * BT_];
__device__ float g_o_hi [BT_ * HE_];
__device__ float g_o_lo [BT_ * HE_];
__device__ float g_att  [(size_t)B_ * H_ * T_ * T_];
__device__ float g_at_hi[(size_t)B_ * H_ * T_ * T_];
__device__ float g_at_lo[(size_t)B_ * H_ * T_ * T_];
__device__ float g_ff_hi[BT_ * FF_];
__device__ float g_ff_lo[BT_ * FF_];
__device__ float g_logits[(size_t)BT_ * NT_];
__device__ float g_pm   [BT_ * 4];
__device__ float g_ps   [BT_ * 4];
__device__ float g_z    [BT_];

// Transposed, pre-split weights
__device__ float g_WqT_hi[(size_t)L_ * HE_ * E_];
__device__ float g_WqT_lo[(size_t)L_ * HE_ * E_];
__device__ float g_WkT_hi[(size_t)L_ * HE_ * E_];
__device__ float g_WkT_lo[(size_t)L_ * HE_ * E_];
__device__ float g_WvT_hi[(size_t)L_ * HE_ * E_];
__device__ float g_WvT_lo[(size_t)L_ * HE_ * E_];
__device__ float g_WuT_hi[(size_t)L_ * E_ * HE_];
__device__ float g_WuT_lo[(size_t)L_ * E_ * HE_];
__device__ float g_W1T_hi[(size_t)L_ * FF_ * E_];
__device__ float g_W1T_lo[(size_t)L_ * FF_ * E_];
__device__ float g_W2T_hi[(size_t)L_ * E_ * FF_];
__device__ float g_W2T_lo[(size_t)L_ * E_ * FF_];
__device__ float g_WpT_hi[(size_t)NT_ * E_];
__device__ float g_WpT_lo[(size_t)NT_ * E_];

// ---------------------------------------------------------------------------
// Helpers
// ---------------------------------------------------------------------------
__device__ __forceinline__ uint32_t smem_u32(const void* p) {
    uint32_t a;
    asm("{ .reg .u64 t; cvta.to.shared.u64 t, %1; cvt.u32.u64 %0, t; }"
        : "=r"(a) : "l"(p));
    return a;
}
// tf32 hi/lo split: hi keeps top mantissa bits (tf32-exact), lo = exact remainder.
__device__ __forceinline__ void split2(float v, float& hi, float& lo) {
    hi = __uint_as_float(__float_as_uint(v) & 0xFFFFE000u);
    lo = v - hi;
}

#if TC_OK
__device__ __forceinline__ int elect1() {
    uint32_t p;
    asm volatile("{\n .reg .pred p;\n elect.sync _|p, 0xFFFFFFFF;\n selp.b32 %0,1,0,p;\n}"
                 : "=r"(p));
    return (int)p;
}
__device__ __forceinline__ uint64_t mkdesc(uint32_t addr) {
    const uint64_t base = (uint64_t(2) << 61) | (uint64_t(1) << 46)
                        | (uint64_t(64) << 32) | (uint64_t(1) << 16);
    return base | ((uint64_t)(addr >> 4) & 0x3FFF);
}
__device__ __forceinline__ void mbar_wait(uint32_t mbar, int parity) {
    asm volatile(
        "{\n\t.reg .pred P;\n\t"
        "W_%=:\n\t"
        "mbarrier.try_wait.parity.acquire.cta.shared::cta.b64 P, [%0], %1, 0x989680;\n\t"
        "@P bra.uni D_%=;\n\t"
        "bra.uni W_%=;\n\t"
        "D_%=:\n\t}"
        :: "r"(mbar), "r"(parity) : "memory");
}
__device__ __forceinline__ void mma_tf32(uint32_t d, uint64_t ad, uint64_t bd,
                                         uint32_t idesc, uint32_t en) {
    asm volatile(
        "{\n .reg .pred p;\n setp.ne.u32 p, %4, 0;\n"
        " tcgen05.mma.cta_group::1.kind::tf32 [%0], %1, %2, %3, {%5,%5,%5,%5}, p;\n}"
        :: "r"(d), "l"(ad), "l"(bd), "r"(idesc), "r"(en), "r"(0u) : "memory");
}

#define LDTM_X32(r, addr) \
    asm volatile( \
        "tcgen05.ld.sync.aligned.32x32b.x32.b32 " \
        "{%0, %1, %2, %3, %4, %5, %6, %7, " \
        " %8, %9, %10, %11, %12, %13, %14, %15, " \
        " %16, %17, %18, %19, %20, %21, %22, %23, " \
        " %24, %25, %26, %27, %28, %29, %30, %31}, [%32];" \
        : "=r"((r)[0]),  "=r"((r)[1]),  "=r"((r)[2]),  "=r"((r)[3]), \
          "=r"((r)[4]),  "=r"((r)[5]),  "=r"((r)[6]),  "=r"((r)[7]), \
          "=r"((r)[8]),  "=r"((r)[9]),  "=r"((r)[10]), "=r"((r)[11]), \
          "=r"((r)[12]), "=r"((r)[13]), "=r"((r)[14]), "=r"((r)[15]), \
          "=r"((r)[16]), "=r"((r)[17]), "=r"((r)[18]), "=r"((r)[19]), \
          "=r"((r)[20]), "=r"((r)[21]), "=r"((r)[22]), "=r"((r)[23]), \
          "=r"((r)[24]), "=r"((r)[25]), "=r"((r)[26]), "=r"((r)[27]), \
          "=r"((r)[28]), "=r"((r)[29]), "=r"((r)[30]), "=r"((r)[31]) \
        : "r"(addr))
#endif  // TC_OK

// idesc: dtype=F32(1<<4), atype=TF32(2<<7), btype=TF32(2<<10), N=128, M=128
static constexpr uint32_t IDESC_TF32 =
    (1u << 4) | (2u << 7) | (2u << 10) | (16u << 17) | (8u << 24);

// SMEM: [0] tmem ptr, [16]/[24] mbarriers; per stage 32KB A (hi+lo) + 32KB B.
static constexpr int SM_A = 1024;
static constexpr int SM_B = 1024 + 4 * 16384;         // 66560
static constexpr int SMEM_BYTES = SM_B + 4 * 16384;   // 132096

// ---------------------------------------------------------------------------
// NT-GEMM on pre-split planes:
//   C[m][n] = alpha * sum_k A[m][k]*B[n][k] + bias[n]   (3xTF32, fp32 acc)
// Outputs: plain C (if C != null) and/or hi/lo pair (if Ch != null).
// ---------------------------------------------------------------------------
__global__ __launch_bounds__(256, 1)
void gemm_tc(int K,
             const float* __restrict__ Ah, const float* __restrict__ Al, int lda,
             const float* __restrict__ Bh, const float* __restrict__ Bl, int ldb,
             float* __restrict__ C, float* __restrict__ Ch, float* __restrict__ Cl,
             int ldc,
             const float* __restrict__ bias,
             float alpha, int doRelu, int causal, int innerCnt,
             long aO, long aI, long bO, long bI, long cO, long cI)
{
    const int bx = blockIdx.x, by = blockIdx.y;
    if (causal && bx > by) return;
    {
        const int bz = blockIdx.z;
        const int oz = bz / innerCnt, iz = bz - oz * innerCnt;
        const long ao = (long)oz * aO + (long)iz * aI;
        const long bo = (long)oz * bO + (long)iz * bI;
        const long co = (long)oz * cO + (long)iz * cI;
        Ah += ao; Al += ao; Bh += bo; Bl += bo;
        if (C)  C  += co;
        if (Ch) { Ch += co; Cl += co; }
    }
    extern __shared__ char smem[];
    const int tid = threadIdx.x;

#if TC_OK
    const uint32_t sb = smem_u32(smem);
    const int wid = tid >> 5, lane = tid & 31;

    if (wid == 0) {
        asm volatile("tcgen05.alloc.cta_group::1.sync.aligned.shared::cta.b32 [%0], %1;"
                     :: "r"(sb), "r"(128u) : "memory");
        asm volatile("tcgen05.relinquish_alloc_permit.cta_group::1.sync.aligned;");
    }
    if (tid == 0) {
        asm volatile("mbarrier.init.shared.b64 [%0], 1;" :: "r"(sb + 16) : "memory");
        asm volatile("mbarrier.init.shared.b64 [%0], 1;" :: "r"(sb + 24) : "memory");
    }
    __syncthreads();
    uint32_t tmem;
    asm volatile("ld.shared.b32 %0, [%1];" : "=r"(tmem) : "r"(sb));

    const long arow_off = (long)(by * 128);
    const long brow_off = (long)(bx * 128);
    const float* Aph = Ah + arow_off * lda;
    const float* Apl = Al + arow_off * lda;
    const float* Bph = Bh + brow_off * ldb;
    const float* Bpl = Bl + brow_off * ldb;

    // per-thread tile coords (4 float4 per plane per chunk)
    int rr[4], cc[4];
    uint32_t sw[4];
#pragma unroll
    for (int i = 0; i < 4; ++i) {
        int f = tid + i * 256;
        rr[i] = f >> 3;
        cc[i] = (f & 7) << 2;
        uint32_t off = (uint32_t)(rr[i] * 128 + cc[i] * 4);
        sw[i] = off ^ ((off >> 3) & 0x70u);
    }

    int ph0 = 0, ph1 = 0;
    const int nch = K >> 5;
    for (int c2 = 0; c2 < nch; ++c2) {
        const int s = c2 & 1;
        if (c2 >= 2) {
            if (s == 0) { mbar_wait(sb + 16, ph0); ph0 ^= 1; }
            else        { mbar_wait(sb + 24, ph1); ph1 ^= 1; }
        }
        const long kc = (long)c2 << 5;
        const uint32_t aoff = (uint32_t)SM_A + (uint32_t)(s * 2) * 16384u;
        const uint32_t boff = (uint32_t)SM_B + (uint32_t)(s * 2) * 16384u;

        float4 vah[4], valo[4], vbh[4], vblo[4];
#pragma unroll
        for (int i = 0; i < 4; ++i) {
            const long ai = (long)rr[i] * lda + kc + cc[i];
            const long bi = (long)rr[i] * ldb + kc + cc[i];
            vah[i]  = *(const float4*)(Aph + ai);
            valo[i] = *(const float4*)(Apl + ai);
            vbh[i]  = *(const float4*)(Bph + bi);
            vblo[i] = *(const float4*)(Bpl + bi);
        }
#pragma unroll
        for (int i = 0; i < 4; ++i) {
            *(float4*)(smem + aoff + sw[i])         = vah[i];
            *(float4*)(smem + aoff + 16384 + sw[i]) = valo[i];
            *(float4*)(smem + boff + sw[i])         = vbh[i];
            *(float4*)(smem + boff + 16384 + sw[i]) = vblo[i];
        }
        asm volatile("fence.proxy.async.shared::cta;" ::: "memory");
        __syncthreads();

        if (wid == 0 && elect1()) {
            uint64_t dAh = mkdesc(sb + aoff), dBh = mkdesc(sb + boff);
            uint64_t dAl = dAh + 1024, dBl = dBh + 1024;
#pragma unroll
            for (int ks = 0; ks < 4; ++ks) {
                uint64_t o = (uint64_t)(ks * 2);
                mma_tf32(tmem, dAh + o, dBh + o, IDESC_TF32, (c2 == 0 && ks == 0) ? 0u : 1u);
                mma_tf32(tmem, dAh + o, dBl + o, IDESC_TF32, 1u);
                mma_tf32(tmem, dAl + o, dBh + o, IDESC_TF32, 1u);
            }
            asm volatile(
                "tcgen05.commit.cta_group::1.mbarrier::arrive::one.shared::cluster.b64 [%0];"
                :: "r"(sb + 16 + 8 * s) : "memory");
        }
    }
    {
        const int s = (nch - 1) & 1;
        if (s == 0) mbar_wait(sb + 16, ph0);
        else        mbar_wait(sb + 24, ph1);
    }
    asm volatile("tcgen05.fence::after_thread_sync;" ::: "memory");

    // Epilogue: warps 0-3 read D cols 0..63, warps 4-7 cols 64..127.
    const int sub = wid & 3, half = wid >> 2;
    const uint32_t woff = (uint32_t)sub << 21;
    const int m = by * 128 + sub * 32 + lane;
    const float* bp2 = bias ? (bias + (long)bx * 128) : nullptr;
#pragma unroll
    for (int blk = 0; blk < 2; ++blk) {
        const int c0 = half * 64 + blk * 32;
        uint32_t r[32];
        LDTM_X32(r, tmem + woff + (uint32_t)c0);
        asm volatile("tcgen05.wait::ld.sync.aligned;" ::: "memory");
        const long crow = (long)m * ldc + bx * 128 + c0;
#pragma unroll
        for (int j = 0; j < 8; ++j) {
            float4 bv = make_float4(0.f, 0.f, 0.f, 0.f);
            if (bp2) bv = *(const float4*)(bp2 + c0 + j * 4);
            float4 o;
            o.x = fmaf(__uint_as_float(r[j * 4 + 0]), alpha, bv.x);
            o.y = fmaf(__uint_as_float(r[j * 4 + 1]), alpha, bv.y);
            o.z = fmaf(__uint_as_float(r[j * 4 + 2]), alpha, bv.z);
            o.w = fmaf(__uint_as_float(r[j * 4 + 3]), alpha, bv.w);
            if (doRelu) {
                o.x = fmaxf(o.x, 0.f); o.y = fmaxf(o.y, 0.f);
                o.z = fmaxf(o.z, 0.f); o.w = fmaxf(o.w, 0.f);
            }
            if (C) *(float4*)(C + crow + j * 4) = o;
            if (Ch) {
                float4 h4, l4;
                split2(o.x, h4.x, l4.x); split2(o.y, h4.y, l4.y);
                split2(o.z, h4.z, l4.z); split2(o.w, h4.w, l4.w);
                *(float4*)(Ch + crow + j * 4) = h4;
                *(float4*)(Cl + crow + j * 4) = l4;
            }
        }
    }
    __syncthreads();
    if (wid == 0) {
        asm volatile("tcgen05.dealloc.cta_group::1.sync.aligned.b32 %0, %1;"
                     :: "r"(tmem), "r"(128u));
    }

#else  // ------- FFMA fallback (portable compile pass only) -------

    float (*As)[132] = (float(*)[132])(smem);
    float (*Bs)[132] = (float(*)[132])(smem + 16 * 132 * sizeof(float));

    const int arow = tid >> 2;
    const int akv  = (tid & 3) << 2;
    const float* Aph = Ah + (long)(by * 128 + arow) * lda + akv;
    const float* Apl = Al + (long)(by * 128 + arow) * lda + akv;
    const float* Bph = Bh + (long)(bx * 128 + arow) * ldb + akv;
    const float* Bpl = Bl + (long)(bx * 128 + arow) * ldb + akv;

    float acc[8][8];
#pragma unroll
    for (int i = 0; i < 8; ++i)
#pragma unroll
        for (int j = 0; j < 8; ++j) acc[i][j] = 0.f;

    const int tx = tid & 15, ty = tid >> 4;
    const int m0 = ty << 2, n0 = tx << 2;

    const int ntiles = K >> 4;
    for (int t = 0; t < ntiles; ++t) {
        float4 a0h = *(const float4*)(Aph), a0l = *(const float4*)(Apl);
        float4 a1h = *(const float4*)(Aph + (long)64 * lda);
        float4 a1l = *(const float4*)(Apl + (long)64 * lda);
        float4 b0h = *(const float4*)(Bph), b0l = *(const float4*)(Bpl);
        float4 b1h = *(const float4*)(Bph + (long)64 * ldb);
        float4 b1l = *(const float4*)(Bpl + (long)64 * ldb);
        __syncthreads();
        As[akv + 0][arow]      = a0h.x + a0l.x; As[akv + 1][arow]      = a0h.y + a0l.y;
        As[akv + 2][arow]      = a0h.z + a0l.z; As[akv + 3][arow]      = a0h.w + a0l.w;
        As[akv + 0][arow + 64] = a1h.x + a1l.x; As[akv + 1][arow + 64] = a1h.y + a1l.y;
        As[akv + 2][arow + 64] = a1h.z + a1l.z; As[akv + 3][arow + 64] = a1h.w + a1l.w;
        Bs[akv + 0][arow]      = b0h.x + b0l.x; Bs[akv + 1][arow]      = b0h.y + b0l.y;
        Bs[akv + 2][arow]      = b0h.z + b0l.z; Bs[akv + 3][arow]      = b0h.w + b0l.w;
        Bs[akv + 0][arow + 64] = b1h.x + b1l.x; Bs[akv + 1][arow + 64] = b1h.y + b1l.y;
        Bs[akv + 2][arow + 64] = b1h.z + b1l.z; Bs[akv + 3][arow + 64] = b1h.w + b1l.w;
        __syncthreads();
#pragma unroll
        for (int k = 0; k < 16; ++k) {
            float4 a0 = *(const float4*)&As[k][m0];
            float4 a1 = *(const float4*)&As[k][m0 + 64];
            float4 b0 = *(const float4*)&Bs[k][n0];
            float4 b1 = *(const float4*)&Bs[k][n0 + 64];
            float av[8] = {a0.x, a0.y, a0.z, a0.w, a1.x, a1.y, a1.z, a1.w};
            float bv[8] = {b0.x, b0.y, b0.z, b0.w, b1.x, b1.y, b1.z, b1.w};
#pragma unroll
            for (int i = 0; i < 8; ++i)
#pragma unroll
                for (int j = 0; j < 8; ++j)
                    acc[i][j] = fmaf(av[i], bv[j], acc[i][j]);
        }
        Aph += 16; Apl += 16; Bph += 16; Bpl += 16;
    }

    float bvv[8];
#pragma unroll
    for (int j = 0; j < 8; ++j) {
        int n = bx * 128 + n0 + ((j < 4) ? j : (64 + j - 4));
        bvv[j] = bias ? bias[n] : 0.f;
    }
#pragma unroll
    for (int i = 0; i < 8; ++i) {
        int m = by * 128 + m0 + ((i < 4) ? i : (64 + i - 4));
#pragma unroll
        for (int j = 0; j < 8; ++j) {
            float v = fmaf(acc[i][j], alpha, bvv[j]);
            v = doRelu ? fmaxf(v, 0.f) : v;
            int n = n0 + ((j < 4) ? j : (64 + j - 4));
            long idx = (long)m * ldc + bx * 128 + n;
            if (C) C[idx] = v;
            if (Ch) { float hi, lo; split2(v, hi, lo); Ch[idx] = hi; Cl[idx] = lo; }
        }
    }
#endif  // TC_OK
}

// ---------------------------------------------------------------------------
// 32x32 tiled transpose emitting hi/lo planes: outT (C x R) = in (R x C)^T
// ---------------------------------------------------------------------------
__global__ void transpose_k(const float* __restrict__ in,
                            float* __restrict__ oh, float* __restrict__ ol,
                            int R, int Cc)
{
    __shared__ float t[32][33];
    const int c0 = blockIdx.x * 32, r0 = blockIdx.y * 32;
    const int x = threadIdx.x, y = threadIdx.y;
#pragma unroll
    for (int i = 0; i < 32; i += 8)
        t[y + i][x] = in[(long)(r0 + y + i) * Cc + c0 + x];
    __syncthreads();
#pragma unroll
    for (int i = 0; i < 32; i += 8) {
        float v = t[x][y + i];
        float hi, lo; split2(v, hi, lo);
        long idx = (long)(c0 + y + i) * R + r0 + x;
        oh[idx] = hi; ol[idx] = lo;
    }
}

// ---------------------------------------------------------------------------
// Elementwise kernels
// ---------------------------------------------------------------------------
__global__ void embed_kernel(const int* __restrict__ x,
                             const float* __restrict__ tok,
                             const float* __restrict__ pos,
                             float* __restrict__ h,
                             float* __restrict__ hh, float* __restrict__ hl)
{
    int idx = blockIdx.x * 256 + threadIdx.x;
    int bt  = idx >> 9;
    int e   = idx & 511;
    int token = x[bt];
    float v = tok[(long)token * E_ + e] + pos[((bt & (T_ - 1)) << 9) + e];
    h[idx] = v;
    float hi, lo; split2(v, hi, lo);
    hh[idx] = hi; hl[idx] = lo;
}

// Causal softmax: reads plain scores, writes hi/lo planes (zeros above diag).
__global__ void softmax_causal_kernel(const float* __restrict__ att,
                                      float* __restrict__ ah,
                                      float* __restrict__ al)
{
    const int i = blockIdx.x & (T_ - 1);
    const long base = (long)blockIdx.x * T_;
    const float* row = att + base;
    const int n = i + 1;
    const int tid = threadIdx.x, lane = tid & 31, w = tid >> 5;
    __shared__ float redm[4], reds[4];

    float mx = -INFINITY;
    for (int j = tid; j < n; j += 128) mx = fmaxf(mx, row[j]);
#pragma unroll
    for (int o = 16; o > 0; o >>= 1) mx = fmaxf(mx, __shfl_xor_sync(0xffffffffu, mx, o));
    if (lane == 0) redm[w] = mx;
    __syncthreads();
    mx = fmaxf(fmaxf(redm[0], redm[1]), fmaxf(redm[2], redm[3]));

    float s = 0.f;
    for (int j = tid; j < n; j += 128) s += expf(row[j] - mx);
#pragma unroll
    for (int o = 16; o > 0; o >>= 1) s += __shfl_xor_sync(0xffffffffu, s, o);
    if (lane == 0) reds[w] = s;
    __syncthreads();
    s = reds[0] + reds[1] + reds[2] + reds[3];

    const float inv = 1.f / s;
    for (int j = tid; j < T_; j += 128) {
        float p = (j < n) ? expf(row[j] - mx) * inv : 0.f;
        float hi, lo; split2(p, hi, lo);
        ah[base + j] = hi; al[base + j] = lo;
    }
}

__global__ void add_ln_kernel(const float* __restrict__ a,
                              float* __restrict__ h,
                              float* __restrict__ hh, float* __restrict__ hl,
                              const float* __restrict__ gam,
                              const float* __restrict__ bet)
{
    const long row = blockIdx.x;
    const float* ar = a + row * E_;
    float* hr = h + row * E_;
    const int tid = threadIdx.x, lane = tid & 31, w = tid >> 5;
    __shared__ float r1[4], r2[4];

    float x[4];
    float s = 0.f;
#pragma unroll
    for (int i = 0; i < 4; ++i) {
        int e = tid + i * 128;
        x[i] = ar[e] + hr[e];
        s += x[i];
    }
#pragma unroll
    for (int o = 16; o > 0; o >>= 1) s += __shfl_xor_sync(0xffffffffu, s, o);
    if (lane == 0) r1[w] = s;
    __syncthreads();
    const float m = (r1[0] + r1[1] + r1[2] + r1[3]) * (1.f / E_);

    float d2 = 0.f;
#pragma unroll
    for (int i = 0; i < 4; ++i) { float d = x[i] - m; d2 += d * d; }
#pragma unroll
    for (int o = 16; o > 0; o >>= 1) d2 += __shfl_xor_sync(0xffffffffu, d2, o);
    if (lane == 0) r2[w] = d2;
    __syncthreads();
    const float var = (r2[0] + r2[1] + r2[2] + r2[3]) * (1.f / E_);
    const float r = rsqrtf(var + 1e-5f);

#pragma unroll
    for (int i = 0; i < 4; ++i) {
        int e = tid + i * 128;
        float y = (x[i] - m) * r * gam[e] + bet[e];
        hr[e] = y;
        float hi, lo; split2(y, hi, lo);
        hh[row * E_ + e] = hi; hl[row * E_ + e] = lo;
    }
}

__global__ void emb_stats_kernel(const float* __restrict__ h,
                                 float* __restrict__ omean,
                                 float* __restrict__ omax)
{
    const int b = blockIdx.x, e = blockIdx.y * 32 + (threadIdx.x & 31);
    const int lane = threadIdx.x & 31, wy = threadIdx.x >> 5;
    __shared__ float ss[8][32], sm[8][32];
    float s = 0.f, m = -INFINITY;
    for (int t = wy; t < T_; t += 8) {
        float v = h[((long)(b * T_ + t)) * E_ + e];
        s += v; m = fmaxf(m, v);
    }
    ss[wy][lane] = s; sm[wy][lane] = m;
    __syncthreads();
    if (wy == 0) {
        float S = 0.f, M = -INFINITY;
#pragma unroll
        for (int w = 0; w < 8; ++w) { S += ss[w][lane]; M = fmaxf(M, sm[w][lane]); }
        omean[b * E_ + e] = S * (1.f / T_);
        omax [b * E_ + e] = M;
    }
}

__global__ void ls_partial_kernel(const float* __restrict__ logits,
                                  float* __restrict__ pm,
                                  float* __restrict__ ps)
{
    const int split = blockIdx.x & 3;
    const int tcol  = blockIdx.x >> 2;
    const int b     = tcol >> 5;
    const int lane  = threadIdx.x & 31, wy = threadIdx.x >> 5;
    const int t     = ((tcol & 31) << 5) + lane;
    const long base = (long)b * BNT_T + t;

    float mx = -INFINITY, s = 0.f;
    const int n0 = split * (NT_ / 4);
#pragma unroll 4
    for (int n = n0 + wy; n < n0 + NT_ / 4; n += 8) {
        float v = logits[base + (long)n * T_];
        if (v > mx) { s = s * __expf(mx - v) + 1.f; mx = v; }
        else        { s += __expf(v - mx); }
    }
    __shared__ float shm[8][32], shs[8][32];
    shm[wy][lane] = mx; shs[wy][lane] = s;
    __syncthreads();
    if (wy == 0) {
        float M = -INFINITY, S = 0.f;
#pragma unroll
        for (int w = 0; w < 8; ++w) {
            float m2 = shm[w][lane], s2 = shs[w][lane];
            if (m2 > M) { S = S * __expf(M - m2) + s2; M = m2; }
            else        { S += s2 * __expf(m2 - M); }
        }
        int idx = b * T_ + t;
        pm[idx * 4 + split] = M;
        ps[idx * 4 + split] = S;
    }
}

__global__ void ls_combine_kernel(const float* __restrict__ pm,
                                  const float* __restrict__ ps,
                                  float* __restrict__ z)
{
    int idx = blockIdx.x * 256 + threadIdx.x;
    if (idx >= BT_) return;
    float M = -INFINITY, S = 0.f;
#pragma unroll
    for (int k = 0; k < 4; ++k) {
        float m2 = pm[idx * 4 + k], s2 = ps[idx * 4 + k];
        if (m2 > M) { S = S * expf(M - m2) + s2; M = m2; }
        else        { S += s2 * expf(m2 - M); }
    }
    z[idx] = M + logf(S);
}

__global__ void ls_write_kernel(const float* __restrict__ logits,
                                const float* __restrict__ z,
                                float* __restrict__ out)
{
    long i4 = (long)blockIdx.x * 256 + threadIdx.x;
    long f  = i4 << 2;
    int  t  = (int)(f & (T_ - 1));
    int  b  = (f >= BNT_T) ? 1 : 0;
    float4 v  = *(const float4*)(logits + f);
    float4 zz = *(const float4*)(z + b * T_ + t);
    float4 o;
    o.x = v.x - zz.x; o.y = v.y - zz.y; o.z = v.z - zz.z; o.w = v.w - zz.w;
    *(float4*)(out + f) = o;
}

// ---------------------------------------------------------------------------
// Host-side launch helpers
// ---------------------------------------------------------------------------
static inline void gemm(int Mtiles, int Ntiles, int K,
                        const float* Ah, const float* Al, int lda,
                        const float* Bh, const float* Bl, int ldb,
                        float* C, float* Ch, float* Cl, int ldc,
                        const float* bias,
                        float alpha, int relu, int causal,
                        int batches = 1, int innerCnt = 1,
                        long aO = 0, long aI = 0, long bO = 0, long bI = 0,
                        long cO = 0, long cI = 0)
{
    dim3 grid(Ntiles, Mtiles, batches), blk(256);
    gemm_tc<<<grid, blk, SMEM_BYTES>>>(K, Ah, Al, lda, Bh, Bl, ldb,
                                       C, Ch, Cl, ldc, bias,
                                       alpha, relu, causal, innerCnt,
                                       aO, aI, bO, bI, cO, cI);
}

static inline void transp(const float* in, float* oh, float* ol, int R, int C)
{
    dim3 g(C / 32, R / 32), b(32, 8);
    transpose_k<<<g, b>>>(in, oh, ol, R, C);
}

extern "C" void kernel_launch(void* const* d_in, const int* in_sizes, int n_in,
                              void* d_out, int out_size)
{
    const int*   x    = (const int*)  d_in[0];
    const float* tok  = (const float*)d_in[1];
    const float* pos  = (const float*)d_in[2];
    const float* Wq   = (const float*)d_in[3];
    const float* Wk   = (const float*)d_in[4];
    const float* Wv   = (const float*)d_in[5];
    const float* Wu   = (const float*)d_in[6];
    const float* bu   = (const float*)d_in[7];
    const float* g1   = (const float*)d_in[8];
    const float* b1n  = (const float*)d_in[9];
    const float* g2   = (const float*)d_in[10];
    const float* b2n  = (const float*)d_in[11];
    const float* W1   = (const float*)d_in[12];
    const float* bf1  = (const float*)d_in[13];
    const float* W2   = (const float*)d_in[14];
    const float* bf2  = (const float*)d_in[15];
    const float* Wp   = (const float*)d_in[16];
    const float* bp   = (const float*)d_in[17];
    float* out = (float*)d_out;

    cudaFuncSetAttribute(gemm_tc, cudaFuncAttributeMaxDynamicSharedMemorySize,
                         SMEM_BYTES);

    float *h, *hh, *hl, *tmp, *qh, *ql, *kh, *kl, *vth, *vtl, *oh, *ol;
    float *att, *ath, *atl, *ffh, *ffl, *logits, *pm, *ps, *z;
    cudaGetSymbolAddress((void**)&h,    g_h);
    cudaGetSymbolAddress((void**)&hh,   g_h_hi);
    cudaGetSymbolAddress((void**)&hl,   g_h_lo);
    cudaGetSymbolAddress((void**)&tmp,  g_tmp);
    cudaGetSymbolAddress((void**)&qh,   g_q_hi);
    cudaGetSymbolAddress((void**)&ql,   g_q_lo);
    cudaGetSymbolAddress((void**)&kh,   g_k_hi);
    cudaGetSymbolAddress((void**)&kl,   g_k_lo);
    cudaGetSymbolAddress((void**)&vth,  g_vt_hi);
    cudaGetSymbolAddress((void**)&vtl,  g_vt_lo);
    cudaGetSymbolAddress((void**)&oh,   g_o_hi);
    cudaGetSymbolAddress((void**)&ol,   g_o_lo);
    cudaGetSymbolAddress((void**)&att,  g_att);
    cudaGetSymbolAddress((void**)&ath,  g_at_hi);
    cudaGetSymbolAddress((void**)&atl,  g_at_lo);
    cudaGetSymbolAddress((void**)&ffh,  g_ff_hi);
    cudaGetSymbolAddress((void**)&ffl,  g_ff_lo);
    cudaGetSymbolAddress((void**)&logits, g_logits);
    cudaGetSymbolAddress((void**)&pm,   g_pm);
    cudaGetSymbolAddress((void**)&ps,   g_ps);
    cudaGetSymbolAddress((void**)&z,    g_z);

    float *WqTh, *WqTl, *WkTh, *WkTl, *WvTh, *WvTl, *WuTh, *WuTl;
    float *W1Th, *W1Tl, *W2Th, *W2Tl, *WpTh, *WpTl;
    cudaGetSymbolAddress((void**)&WqTh, g_WqT_hi);
    cudaGetSymbolAddress((void**)&WqTl, g_WqT_lo);
    cudaGetSymbolAddress((void**)&WkTh, g_WkT_hi);
    cudaGetSymbolAddress((void**)&WkTl, g_WkT_lo);
    cudaGetSymbolAddress((void**)&WvTh, g_WvT_hi);
    cudaGetSymbolAddress((void**)&WvTl, g_WvT_lo);
    cudaGetSymbolAddress((void**)&WuTh, g_WuT_hi);
    cudaGetSymbolAddress((void**)&WuTl, g_WuT_lo);
    cudaGetSymbolAddress((void**)&W1Th, g_W1T_hi);
    cudaGetSymbolAddress((void**)&W1Tl, g_W1T_lo);
    cudaGetSymbolAddress((void**)&W2Th, g_W2T_hi);
    cudaGetSymbolAddress((void**)&W2Tl, g_W2T_lo);
    cudaGetSymbolAddress((void**)&WpTh, g_WpT_hi);
    cudaGetSymbolAddress((void**)&WpTl, g_WpT_lo);

    // Weight transposes + hi/lo split (once per launch)
    for (int l = 0; l < L_; ++l) {
        transp(Wq + (long)l * E_ * HE_, WqTh + (long)l * HE_ * E_,
               WqTl + (long)l * HE_ * E_, E_,  HE_);
        transp(Wk + (long)l * E_ * HE_, WkTh + (long)l * HE_ * E_,
               WkTl + (long)l * HE_ * E_, E_,  HE_);
        transp(Wv + (long)l * E_ * HE_, WvTh + (long)l * HE_ * E_,
               WvTl + (long)l * HE_ * E_, E_,  HE_);
        transp(Wu + (long)l * HE_ * E_, WuTh + (long)l * E_ * HE_,
               WuTl + (long)l * E_ * HE_, HE_, E_);
        transp(W1 + (long)l * E_ * FF_, W1Th + (long)l * FF_ * E_,
               W1Tl + (long)l * FF_ * E_, E_,  FF_);
        transp(W2 + (long)l * FF_ * E_, W2Th + (long)l * E_ * FF_,
               W2Tl + (long)l * E_ * FF_, FF_, E_);
    }
    transp(Wp, WpTh, WpTl, E_, NT_);

    embed_kernel<<<(BT_ * E_) / 256, 256>>>(x, tok, pos, h, hh, hl);

    const float qs = 0.21022410381342863f;   // 512^(-1/4)

    for (int l = 0; l < L_; ++l) {
        const long wqo = (long)l * HE_ * E_;
        const long wuo = (long)l * E_ * HE_;
        const long w1o = (long)l * FF_ * E_;
        const long w2o = (long)l * E_ * FF_;
        const float* bu_l  = bu  + (long)l * E_;
        const float* g1_l  = g1  + (long)l * E_;
        const float* b1_l  = b1n + (long)l * E_;
        const float* g2_l  = g2  + (long)l * E_;
        const float* b2_l  = b2n + (long)l * E_;
        const float* bf1_l = bf1 + (long)l * FF_;
        const float* bf2_l = bf2 + (long)l * E_;

        // q = qs * h @ Wq ; k = qs * h @ Wk  -> pairs
        gemm(16, 32, E_, hh, hl, E_, WqTh + wqo, WqTl + wqo, E_,
             nullptr, qh, ql, HE_, nullptr, qs, 0, 0);
        gemm(16, 32, E_, hh, hl, E_, WkTh + wqo, WkTl + wqo, E_,
             nullptr, kh, kl, HE_, nullptr, qs, 0, 0);
        // Vt (HE x BT) = WvT @ h^T -> pair
        gemm(32, 16, E_, WvTh + wqo, WvTl + wqo, E_, hh, hl, E_,
             nullptr, vth, vtl, BT_, nullptr, 1.f, 0, 0);

        // scores: att = q_bh @ k_bh^T (plain), causal tile skip
        gemm(8, 8, E_, qh, ql, HE_, kh, kl, HE_,
             att, nullptr, nullptr, T_, nullptr, 1.f, 0, 1,
             B_ * H_, H_,
             (long)T_ * HE_, (long)E_,
             (long)T_ * HE_, (long)E_,
             (long)H_ * T_ * T_, (long)T_ * T_);

        softmax_causal_kernel<<<B_ * H_ * T_, 128>>>(att, ath, atl);

        // o = att @ V -> pair
        gemm(8, 4, T_, ath, atl, T_, vth, vtl, BT_,
             nullptr, oh, ol, HE_, nullptr, 1.f, 0, 0,
             B_ * H_, H_,
             (long)H_ * T_ * T_, (long)T_ * T_,
             (long)T_,           (long)E_ * BT_,
             (long)T_ * HE_,     (long)E_);

        // unify heads + bias -> plain tmp
        gemm(16, 4, HE_, oh, ol, HE_, WuTh + wuo, WuTl + wuo, HE_,
             tmp, nullptr, nullptr, E_, bu_l, 1.f, 0, 0);
        add_ln_kernel<<<BT_, 128>>>(tmp, h, hh, hl, g1_l, b1_l);

        // FFN
        gemm(16, 16, E_, hh, hl, E_, W1Th + w1o, W1Tl + w1o, E_,
             nullptr, ffh, ffl, FF_, bf1_l, 1.f, 1, 0);
        gemm(16, 4, FF_, ffh, ffl, FF_, W2Th + w2o, W2Tl + w2o, FF_,
             tmp, nullptr, nullptr, E_, bf2_l, 1.f, 0, 0);
        add_ln_kernel<<<BT_, 128>>>(tmp, h, hh, hl, g2_l, b2_l);
    }

    // emb_mean / emb_max (flattened after the log_softmax block)
    if ((long)out_size >= LOGITS_N + 2L * B_ * E_) {
        emb_stats_kernel<<<dim3(B_, E_ / 32), 256>>>(
            h, out + LOGITS_N, out + LOGITS_N + B_ * E_);
    }

    // vocab projection: (2048,512) @ (512,32000) + bp -> plain logits
    gemm(16, NT_ / 128, E_, hh, hl, E_, WpTh, WpTl, E_,
         logits, nullptr, nullptr, NT_, bp, 1.f, 0, 0);

    // log_softmax over axis 1 of the raw (B, NT, T) reshape
    ls_partial_kernel<<<256, 256>>>(logits, pm, ps);
    ls_combine_kernel<<<(BT_ + 255) / 256, 256>>>(pm, ps, z);
    ls_write_kernel<<<(int)(LOGITS_N / 4 / 256), 256>>>(logits, z, out);
}

// round 7
// speedup vs baseline: 1.7192x; 1.0313x over previous
#include <cuda_runtime.h>
#include <math.h>
#include <stdint.h>

// Arch gate: tcgen05 PTX is only legal on the sm_103a arch-specific target.
#if defined(__CUDA_ARCH__) && (__CUDA_ARCH__ >= 1000) && \
    (defined(__CUDA_ARCH_FEAT_SM103_ALL) || defined(__CUDA_ARCH_SPECIFIC__) || \
     defined(__CUDA_ARCH_FEAT_SM100_ALL))
#define TC_OK 1
#else
#define TC_OK 0
#endif

// ---------------------------------------------------------------------------
// Problem dims
// ---------------------------------------------------------------------------
static constexpr int B_  = 2;
static constexpr int T_  = 1024;
static constexpr int E_  = 512;
static constexpr int H_  = 8;
static constexpr int L_  = 4;
static constexpr int NT_ = 32000;
static constexpr int FF_ = 2048;
static constexpr int BT_ = B_ * T_;        // 2048
static constexpr int HE_ = H_ * E_;        // 4096
static constexpr long LOGITS_N = (long)BT_ * NT_;
static constexpr long BNT_T    = (long)NT_ * T_;

// ---------------------------------------------------------------------------
// Scratch (device globals; no allocation allowed).
// GEMM operands live as pre-split hi/lo planes (identical layouts).
// ---------------------------------------------------------------------------
__device__ float g_h    [BT_ * E_];
__device__ float g_h_hi [BT_ * E_];
__device__ float g_h_lo [BT_ * E_];
__device__ float g_tmp  [BT_ * E_];
__device__ float g_q_hi [BT_ * HE_];
__device__ float g_q_lo [BT_ * HE_];
__device__ float g_k_hi [BT_ * HE_];
__device__ float g_k_lo [BT_ * HE_];
__device__ float g_vt_hi[(size_t)HE_ * BT_];
__device__ float g_vt_lo[(size_t)HE_ * BT_];
__device__ float g_o_hi [BT_ * HE_];
__device__ float g_o_lo [BT_ * HE_];
__device__ float g_att  [(size_t)B_ * H_ * T_ * T_];
__device__ float g_at_hi[(size_t)B_ * H_ * T_ * T_];
__device__ float g_at_lo[(size_t)B_ * H_ * T_ * T_];
__device__ float g_ff_hi[BT_ * FF_];
__device__ float g_ff_lo[BT_ * FF_];
__device__ float g_logits[(size_t)BT_ * NT_];
__device__ float g_pm   [BT_ * 4];
__device__ float g_ps   [BT_ * 4];
__device__ float g_z    [BT_];

// Transposed, pre-split weights
__device__ float g_WqT_hi[(size_t)L_ * HE_ * E_];
__device__ float g_WqT_lo[(size_t)L_ * HE_ * E_];
__device__ float g_WkT_hi[(size_t)L_ * HE_ * E_];
__device__ float g_WkT_lo[(size_t)L_ * HE_ * E_];
__device__ float g_WvT_hi[(size_t)L_ * HE_ * E_];
__device__ float g_WvT_lo[(size_t)L_ * HE_ * E_];
__device__ float g_WuT_hi[(size_t)L_ * E_ * HE_];
__device__ float g_WuT_lo[(size_t)L_ * E_ * HE_];
__device__ float g_W1T_hi[(size_t)L_ * FF_ * E_];
__device__ float g_W1T_lo[(size_t)L_ * FF_ * E_];
__device__ float g_W2T_hi[(size_t)L_ * E_ * FF_];
__device__ float g_W2T_lo[(size_t)L_ * E_ * FF_];
__device__ float g_WpT_hi[(size_t)NT_ * E_];
__device__ float g_WpT_lo[(size_t)NT_ * E_];

// ---------------------------------------------------------------------------
// Helpers
// ---------------------------------------------------------------------------
__device__ __forceinline__ uint32_t smem_u32(const void* p) {
    uint32_t a;
    asm("{ .reg .u64 t; cvta.to.shared.u64 t, %1; cvt.u32.u64 %0, t; }"
        : "=r"(a) : "l"(p));
    return a;
}
// tf32 hi/lo split: hi keeps top mantissa bits (tf32-exact), lo = exact remainder.
__device__ __forceinline__ void split2(float v, float& hi, float& lo) {
    hi = __uint_as_float(__float_as_uint(v) & 0xFFFFE000u);
    lo = v - hi;
}

#if TC_OK
__device__ __forceinline__ int elect1() {
    uint32_t p;
    asm volatile("{\n .reg .pred p;\n elect.sync _|p, 0xFFFFFFFF;\n selp.b32 %0,1,0,p;\n}"
                 : "=r"(p));
    return (int)p;
}
__device__ __forceinline__ uint64_t mkdesc(uint32_t addr) {
    const uint64_t base = (uint64_t(2) << 61) | (uint64_t(1) << 46)
                        | (uint64_t(64) << 32) | (uint64_t(1) << 16);
    return base | ((uint64_t)(addr >> 4) & 0x3FFF);
}
__device__ __forceinline__ void mbar_wait(uint32_t mbar, int parity) {
    asm volatile(
        "{\n\t.reg .pred P;\n\t"
        "W_%=:\n\t"
        "mbarrier.try_wait.parity.acquire.cta.shared::cta.b64 P, [%0], %1, 0x989680;\n\t"
        "@P bra.uni D_%=;\n\t"
        "bra.uni W_%=;\n\t"
        "D_%=:\n\t}"
        :: "r"(mbar), "r"(parity) : "memory");
}
__device__ __forceinline__ void mma_tf32(uint32_t d, uint64_t ad, uint64_t bd,
                                         uint32_t idesc, uint32_t en) {
    asm volatile(
        "{\n .reg .pred p;\n setp.ne.u32 p, %4, 0;\n"
        " tcgen05.mma.cta_group::1.kind::tf32 [%0], %1, %2, %3, {%5,%5,%5,%5}, p;\n}"
        :: "r"(d), "l"(ad), "l"(bd), "r"(idesc), "r"(en), "r"(0u) : "memory");
}

#define LDTM_X32(r, addr) \
    asm volatile( \
        "tcgen05.ld.sync.aligned.32x32b.x32.b32 " \
        "{%0, %1, %2, %3, %4, %5, %6, %7, " \
        " %8, %9, %10, %11, %12, %13, %14, %15, " \
        " %16, %17, %18, %19, %20, %21, %22, %23, " \
        " %24, %25, %26, %27, %28, %29, %30, %31}, [%32];" \
        : "=r"((r)[0]),  "=r"((r)[1]),  "=r"((r)[2]),  "=r"((r)[3]), \
          "=r"((r)[4]),  "=r"((r)[5]),  "=r"((r)[6]),  "=r"((r)[7]), \
          "=r"((r)[8]),  "=r"((r)[9]),  "=r"((r)[10]), "=r"((r)[11]), \
          "=r"((r)[12]), "=r"((r)[13]), "=r"((r)[14]), "=r"((r)[15]), \
          "=r"((r)[16]), "=r"((r)[17]), "=r"((r)[18]), "=r"((r)[19]), \
          "=r"((r)[20]), "=r"((r)[21]), "=r"((r)[22]), "=r"((r)[23]), \
          "=r"((r)[24]), "=r"((r)[25]), "=r"((r)[26]), "=r"((r)[27]), \
          "=r"((r)[28]), "=r"((r)[29]), "=r"((r)[30]), "=r"((r)[31]) \
        : "r"(addr))
#endif  // TC_OK

// idesc: dtype=F32(1<<4), atype=TF32(2<<7), btype=TF32(2<<10), N=128, M=128
static constexpr uint32_t IDESC_TF32 =
    (1u << 4) | (2u << 7) | (2u << 10) | (16u << 17) | (8u << 24);

// SMEM: [0] tmem ptr, [16]/[24] mbarriers; per stage 32KB A (hi+lo) + 32KB B.
static constexpr int SM_A = 1024;
static constexpr int SM_B = 1024 + 4 * 16384;         // 66560
static constexpr int SMEM_BYTES = SM_B + 4 * 16384;   // 132096

// ---------------------------------------------------------------------------
// NT-GEMM on pre-split planes:
//   C[m][n] = alpha * sum_k A[m][k]*B[n][k] + bias[n]   (3xTF32, fp32 acc)
// Producer register-prefetch pipeline: LDG for chunk c+1 issued right after
// the MMA for chunk c, overlapping global latency with tensor work.
// ---------------------------------------------------------------------------
__global__ __launch_bounds__(256, 1)
void gemm_tc(int K,
             const float* __restrict__ Ah, const float* __restrict__ Al, int lda,
             const float* __restrict__ Bh, const float* __restrict__ Bl, int ldb,
             float* __restrict__ C, float* __restrict__ Ch, float* __restrict__ Cl,
             int ldc,
             const float* __restrict__ bias,
             float alpha, int doRelu, int causal, int innerCnt,
             long aO, long aI, long bO, long bI, long cO, long cI)
{
    const int bx = blockIdx.x, by = blockIdx.y;
    if (causal && bx > by) return;
    {
        const int bz = blockIdx.z;
        const int oz = bz / innerCnt, iz = bz - oz * innerCnt;
        const long ao = (long)oz * aO + (long)iz * aI;
        const long bo = (long)oz * bO + (long)iz * bI;
        const long co = (long)oz * cO + (long)iz * cI;
        Ah += ao; Al += ao; Bh += bo; Bl += bo;
        if (C)  C  += co;
        if (Ch) { Ch += co; Cl += co; }
    }
    extern __shared__ char smem[];
    const int tid = threadIdx.x;

#if TC_OK
    const uint32_t sb = smem_u32(smem);
    const int wid = tid >> 5, lane = tid & 31;

    if (wid == 0) {
        asm volatile("tcgen05.alloc.cta_group::1.sync.aligned.shared::cta.b32 [%0], %1;"
                     :: "r"(sb), "r"(128u) : "memory");
        asm volatile("tcgen05.relinquish_alloc_permit.cta_group::1.sync.aligned;");
    }
    if (tid == 0) {
        asm volatile("mbarrier.init.shared.b64 [%0], 1;" :: "r"(sb + 16) : "memory");
        asm volatile("mbarrier.init.shared.b64 [%0], 1;" :: "r"(sb + 24) : "memory");
    }

    const long arow_off = (long)(by * 128);
    const long brow_off = (long)(bx * 128);
    const float* Aph = Ah + arow_off * lda;
    const float* Apl = Al + arow_off * lda;
    const float* Bph = Bh + brow_off * ldb;
    const float* Bpl = Bl + brow_off * ldb;

    // per-thread tile coords (4 float4 per plane per chunk)
    int rr[4], cc[4];
    uint32_t sw[4];
#pragma unroll
    for (int i = 0; i < 4; ++i) {
        int f = tid + i * 256;
        rr[i] = f >> 3;
        cc[i] = (f & 7) << 2;
        uint32_t off = (uint32_t)(rr[i] * 128 + cc[i] * 4);
        sw[i] = off ^ ((off >> 3) & 0x70u);
    }

    float4 vah[4], valo[4], vbh[4], vblo[4];
    auto load_chunk = [&](int c2) {
        const long kc = (long)c2 << 5;
#pragma unroll
        for (int i = 0; i < 4; ++i) {
            const long ai = (long)rr[i] * lda + kc + cc[i];
            const long bi = (long)rr[i] * ldb + kc + cc[i];
            vah[i]  = *(const float4*)(Aph + ai);
            valo[i] = *(const float4*)(Apl + ai);
            vbh[i]  = *(const float4*)(Bph + bi);
            vblo[i] = *(const float4*)(Bpl + bi);
        }
    };

    // Prologue: start chunk-0 loads immediately (overlaps TMEM alloc / mbar init).
    load_chunk(0);
    __syncthreads();
    uint32_t tmem;
    asm volatile("ld.shared.b32 %0, [%1];" : "=r"(tmem) : "r"(sb));

    int ph0 = 0, ph1 = 0;
    const int nch = K >> 5;
    for (int c2 = 0; c2 < nch; ++c2) {
        const int s = c2 & 1;
        if (c2 >= 2) {   // buffer s reusable once MMA of chunk c2-2 committed
            if (s == 0) { mbar_wait(sb + 16, ph0); ph0 ^= 1; }
            else        { mbar_wait(sb + 24, ph1); ph1 ^= 1; }
        }
        const uint32_t aoff = (uint32_t)SM_A + (uint32_t)(s * 2) * 16384u;
        const uint32_t boff = (uint32_t)SM_B + (uint32_t)(s * 2) * 16384u;

#pragma unroll
        for (int i = 0; i < 4; ++i) {
            *(float4*)(smem + aoff + sw[i])         = vah[i];
            *(float4*)(smem + aoff + 16384 + sw[i]) = valo[i];
            *(float4*)(smem + boff + sw[i])         = vbh[i];
            *(float4*)(smem + boff + 16384 + sw[i]) = vblo[i];
        }
        asm volatile("fence.proxy.async.shared::cta;" ::: "memory");
        __syncthreads();

        if (wid == 0 && elect1()) {
            uint64_t dAh = mkdesc(sb + aoff), dBh = mkdesc(sb + boff);
            uint64_t dAl = dAh + 1024, dBl = dBh + 1024;
#pragma unroll
            for (int ks = 0; ks < 4; ++ks) {
                uint64_t o = (uint64_t)(ks * 2);
                mma_tf32(tmem, dAh + o, dBh + o, IDESC_TF32, (c2 == 0 && ks == 0) ? 0u : 1u);
                mma_tf32(tmem, dAh + o, dBl + o, IDESC_TF32, 1u);
                mma_tf32(tmem, dAl + o, dBh + o, IDESC_TF32, 1u);
            }
            asm volatile(
                "tcgen05.commit.cta_group::1.mbarrier::arrive::one.shared::cluster.b64 [%0];"
                :: "r"(sb + 16 + 8 * s) : "memory");
        }
        // Prefetch next chunk: LDG latency overlaps the MMA just issued.
        if (c2 + 1 < nch) load_chunk(c2 + 1);
    }
    {
        const int s = (nch - 1) & 1;
        if (s == 0) mbar_wait(sb + 16, ph0);
        else        mbar_wait(sb + 24, ph1);
    }
    asm volatile("tcgen05.fence::after_thread_sync;" ::: "memory");

    // Epilogue: warps 0-3 read D cols 0..63, warps 4-7 cols 64..127.
    const int sub = wid & 3, half = wid >> 2;
    const uint32_t woff = (uint32_t)sub << 21;
    const int m = by * 128 + sub * 32 + lane;
    const float* bp2 = bias ? (bias + (long)bx * 128) : nullptr;
#pragma unroll
    for (int blk = 0; blk < 2; ++blk) {
        const int c0 = half * 64 + blk * 32;
        uint32_t r[32];
        LDTM_X32(r, tmem + woff + (uint32_t)c0);
        asm volatile("tcgen05.wait::ld.sync.aligned;" ::: "memory");
        const long crow = (long)m * ldc + bx * 128 + c0;
#pragma unroll
        for (int j = 0; j < 8; ++j) {
            float4 bv = make_float4(0.f, 0.f, 0.f, 0.f);
            if (bp2) bv = *(const float4*)(bp2 + c0 + j * 4);
            float4 o;
            o.x = fmaf(__uint_as_float(r[j * 4 + 0]), alpha, bv.x);
            o.y = fmaf(__uint_as_float(r[j * 4 + 1]), alpha, bv.y);
            o.z = fmaf(__uint_as_float(r[j * 4 + 2]), alpha, bv.z);
            o.w = fmaf(__uint_as_float(r[j * 4 + 3]), alpha, bv.w);
            if (doRelu) {
                o.x = fmaxf(o.x, 0.f); o.y = fmaxf(o.y, 0.f);
                o.z = fmaxf(o.z, 0.f); o.w = fmaxf(o.w, 0.f);
            }
            if (C) *(float4*)(C + crow + j * 4) = o;
            if (Ch) {
                float4 h4, l4;
                split2(o.x, h4.x, l4.x); split2(o.y, h4.y, l4.y);
                split2(o.z, h4.z, l4.z); split2(o.w, h4.w, l4.w);
                *(float4*)(Ch + crow + j * 4) = h4;
                *(float4*)(Cl + crow + j * 4) = l4;
            }
        }
    }
    __syncthreads();
    if (wid == 0) {
        asm volatile("tcgen05.dealloc.cta_group::1.sync.aligned.b32 %0, %1;"
                     :: "r"(tmem), "r"(128u));
    }

#else  // ------- FFMA fallback (portable compile pass only) -------

    float (*As)[132] = (float(*)[132])(smem);
    float (*Bs)[132] = (float(*)[132])(smem + 16 * 132 * sizeof(float));

    const int arow = tid >> 2;
    const int akv  = (tid & 3) << 2;
    const float* Aph = Ah + (long)(by * 128 + arow) * lda + akv;
    const float* Apl = Al + (long)(by * 128 + arow) * lda + akv;
    const float* Bph = Bh + (long)(bx * 128 + arow) * ldb + akv;
    const float* Bpl = Bl + (long)(bx * 128 + arow) * ldb + akv;

    float acc[8][8];
#pragma unroll
    for (int i = 0; i < 8; ++i)
#pragma unroll
        for (int j = 0; j < 8; ++j) acc[i][j] = 0.f;

    const int tx = tid & 15, ty = tid >> 4;
    const int m0 = ty << 2, n0 = tx << 2;

    const int ntiles = K >> 4;
    for (int t = 0; t < ntiles; ++t) {
        float4 a0h = *(const float4*)(Aph), a0l = *(const float4*)(Apl);
        float4 a1h = *(const float4*)(Aph + (long)64 * lda);
        float4 a1l = *(const float4*)(Apl + (long)64 * lda);
        float4 b0h = *(const float4*)(Bph), b0l = *(const float4*)(Bpl);
        float4 b1h = *(const float4*)(Bph + (long)64 * ldb);
        float4 b1l = *(const float4*)(Bpl + (long)64 * ldb);
        __syncthreads();
        As[akv + 0][arow]      = a0h.x + a0l.x; As[akv + 1][arow]      = a0h.y + a0l.y;
        As[akv + 2][arow]      = a0h.z + a0l.z; As[akv + 3][arow]      = a0h.w + a0l.w;
        As[akv + 0][arow + 64] = a1h.x + a1l.x; As[akv + 1][arow + 64] = a1h.y + a1l.y;
        As[akv + 2][arow + 64] = a1h.z + a1l.z; As[akv + 3][arow + 64] = a1h.w + a1l.w;
        Bs[akv + 0][arow]      = b0h.x + b0l.x; Bs[akv + 1][arow]      = b0h.y + b0l.y;
        Bs[akv + 2][arow]      = b0h.z + b0l.z; Bs[akv + 3][arow]      = b0h.w + b0l.w;
        Bs[akv + 0][arow + 64] = b1h.x + b1l.x; Bs[akv + 1][arow + 64] = b1h.y + b1l.y;
        Bs[akv + 2][arow + 64] = b1h.z + b1l.z; Bs[akv + 3][arow + 64] = b1h.w + b1l.w;
        __syncthreads();
#pragma unroll
        for (int k = 0; k < 16; ++k) {
            float4 a0 = *(const float4*)&As[k][m0];
            float4 a1 = *(const float4*)&As[k][m0 + 64];
            float4 b0 = *(const float4*)&Bs[k][n0];
            float4 b1 = *(const float4*)&Bs[k][n0 + 64];
            float av[8] = {a0.x, a0.y, a0.z, a0.w, a1.x, a1.y, a1.z, a1.w};
            float bv[8] = {b0.x, b0.y, b0.z, b0.w, b1.x, b1.y, b1.z, b1.w};
#pragma unroll
            for (int i = 0; i < 8; ++i)
#pragma unroll
                for (int j = 0; j < 8; ++j)
                    acc[i][j] = fmaf(av[i], bv[j], acc[i][j]);
        }
        Aph += 16; Apl += 16; Bph += 16; Bpl += 16;
    }

    float bvv[8];
#pragma unroll
    for (int j = 0; j < 8; ++j) {
        int n = bx * 128 + n0 + ((j < 4) ? j : (64 + j - 4));
        bvv[j] = bias ? bias[n] : 0.f;
    }
#pragma unroll
    for (int i = 0; i < 8; ++i) {
        int m = by * 128 + m0 + ((i < 4) ? i : (64 + i - 4));
#pragma unroll
        for (int j = 0; j < 8; ++j) {
            float v = fmaf(acc[i][j], alpha, bvv[j]);
            v = doRelu ? fmaxf(v, 0.f) : v;
            int n = n0 + ((j < 4) ? j : (64 + j - 4));
            long idx = (long)m * ldc + bx * 128 + n;
            if (C) C[idx] = v;
            if (Ch) { float hi, lo; split2(v, hi, lo); Ch[idx] = hi; Cl[idx] = lo; }
        }
    }
#endif  // TC_OK
}

// ---------------------------------------------------------------------------
// 32x32 tiled transpose emitting hi/lo planes: outT (C x R) = in (R x C)^T
// ---------------------------------------------------------------------------
__global__ void transpose_k(const float* __restrict__ in,
                            float* __restrict__ oh, float* __restrict__ ol,
                            int R, int Cc)
{
    __shared__ float t[32][33];
    const int c0 = blockIdx.x * 32, r0 = blockIdx.y * 32;
    const int x = threadIdx.x, y = threadIdx.y;
#pragma unroll
    for (int i = 0; i < 32; i += 8)
        t[y + i][x] = in[(long)(r0 + y + i) * Cc + c0 + x];
    __syncthreads();
#pragma unroll
    for (int i = 0; i < 32; i += 8) {
        float v = t[x][y + i];
        float hi, lo; split2(v, hi, lo);
        long idx = (long)(c0 + y + i) * R + r0 + x;
        oh[idx] = hi; ol[idx] = lo;
    }
}

// ---------------------------------------------------------------------------
// Elementwise kernels
// ---------------------------------------------------------------------------
__global__ void embed_kernel(const int* __restrict__ x,
                             const float* __restrict__ tok,
                             const float* __restrict__ pos,
                             float* __restrict__ h,
                             float* __restrict__ hh, float* __restrict__ hl)
{
    int idx = blockIdx.x * 256 + threadIdx.x;
    int bt  = idx >> 9;
    int e   = idx & 511;
    int token = x[bt];
    float v = tok[(long)token * E_ + e] + pos[((bt & (T_ - 1)) << 9) + e];
    h[idx] = v;
    float hi, lo; split2(v, hi, lo);
    hh[idx] = hi; hl[idx] = lo;
}

// Causal softmax: reads plain scores, writes hi/lo planes (zeros above diag).
__global__ void softmax_causal_kernel(const float* __restrict__ att,
                                      float* __restrict__ ah,
                                      float* __restrict__ al)
{
    const int i = blockIdx.x & (T_ - 1);
    const long base = (long)blockIdx.x * T_;
    const float* row = att + base;
    const int n = i + 1;
    const int tid = threadIdx.x, lane = tid & 31, w = tid >> 5;
    __shared__ float redm[4], reds[4];

    float mx = -INFINITY;
    for (int j = tid; j < n; j += 128) mx = fmaxf(mx, row[j]);
#pragma unroll
    for (int o = 16; o > 0; o >>= 1) mx = fmaxf(mx, __shfl_xor_sync(0xffffffffu, mx, o));
    if (lane == 0) redm[w] = mx;
    __syncthreads();
    mx = fmaxf(fmaxf(redm[0], redm[1]), fmaxf(redm[2], redm[3]));

    float s = 0.f;
    for (int j = tid; j < n; j += 128) s += expf(row[j] - mx);
#pragma unroll
    for (int o = 16; o > 0; o >>= 1) s += __shfl_xor_sync(0xffffffffu, s, o);
    if (lane == 0) reds[w] = s;
    __syncthreads();
    s = reds[0] + reds[1] + reds[2] + reds[3];

    const float inv = 1.f / s;
    for (int j = tid; j < T_; j += 128) {
        float p = (j < n) ? expf(row[j] - mx) * inv : 0.f;
        float hi, lo; split2(p, hi, lo);
        ah[base + j] = hi; al[base + j] = lo;
    }
}

__global__ void add_ln_kernel(const float* __restrict__ a,
                              float* __restrict__ h,
                              float* __restrict__ hh, float* __restrict__ hl,
                              const float* __restrict__ gam,
                              const float* __restrict__ bet)
{
    const long row = blockIdx.x;
    const float* ar = a + row * E_;
    float* hr = h + row * E_;
    const int tid = threadIdx.x, lane = tid & 31, w = tid >> 5;
    __shared__ float r1[4], r2[4];

    float x[4];
    float s = 0.f;
#pragma unroll
    for (int i = 0; i < 4; ++i) {
        int e = tid + i * 128;
        x[i] = ar[e] + hr[e];
        s += x[i];
    }
#pragma unroll
    for (int o = 16; o > 0; o >>= 1) s += __shfl_xor_sync(0xffffffffu, s, o);
    if (lane == 0) r1[w] = s;
    __syncthreads();
    const float m = (r1[0] + r1[1] + r1[2] + r1[3]) * (1.f / E_);

    float d2 = 0.f;
#pragma unroll
    for (int i = 0; i < 4; ++i) { float d = x[i] - m; d2 += d * d; }
#pragma unroll
    for (int o = 16; o > 0; o >>= 1) d2 += __shfl_xor_sync(0xffffffffu, d2, o);
    if (lane == 0) r2[w] = d2;
    __syncthreads();
    const float var = (r2[0] + r2[1] + r2[2] + r2[3]) * (1.f / E_);
    const float r = rsqrtf(var + 1e-5f);

#pragma unroll
    for (int i = 0; i < 4; ++i) {
        int e = tid + i * 128;
        float y = (x[i] - m) * r * gam[e] + bet[e];
        hr[e] = y;
        float hi, lo; split2(y, hi, lo);
        hh[row * E_ + e] = hi; hl[row * E_ + e] = lo;
    }
}

__global__ void emb_stats_kernel(const float* __restrict__ h,
                                 float* __restrict__ omean,
                                 float* __restrict__ omax)
{
    const int b = blockIdx.x, e = blockIdx.y * 32 + (threadIdx.x & 31);
    const int lane = threadIdx.x & 31, wy = threadIdx.x >> 5;
    __shared__ float ss[8][32], sm[8][32];
    float s = 0.f, m = -INFINITY;
    for (int t = wy; t < T_; t += 8) {
        float v = h[((long)(b * T_ + t)) * E_ + e];
        s += v; m = fmaxf(m, v);
    }
    ss[wy][lane] = s; sm[wy][lane] = m;
    __syncthreads();
    if (wy == 0) {
        float S = 0.f, M = -INFINITY;
#pragma unroll
        for (int w = 0; w < 8; ++w) { S += ss[w][lane]; M = fmaxf(M, sm[w][lane]); }
        omean[b * E_ + e] = S * (1.f / T_);
        omax [b * E_ + e] = M;
    }
}

__global__ void ls_partial_kernel(const float* __restrict__ logits,
                                  float* __restrict__ pm,
                                  float* __restrict__ ps)
{
    const int split = blockIdx.x & 3;
    const int tcol  = blockIdx.x >> 2;
    const int b     = tcol >> 5;
    const int lane  = threadIdx.x & 31, wy = threadIdx.x >> 5;
    const int t     = ((tcol & 31) << 5) + lane;
    const long base = (long)b * BNT_T + t;

    float mx = -INFINITY, s = 0.f;
    const int n0 = split * (NT_ / 4);
#pragma unroll 4
    for (int n = n0 + wy; n < n0 + NT_ / 4; n += 8) {
        float v = logits[base + (long)n * T_];
        if (v > mx) { s = s * __expf(mx - v) + 1.f; mx = v; }
        else        { s += __expf(v - mx); }
    }
    __shared__ float shm[8][32], shs[8][32];
    shm[wy][lane] = mx; shs[wy][lane] = s;
    __syncthreads();
    if (wy == 0) {
        float M = -INFINITY, S = 0.f;
#pragma unroll
        for (int w = 0; w < 8; ++w) {
            float m2 = shm[w][lane], s2 = shs[w][lane];
            if (m2 > M) { S = S * __expf(M - m2) + s2; M = m2; }
            else        { S += s2 * __expf(m2 - M); }
        }
        int idx = b * T_ + t;
        pm[idx * 4 + split] = M;
        ps[idx * 4 + split] = S;
    }
}

__global__ void ls_combine_kernel(const float* __restrict__ pm,
                                  const float* __restrict__ ps,
                                  float* __restrict__ z)
{
    int idx = blockIdx.x * 256 + threadIdx.x;
    if (idx >= BT_) return;
    float M = -INFINITY, S = 0.f;
#pragma unroll
    for (int k = 0; k < 4; ++k) {
        float m2 = pm[idx * 4 + k], s2 = ps[idx * 4 + k];
        if (m2 > M) { S = S * expf(M - m2) + s2; M = m2; }
        else        { S += s2 * expf(m2 - M); }
    }
    z[idx] = M + logf(S);
}

__global__ void ls_write_kernel(const float* __restrict__ logits,
                                const float* __restrict__ z,
                                float* __restrict__ out)
{
    long i4 = (long)blockIdx.x * 256 + threadIdx.x;
    long f  = i4 << 2;
    int  t  = (int)(f & (T_ - 1));
    int  b  = (f >= BNT_T) ? 1 : 0;
    float4 v  = *(const float4*)(logits + f);
    float4 zz = *(const float4*)(z + b * T_ + t);
    float4 o;
    o.x = v.x - zz.x; o.y = v.y - zz.y; o.z = v.z - zz.z; o.w = v.w - zz.w;
    *(float4*)(out + f) = o;
}

// ---------------------------------------------------------------------------
// Host-side launch helpers
// ---------------------------------------------------------------------------
static inline void gemm(int Mtiles, int Ntiles, int K,
                        const float* Ah, const float* Al, int lda,
                        const float* Bh, const float* Bl, int ldb,
                        float* C, float* Ch, float* Cl, int ldc,
                        const float* bias,
                        float alpha, int relu, int causal,
                        int batches = 1, int innerCnt = 1,
                        long aO = 0, long aI = 0, long bO = 0, long bI = 0,
                        long cO = 0, long cI = 0)
{
    dim3 grid(Ntiles, Mtiles, batches), blk(256);
    gemm_tc<<<grid, blk, SMEM_BYTES>>>(K, Ah, Al, lda, Bh, Bl, ldb,
                                       C, Ch, Cl, ldc, bias,
                                       alpha, relu, causal, innerCnt,
                                       aO, aI, bO, bI, cO, cI);
}

static inline void transp(const float* in, float* oh, float* ol, int R, int C)
{
    dim3 g(C / 32, R / 32), b(32, 8);
    transpose_k<<<g, b>>>(in, oh, ol, R, C);
}

extern "C" void kernel_launch(void* const* d_in, const int* in_sizes, int n_in,
                              void* d_out, int out_size)
{
    const int*   x    = (const int*)  d_in[0];
    const float* tok  = (const float*)d_in[1];
    const float* pos  = (const float*)d_in[2];
    const float* Wq   = (const float*)d_in[3];
    const float* Wk   = (const float*)d_in[4];
    const float* Wv   = (const float*)d_in[5];
    const float* Wu   = (const float*)d_in[6];
    const float* bu   = (const float*)d_in[7];
    const float* g1   = (const float*)d_in[8];
    const float* b1n  = (const float*)d_in[9];
    const float* g2   = (const float*)d_in[10];
    const float* b2n  = (const float*)d_in[11];
    const float* W1   = (const float*)d_in[12];
    const float* bf1  = (const float*)d_in[13];
    const float* W2   = (const float*)d_in[14];
    const float* bf2  = (const float*)d_in[15];
    const float* Wp   = (const float*)d_in[16];
    const float* bp   = (const float*)d_in[17];
    float* out = (float*)d_out;

    cudaFuncSetAttribute(gemm_tc, cudaFuncAttributeMaxDynamicSharedMemorySize,
                         SMEM_BYTES);

    float *h, *hh, *hl, *tmp, *qh, *ql, *kh, *kl, *vth, *vtl, *oh, *ol;
    float *att, *ath, *atl, *ffh, *ffl, *logits, *pm, *ps, *z;
    cudaGetSymbolAddress((void**)&h,    g_h);
    cudaGetSymbolAddress((void**)&hh,   g_h_hi);
    cudaGetSymbolAddress((void**)&hl,   g_h_lo);
    cudaGetSymbolAddress((void**)&tmp,  g_tmp);
    cudaGetSymbolAddress((void**)&qh,   g_q_hi);
    cudaGetSymbolAddress((void**)&ql,   g_q_lo);
    cudaGetSymbolAddress((void**)&kh,   g_k_hi);
    cudaGetSymbolAddress((void**)&kl,   g_k_lo);
    cudaGetSymbolAddress((void**)&vth,  g_vt_hi);
    cudaGetSymbolAddress((void**)&vtl,  g_vt_lo);
    cudaGetSymbolAddress((void**)&oh,   g_o_hi);
    cudaGetSymbolAddress((void**)&ol,   g_o_lo);
    cudaGetSymbolAddress((void**)&att,  g_att);
    cudaGetSymbolAddress((void**)&ath,  g_at_hi);
    cudaGetSymbolAddress((void**)&atl,  g_at_lo);
    cudaGetSymbolAddress((void**)&ffh,  g_ff_hi);
    cudaGetSymbolAddress((void**)&ffl,  g_ff_lo);
    cudaGetSymbolAddress((void**)&logits, g_logits);
    cudaGetSymbolAddress((void**)&pm,   g_pm);
    cudaGetSymbolAddress((void**)&ps,   g_ps);
    cudaGetSymbolAddress((void**)&z,    g_z);

    float *WqTh, *WqTl, *WkTh, *WkTl, *WvTh, *WvTl, *WuTh, *WuTl;
    float *W1Th, *W1Tl, *W2Th, *W2Tl, *WpTh, *WpTl;
    cudaGetSymbolAddress((void**)&WqTh, g_WqT_hi);
    cudaGetSymbolAddress((void**)&WqTl, g_WqT_lo);
    cudaGetSymbolAddress((void**)&WkTh, g_WkT_hi);
    cudaGetSymbolAddress((void**)&WkTl, g_WkT_lo);
    cudaGetSymbolAddress((void**)&WvTh, g_WvT_hi);
    cudaGetSymbolAddress((void**)&WvTl, g_WvT_lo);
    cudaGetSymbolAddress((void**)&WuTh, g_WuT_hi);
    cudaGetSymbolAddress((void**)&WuTl, g_WuT_lo);
    cudaGetSymbolAddress((void**)&W1Th, g_W1T_hi);
    cudaGetSymbolAddress((void**)&W1Tl, g_W1T_lo);
    cudaGetSymbolAddress((void**)&W2Th, g_W2T_hi);
    cudaGetSymbolAddress((void**)&W2Tl, g_W2T_lo);
    cudaGetSymbolAddress((void**)&WpTh, g_WpT_hi);
    cudaGetSymbolAddress((void**)&WpTl, g_WpT_lo);

    // Weight transposes + hi/lo split (once per launch)
    for (int l = 0; l < L_; ++l) {
        transp(Wq + (long)l * E_ * HE_, WqTh + (long)l * HE_ * E_,
               WqTl + (long)l * HE_ * E_, E_,  HE_);
        transp(Wk + (long)l * E_ * HE_, WkTh + (long)l * HE_ * E_,
               WkTl + (long)l * HE_ * E_, E_,  HE_);
        transp(Wv + (long)l * E_ * HE_, WvTh + (long)l * HE_ * E_,
               WvTl + (long)l * HE_ * E_, E_,  HE_);
        transp(Wu + (long)l * HE_ * E_, WuTh + (long)l * E_ * HE_,
               WuTl + (long)l * E_ * HE_, HE_, E_);
        transp(W1 + (long)l * E_ * FF_, W1Th + (long)l * FF_ * E_,
               W1Tl + (long)l * FF_ * E_, E_,  FF_);
        transp(W2 + (long)l * FF_ * E_, W2Th + (long)l * E_ * FF_,
               W2Tl + (long)l * E_ * FF_, FF_, E_);
    }
    transp(Wp, WpTh, WpTl, E_, NT_);

    embed_kernel<<<(BT_ * E_) / 256, 256>>>(x, tok, pos, h, hh, hl);

    const float qs = 0.21022410381342863f;   // 512^(-1/4)

    for (int l = 0; l < L_; ++l) {
        const long wqo = (long)l * HE_ * E_;
        const long wuo = (long)l * E_ * HE_;
        const long w1o = (long)l * FF_ * E_;
        const long w2o = (long)l * E_ * FF_;
        const float* bu_l  = bu  + (long)l * E_;
        const float* g1_l  = g1  + (long)l * E_;
        const float* b1_l  = b1n + (long)l * E_;
        const float* g2_l  = g2  + (long)l * E_;
        const float* b2_l  = b2n + (long)l * E_;
        const float* bf1_l = bf1 + (long)l * FF_;
        const float* bf2_l = bf2 + (long)l * E_;

        // q = qs * h @ Wq ; k = qs * h @ Wk  -> pairs
        gemm(16, 32, E_, hh, hl, E_, WqTh + wqo, WqTl + wqo, E_,
             nullptr, qh, ql, HE_, nullptr, qs, 0, 0);
        gemm(16, 32, E_, hh, hl, E_, WkTh + wqo, WkTl + wqo, E_,
             nullptr, kh, kl, HE_, nullptr, qs, 0, 0);
        // Vt (HE x BT) = WvT @ h^T -> pair
        gemm(32, 16, E_, WvTh + wqo, WvTl + wqo, E_, hh, hl, E_,
             nullptr, vth, vtl, BT_, nullptr, 1.f, 0, 0);

        // scores: att = q_bh @ k_bh^T (plain), causal tile skip
        gemm(8, 8, E_, qh, ql, HE_, kh, kl, HE_,
             att, nullptr, nullptr, T_, nullptr, 1.f, 0, 1,
             B_ * H_, H_,
             (long)T_ * HE_, (long)E_,
             (long)T_ * HE_, (long)E_,
             (long)H_ * T_ * T_, (long)T_ * T_);

        softmax_causal_kernel<<<B_ * H_ * T_, 128>>>(att, ath, atl);

        // o = att @ V -> pair
        gemm(8, 4, T_, ath, atl, T_, vth, vtl, BT_,
             nullptr, oh, ol, HE_, nullptr, 1.f, 0, 0,
             B_ * H_, H_,
             (long)H_ * T_ * T_, (long)T_ * T_,
             (long)T_,           (long)E_ * BT_,
             (long)T_ * HE_,     (long)E_);

        // unify heads + bias -> plain tmp
        gemm(16, 4, HE_, oh, ol, HE_, WuTh + wuo, WuTl + wuo, HE_,
             tmp, nullptr, nullptr, E_, bu_l, 1.f, 0, 0);
        add_ln_kernel<<<BT_, 128>>>(tmp, h, hh, hl, g1_l, b1_l);

        // FFN
        gemm(16, 16, E_, hh, hl, E_, W1Th + w1o, W1Tl + w1o, E_,
             nullptr, ffh, ffl, FF_, bf1_l, 1.f, 1, 0);
        gemm(16, 4, FF_, ffh, ffl, FF_, W2Th + w2o, W2Tl + w2o, FF_,
             tmp, nullptr, nullptr, E_, bf2_l, 1.f, 0, 0);
        add_ln_kernel<<<BT_, 128>>>(tmp, h, hh, hl, g2_l, b2_l);
    }

    // emb_mean / emb_max (flattened after the log_softmax block)
    if ((long)out_size >= LOGITS_N + 2L * B_ * E_) {
        emb_stats_kernel<<<dim3(B_, E_ / 32), 256>>>(
            h, out + LOGITS_N, out + LOGITS_N + B_ * E_);
    }

    // vocab projection: (2048,512) @ (512,32000) + bp -> plain logits
    gemm(16, NT_ / 128, E_, hh, hl, E_, WpTh, WpTl, E_,
         logits, nullptr, nullptr, NT_, bp, 1.f, 0, 0);

    // log_softmax over axis 1 of the raw (B, NT, T) reshape
    ls_partial_kernel<<<256, 256>>>(logits, pm, ps);
    ls_combine_kernel<<<(BT_ + 255) / 256, 256>>>(pm, ps, z);
    ls_write_kernel<<<(int)(LOGITS_N / 4 / 256), 256>>>(logits, z, out);
}

// round 8
// speedup vs baseline: 2.3297x; 1.3551x over previous
#include <cuda_runtime.h>
#include <math.h>
#include <stdint.h>

// Arch gate: tcgen05 PTX is only legal on the sm_103a arch-specific target.
#if defined(__CUDA_ARCH__) && (__CUDA_ARCH__ >= 1000) && \
    (defined(__CUDA_ARCH_FEAT_SM103_ALL) || defined(__CUDA_ARCH_SPECIFIC__) || \
     defined(__CUDA_ARCH_FEAT_SM100_ALL))
#define TC_OK 1
#else
#define TC_OK 0
#endif

// ---------------------------------------------------------------------------
// Problem dims
// ---------------------------------------------------------------------------
static constexpr int B_  = 2;
static constexpr int T_  = 1024;
static constexpr int E_  = 512;
static constexpr int H_  = 8;
static constexpr int L_  = 4;
static constexpr int NT_ = 32000;
static constexpr int FF_ = 2048;
static constexpr int BT_ = B_ * T_;        // 2048
static constexpr int HE_ = H_ * E_;        // 4096
static constexpr long LOGITS_N = (long)BT_ * NT_;
static constexpr long BNT_T    = (long)NT_ * T_;

// ---------------------------------------------------------------------------
// Scratch (device globals; no allocation allowed).
// GEMM operands live as pre-split hi/lo planes (identical layouts).
// ---------------------------------------------------------------------------
__device__ float g_h    [BT_ * E_];
__device__ float g_h_hi [BT_ * E_];
__device__ float g_h_lo [BT_ * E_];
__device__ float g_tmp  [BT_ * E_];
__device__ float g_q_hi [BT_ * HE_];
__device__ float g_q_lo [BT_ * HE_];
__device__ float g_k_hi [BT_ * HE_];
__device__ float g_k_lo [BT_ * HE_];
__device__ float g_vt_hi[(size_t)HE_ * BT_];
__device__ float g_vt_lo[(size_t)HE_ * BT_];
__device__ float g_o_hi [BT_ * HE_];
__device__ float g_o_lo [BT_ * HE_];
__device__ float g_att  [(size_t)B_ * H_ * T_ * T_];
__device__ float g_at_hi[(size_t)B_ * H_ * T_ * T_];
__device__ float g_at_lo[(size_t)B_ * H_ * T_ * T_];
__device__ float g_ff_hi[BT_ * FF_];
__device__ float g_ff_lo[BT_ * FF_];
__device__ float g_logits[(size_t)BT_ * NT_];
__device__ float g_pm   [BT_ * 4];
__device__ float g_ps   [BT_ * 4];
__device__ float g_z    [BT_];

// Transposed, pre-split weights
__device__ float g_WqT_hi[(size_t)L_ * HE_ * E_];
__device__ float g_WqT_lo[(size_t)L_ * HE_ * E_];
__device__ float g_WkT_hi[(size_t)L_ * HE_ * E_];
__device__ float g_WkT_lo[(size_t)L_ * HE_ * E_];
__device__ float g_WvT_hi[(size_t)L_ * HE_ * E_];
__device__ float g_WvT_lo[(size_t)L_ * HE_ * E_];
__device__ float g_WuT_hi[(size_t)L_ * E_ * HE_];
__device__ float g_WuT_lo[(size_t)L_ * E_ * HE_];
__device__ float g_W1T_hi[(size_t)L_ * FF_ * E_];
__device__ float g_W1T_lo[(size_t)L_ * FF_ * E_];
__device__ float g_W2T_hi[(size_t)L_ * E_ * FF_];
__device__ float g_W2T_lo[(size_t)L_ * E_ * FF_];
__device__ float g_WpT_hi[(size_t)NT_ * E_];
__device__ float g_WpT_lo[(size_t)NT_ * E_];

// ---------------------------------------------------------------------------
// Helpers
// ---------------------------------------------------------------------------
__device__ __forceinline__ uint32_t smem_u32(const void* p) {
    uint32_t a;
    asm("{ .reg .u64 t; cvta.to.shared.u64 t, %1; cvt.u32.u64 %0, t; }"
        : "=r"(a) : "l"(p));
    return a;
}
// tf32 hi/lo split: hi keeps top mantissa bits (tf32-exact), lo = exact remainder.
__device__ __forceinline__ void split2(float v, float& hi, float& lo) {
    hi = __uint_as_float(__float_as_uint(v) & 0xFFFFE000u);
    lo = v - hi;
}

#if TC_OK
__device__ __forceinline__ int elect1() {
    uint32_t p;
    asm volatile("{\n .reg .pred p;\n elect.sync _|p, 0xFFFFFFFF;\n selp.b32 %0,1,0,p;\n}"
                 : "=r"(p));
    return (int)p;
}
__device__ __forceinline__ uint64_t mkdesc(uint32_t addr) {
    const uint64_t base = (uint64_t(2) << 61) | (uint64_t(1) << 46)
                        | (uint64_t(64) << 32) | (uint64_t(1) << 16);
    return base | ((uint64_t)(addr >> 4) & 0x3FFF);
}
__device__ __forceinline__ void mbar_wait(uint32_t mbar, int parity) {
    asm volatile(
        "{\n\t.reg .pred P;\n\t"
        "W_%=:\n\t"
        "mbarrier.try_wait.parity.acquire.cta.shared::cta.b64 P, [%0], %1, 0x989680;\n\t"
        "@P bra.uni D_%=;\n\t"
        "bra.uni W_%=;\n\t"
        "D_%=:\n\t}"
        :: "r"(mbar), "r"(parity) : "memory");
}
__device__ __forceinline__ void mma_tf32(uint32_t d, uint64_t ad, uint64_t bd,
                                         uint32_t idesc, uint32_t en) {
    asm volatile(
        "{\n .reg .pred p;\n setp.ne.u32 p, %4, 0;\n"
        " tcgen05.mma.cta_group::1.kind::tf32 [%0], %1, %2, %3, {%5,%5,%5,%5}, p;\n}"
        :: "r"(d), "l"(ad), "l"(bd), "r"(idesc), "r"(en), "r"(0u) : "memory");
}
__device__ __forceinline__ void cp16(uint32_t dst, const float* src) {
    asm volatile("cp.async.cg.shared.global [%0], [%1], 16;"
                 :: "r"(dst), "l"(src) : "memory");
}

#define LDTM_X32(r, addr) \
    asm volatile( \
        "tcgen05.ld.sync.aligned.32x32b.x32.b32 " \
        "{%0, %1, %2, %3, %4, %5, %6, %7, " \
        " %8, %9, %10, %11, %12, %13, %14, %15, " \
        " %16, %17, %18, %19, %20, %21, %22, %23, " \
        " %24, %25, %26, %27, %28, %29, %30, %31}, [%32];" \
        : "=r"((r)[0]),  "=r"((r)[1]),  "=r"((r)[2]),  "=r"((r)[3]), \
          "=r"((r)[4]),  "=r"((r)[5]),  "=r"((r)[6]),  "=r"((r)[7]), \
          "=r"((r)[8]),  "=r"((r)[9]),  "=r"((r)[10]), "=r"((r)[11]), \
          "=r"((r)[12]), "=r"((r)[13]), "=r"((r)[14]), "=r"((r)[15]), \
          "=r"((r)[16]), "=r"((r)[17]), "=r"((r)[18]), "=r"((r)[19]), \
          "=r"((r)[20]), "=r"((r)[21]), "=r"((r)[22]), "=r"((r)[23]), \
          "=r"((r)[24]), "=r"((r)[25]), "=r"((r)[26]), "=r"((r)[27]), \
          "=r"((r)[28]), "=r"((r)[29]), "=r"((r)[30]), "=r"((r)[31]) \
        : "r"(addr))
#endif  // TC_OK

// idesc: dtype=F32(1<<4), atype=TF32(2<<7), btype=TF32(2<<10), N=128, M=128
static constexpr uint32_t IDESC_TF32 =
    (1u << 4) | (2u << 7) | (2u << 10) | (16u << 17) | (8u << 24);

// SMEM: [0] tmem ptr, [16/24/32] mbarriers; 3 stages of 64KB:
// per stage: A_hi(16K) A_lo(16K) B_hi(16K) B_lo(16K).
static constexpr int STAGE_BYTES = 65536;
static constexpr int SMEM_BYTES  = 1024 + 3 * STAGE_BYTES;   // 197632

// ---------------------------------------------------------------------------
// NT-GEMM on pre-split planes:
//   C[m][n] = alpha * sum_k A[m][k]*B[n][k] + bias[n]   (3xTF32, fp32 acc)
// cp.async 3-stage pipeline: chunk c's loads are issued ~2 chunk-times before
// use, landing directly in SMEM (no register round-trip, no STS phase).
// ---------------------------------------------------------------------------
__global__ __launch_bounds__(256, 1)
void gemm_tc(int K,
             const float* __restrict__ Ah, const float* __restrict__ Al, int lda,
             const float* __restrict__ Bh, const float* __restrict__ Bl, int ldb,
             float* __restrict__ C, float* __restrict__ Ch, float* __restrict__ Cl,
             int ldc,
             const float* __restrict__ bias,
             float alpha, int doRelu, int causal, int innerCnt,
             long aO, long aI, long bO, long bI, long cO, long cI)
{
    const int bx = blockIdx.x, by = blockIdx.y;
    if (causal && bx > by) return;
    {
        const int bz = blockIdx.z;
        const int oz = bz / innerCnt, iz = bz - oz * innerCnt;
        const long ao = (long)oz * aO + (long)iz * aI;
        const long bo = (long)oz * bO + (long)iz * bI;
        const long co = (long)oz * cO + (long)iz * cI;
        Ah += ao; Al += ao; Bh += bo; Bl += bo;
        if (C)  C  += co;
        if (Ch) { Ch += co; Cl += co; }
    }
    extern __shared__ char smem[];
    const int tid = threadIdx.x;

#if TC_OK
    const uint32_t sb = smem_u32(smem);
    const int wid = tid >> 5, lane = tid & 31;

    if (wid == 0) {
        asm volatile("tcgen05.alloc.cta_group::1.sync.aligned.shared::cta.b32 [%0], %1;"
                     :: "r"(sb), "r"(128u) : "memory");
        asm volatile("tcgen05.relinquish_alloc_permit.cta_group::1.sync.aligned;");
    }
    if (tid == 0) {
        asm volatile("mbarrier.init.shared.b64 [%0], 1;" :: "r"(sb + 16) : "memory");
        asm volatile("mbarrier.init.shared.b64 [%0], 1;" :: "r"(sb + 24) : "memory");
        asm volatile("mbarrier.init.shared.b64 [%0], 1;" :: "r"(sb + 32) : "memory");
    }

    const long arow_off = (long)(by * 128);
    const long brow_off = (long)(bx * 128);
    const float* Aph = Ah + arow_off * lda;
    const float* Apl = Al + arow_off * lda;
    const float* Bph = Bh + brow_off * ldb;
    const float* Bpl = Bl + brow_off * ldb;

    // per-thread tile coords (4 float4 per plane per chunk)
    int rr[4], cc[4];
    uint32_t sw[4];
#pragma unroll
    for (int i = 0; i < 4; ++i) {
        int f = tid + i * 256;
        rr[i] = f >> 3;
        cc[i] = (f & 7) << 2;
        uint32_t off = (uint32_t)(rr[i] * 128 + cc[i] * 4);
        sw[i] = off ^ ((off >> 3) & 0x70u);
    }

    auto issue_chunk = [&](int c2, int s) {
        const long kc = (long)c2 << 5;
        const uint32_t st = sb + 1024u + (uint32_t)s * (uint32_t)STAGE_BYTES;
#pragma unroll
        for (int i = 0; i < 4; ++i) {
            const long ai = (long)rr[i] * lda + kc + cc[i];
            const long bi = (long)rr[i] * ldb + kc + cc[i];
            cp16(st + sw[i],          Aph + ai);
            cp16(st + 16384 + sw[i],  Apl + ai);
            cp16(st + 32768 + sw[i],  Bph + bi);
            cp16(st + 49152 + sw[i],  Bpl + bi);
        }
        asm volatile("cp.async.commit_group;" ::: "memory");
    };

    const int nch = K >> 5;   // always >= 2 here
    // Prologue: fill stages 0 and 1.
    issue_chunk(0, 0);
    issue_chunk(1, 1);
    __syncthreads();
    uint32_t tmem;
    asm volatile("ld.shared.b32 %0, [%1];" : "=r"(tmem) : "r"(sb));

    int ph[3] = {0, 0, 0};
    for (int c2 = 0; c2 < nch; ++c2) {
        const int s = c2 % 3;
        // Wait for chunk c2's group (allow the next one to stay in flight).
        if (c2 + 1 < nch) asm volatile("cp.async.wait_group 1;" ::: "memory");
        else              asm volatile("cp.async.wait_group 0;" ::: "memory");
        asm volatile("fence.proxy.async.shared::cta;" ::: "memory");
        __syncthreads();

        if (wid == 0 && elect1()) {
            const uint32_t st = sb + 1024u + (uint32_t)s * (uint32_t)STAGE_BYTES;
            uint64_t dAh = mkdesc(st), dAl = dAh + 1024;          // +16KB
            uint64_t dBh = mkdesc(st + 32768), dBl = dBh + 1024;
#pragma unroll
            for (int ks = 0; ks < 4; ++ks) {
                uint64_t o = (uint64_t)(ks * 2);
                mma_tf32(tmem, dAh + o, dBh + o, IDESC_TF32, (c2 == 0 && ks == 0) ? 0u : 1u);
                mma_tf32(tmem, dAh + o, dBl + o, IDESC_TF32, 1u);
                mma_tf32(tmem, dAl + o, dBh + o, IDESC_TF32, 1u);
            }
            asm volatile(
                "tcgen05.commit.cta_group::1.mbarrier::arrive::one.shared::cluster.b64 [%0];"
                :: "r"(sb + 16 + 8 * s) : "memory");
        }

        // Refill: stage (c2+2)%3 held chunk c2-1; wait its MMA commit first.
        if (c2 + 2 < nch) {
            const int sn = (c2 + 2) % 3;
            if (c2 >= 1) { mbar_wait(sb + 16 + 8 * sn, ph[sn]); ph[sn] ^= 1; }
            issue_chunk(c2 + 2, sn);
        }
    }
    {
        const int sl = (nch - 1) % 3;
        mbar_wait(sb + 16 + 8 * sl, ph[sl]);
    }
    asm volatile("tcgen05.fence::after_thread_sync;" ::: "memory");

    // Epilogue: warps 0-3 read D cols 0..63, warps 4-7 cols 64..127.
    const int sub = wid & 3, half = wid >> 2;
    const uint32_t woff = (uint32_t)sub << 21;
    const int m = by * 128 + sub * 32 + lane;
    const float* bp2 = bias ? (bias + (long)bx * 128) : nullptr;
#pragma unroll
    for (int blk = 0; blk < 2; ++blk) {
        const int c0 = half * 64 + blk * 32;
        uint32_t r[32];
        LDTM_X32(r, tmem + woff + (uint32_t)c0);
        asm volatile("tcgen05.wait::ld.sync.aligned;" ::: "memory");
        const long crow = (long)m * ldc + bx * 128 + c0;
#pragma unroll
        for (int j = 0; j < 8; ++j) {
            float4 bv = make_float4(0.f, 0.f, 0.f, 0.f);
            if (bp2) bv = *(const float4*)(bp2 + c0 + j * 4);
            float4 o;
            o.x = fmaf(__uint_as_float(r[j * 4 + 0]), alpha, bv.x);
            o.y = fmaf(__uint_as_float(r[j * 4 + 1]), alpha, bv.y);
            o.z = fmaf(__uint_as_float(r[j * 4 + 2]), alpha, bv.z);
            o.w = fmaf(__uint_as_float(r[j * 4 + 3]), alpha, bv.w);
            if (doRelu) {
                o.x = fmaxf(o.x, 0.f); o.y = fmaxf(o.y, 0.f);
                o.z = fmaxf(o.z, 0.f); o.w = fmaxf(o.w, 0.f);
            }
            if (C) *(float4*)(C + crow + j * 4) = o;
            if (Ch) {
                float4 h4, l4;
                split2(o.x, h4.x, l4.x); split2(o.y, h4.y, l4.y);
                split2(o.z, h4.z, l4.z); split2(o.w, h4.w, l4.w);
                *(float4*)(Ch + crow + j * 4) = h4;
                *(float4*)(Cl + crow + j * 4) = l4;
            }
        }
    }
    __syncthreads();
    if (wid == 0) {
        asm volatile("tcgen05.dealloc.cta_group::1.sync.aligned.b32 %0, %1;"
                     :: "r"(tmem), "r"(128u));
    }

#else  // ------- FFMA fallback (portable compile pass only) -------

    float (*As)[132] = (float(*)[132])(smem);
    float (*Bs)[132] = (float(*)[132])(smem + 16 * 132 * sizeof(float));

    const int arow = tid >> 2;
    const int akv  = (tid & 3) << 2;
    const float* Aph = Ah + (long)(by * 128 + arow) * lda + akv;
    const float* Apl = Al + (long)(by * 128 + arow) * lda + akv;
    const float* Bph = Bh + (long)(bx * 128 + arow) * ldb + akv;
    const float* Bpl = Bl + (long)(bx * 128 + arow) * ldb + akv;

    float acc[8][8];
#pragma unroll
    for (int i = 0; i < 8; ++i)
#pragma unroll
        for (int j = 0; j < 8; ++j) acc[i][j] = 0.f;

    const int tx = tid & 15, ty = tid >> 4;
    const int m0 = ty << 2, n0 = tx << 2;

    const int ntiles = K >> 4;
    for (int t = 0; t < ntiles; ++t) {
        float4 a0h = *(const float4*)(Aph), a0l = *(const float4*)(Apl);
        float4 a1h = *(const float4*)(Aph + (long)64 * lda);
        float4 a1l = *(const float4*)(Apl + (long)64 * lda);
        float4 b0h = *(const float4*)(Bph), b0l = *(const float4*)(Bpl);
        float4 b1h = *(const float4*)(Bph + (long)64 * ldb);
        float4 b1l = *(const float4*)(Bpl + (long)64 * ldb);
        __syncthreads();
        As[akv + 0][arow]      = a0h.x + a0l.x; As[akv + 1][arow]      = a0h.y + a0l.y;
        As[akv + 2][arow]      = a0h.z + a0l.z; As[akv + 3][arow]      = a0h.w + a0l.w;
        As[akv + 0][arow + 64] = a1h.x + a1l.x; As[akv + 1][arow + 64] = a1h.y + a1l.y;
        As[akv + 2][arow + 64] = a1h.z + a1l.z; As[akv + 3][arow + 64] = a1h.w + a1l.w;
        Bs[akv + 0][arow]      = b0h.x + b0l.x; Bs[akv + 1][arow]      = b0h.y + b0l.y;
        Bs[akv + 2][arow]      = b0h.z + b0l.z; Bs[akv + 3][arow]      = b0h.w + b0l.w;
        Bs[akv + 0][arow + 64] = b1h.x + b1l.x; Bs[akv + 1][arow + 64] = b1h.y + b1l.y;
        Bs[akv + 2][arow + 64] = b1h.z + b1l.z; Bs[akv + 3][arow + 64] = b1h.w + b1l.w;
        __syncthreads();
#pragma unroll
        for (int k = 0; k < 16; ++k) {
            float4 a0 = *(const float4*)&As[k][m0];
            float4 a1 = *(const float4*)&As[k][m0 + 64];
            float4 b0 = *(const float4*)&Bs[k][n0];
            float4 b1 = *(const float4*)&Bs[k][n0 + 64];
            float av[8] = {a0.x, a0.y, a0.z, a0.w, a1.x, a1.y, a1.z, a1.w};
            float bv[8] = {b0.x, b0.y, b0.z, b0.w, b1.x, b1.y, b1.z, b1.w};
#pragma unroll
            for (int i = 0; i < 8; ++i)
#pragma unroll
                for (int j = 0; j < 8; ++j)
                    acc[i][j] = fmaf(av[i], bv[j], acc[i][j]);
        }
        Aph += 16; Apl += 16; Bph += 16; Bpl += 16;
    }

    float bvv[8];
#pragma unroll
    for (int j = 0; j < 8; ++j) {
        int n = bx * 128 + n0 + ((j < 4) ? j : (64 + j - 4));
        bvv[j] = bias ? bias[n] : 0.f;
    }
#pragma unroll
    for (int i = 0; i < 8; ++i) {
        int m = by * 128 + m0 + ((i < 4) ? i : (64 + i - 4));
#pragma unroll
        for (int j = 0; j < 8; ++j) {
            float v = fmaf(acc[i][j], alpha, bvv[j]);
            v = doRelu ? fmaxf(v, 0.f) : v;
            int n = n0 + ((j < 4) ? j : (64 + j - 4));
            long idx = (long)m * ldc + bx * 128 + n;
            if (C) C[idx] = v;
            if (Ch) { float hi, lo; split2(v, hi, lo); Ch[idx] = hi; Cl[idx] = lo; }
        }
    }
#endif  // TC_OK
}

// ---------------------------------------------------------------------------
// 32x32 tiled transpose emitting hi/lo planes: outT (C x R) = in (R x C)^T
// ---------------------------------------------------------------------------
__global__ void transpose_k(const float* __restrict__ in,
                            float* __restrict__ oh, float* __restrict__ ol,
                            int R, int Cc)
{
    __shared__ float t[32][33];
    const int c0 = blockIdx.x * 32, r0 = blockIdx.y * 32;
    const int x = threadIdx.x, y = threadIdx.y;
#pragma unroll
    for (int i = 0; i < 32; i += 8)
        t[y + i][x] = in[(long)(r0 + y + i) * Cc + c0 + x];
    __syncthreads();
#pragma unroll
    for (int i = 0; i < 32; i += 8) {
        float v = t[x][y + i];
        float hi, lo; split2(v, hi, lo);
        long idx = (long)(c0 + y + i) * R + r0 + x;
        oh[idx] = hi; ol[idx] = lo;
    }
}

// ---------------------------------------------------------------------------
// Elementwise kernels
// ---------------------------------------------------------------------------
__global__ void embed_kernel(const int* __restrict__ x,
                             const float* __restrict__ tok,
                             const float* __restrict__ pos,
                             float* __restrict__ h,
                             float* __restrict__ hh, float* __restrict__ hl)
{
    int idx = blockIdx.x * 256 + threadIdx.x;
    int bt  = idx >> 9;
    int e   = idx & 511;
    int token = x[bt];
    float v = tok[(long)token * E_ + e] + pos[((bt & (T_ - 1)) << 9) + e];
    h[idx] = v;
    float hi, lo; split2(v, hi, lo);
    hh[idx] = hi; hl[idx] = lo;
}

// Causal softmax: reads plain scores, writes hi/lo planes (zeros above diag).
__global__ void softmax_causal_kernel(const float* __restrict__ att,
                                      float* __restrict__ ah,
                                      float* __restrict__ al)
{
    const int i = blockIdx.x & (T_ - 1);
    const long base = (long)blockIdx.x * T_;
    const float* row = att + base;
    const int n = i + 1;
    const int tid = threadIdx.x, lane = tid & 31, w = tid >> 5;
    __shared__ float redm[4], reds[4];

    float mx = -INFINITY;
    for (int j = tid; j < n; j += 128) mx = fmaxf(mx, row[j]);
#pragma unroll
    for (int o = 16; o > 0; o >>= 1) mx = fmaxf(mx, __shfl_xor_sync(0xffffffffu, mx, o));
    if (lane == 0) redm[w] = mx;
    __syncthreads();
    mx = fmaxf(fmaxf(redm[0], redm[1]), fmaxf(redm[2], redm[3]));

    float s = 0.f;
    for (int j = tid; j < n; j += 128) s += expf(row[j] - mx);
#pragma unroll
    for (int o = 16; o > 0; o >>= 1) s += __shfl_xor_sync(0xffffffffu, s, o);
    if (lane == 0) reds[w] = s;
    __syncthreads();
    s = reds[0] + reds[1] + reds[2] + reds[3];

    const float inv = 1.f / s;
    for (int j = tid; j < T_; j += 128) {
        float p = (j < n) ? expf(row[j] - mx) * inv : 0.f;
        float hi, lo; split2(p, hi, lo);
        ah[base + j] = hi; al[base + j] = lo;
    }
}

__global__ void add_ln_kernel(const float* __restrict__ a,
                              float* __restrict__ h,
                              float* __restrict__ hh, float* __restrict__ hl,
                              const float* __restrict__ gam,
                              const float* __restrict__ bet)
{
    const long row = blockIdx.x;
    const float* ar = a + row * E_;
    float* hr = h + row * E_;
    const int tid = threadIdx.x, lane = tid & 31, w = tid >> 5;
    __shared__ float r1[4], r2[4];

    float x[4];
    float s = 0.f;
#pragma unroll
    for (int i = 0; i < 4; ++i) {
        int e = tid + i * 128;
        x[i] = ar[e] + hr[e];
        s += x[i];
    }
#pragma unroll
    for (int o = 16; o > 0; o >>= 1) s += __shfl_xor_sync(0xffffffffu, s, o);
    if (lane == 0) r1[w] = s;
    __syncthreads();
    const float m = (r1[0] + r1[1] + r1[2] + r1[3]) * (1.f / E_);

    float d2 = 0.f;
#pragma unroll
    for (int i = 0; i < 4; ++i) { float d = x[i] - m; d2 += d * d; }
#pragma unroll
    for (int o = 16; o > 0; o >>= 1) d2 += __shfl_xor_sync(0xffffffffu, d2, o);
    if (lane == 0) r2[w] = d2;
    __syncthreads();
    const float var = (r2[0] + r2[1] + r2[2] + r2[3]) * (1.f / E_);
    const float r = rsqrtf(var + 1e-5f);

#pragma unroll
    for (int i = 0; i < 4; ++i) {
        int e = tid + i * 128;
        float y = (x[i] - m) * r * gam[e] + bet[e];
        hr[e] = y;
        float hi, lo; split2(y, hi, lo);
        hh[row * E_ + e] = hi; hl[row * E_ + e] = lo;
    }
}

__global__ void emb_stats_kernel(const float* __restrict__ h,
                                 float* __restrict__ omean,
                                 float* __restrict__ omax)
{
    const int b = blockIdx.x, e = blockIdx.y * 32 + (threadIdx.x & 31);
    const int lane = threadIdx.x & 31, wy = threadIdx.x >> 5;
    __shared__ float ss[8][32], sm[8][32];
    float s = 0.f, m = -INFINITY;
    for (int t = wy; t < T_; t += 8) {
        float v = h[((long)(b * T_ + t)) * E_ + e];
        s += v; m = fmaxf(m, v);
    }
    ss[wy][lane] = s; sm[wy][lane] = m;
    __syncthreads();
    if (wy == 0) {
        float S = 0.f, M = -INFINITY;
#pragma unroll
        for (int w = 0; w < 8; ++w) { S += ss[w][lane]; M = fmaxf(M, sm[w][lane]); }
        omean[b * E_ + e] = S * (1.f / T_);
        omax [b * E_ + e] = M;
    }
}

__global__ void ls_partial_kernel(const float* __restrict__ logits,
                                  float* __restrict__ pm,
                                  float* __restrict__ ps)
{
    const int split = blockIdx.x & 3;
    const int tcol  = blockIdx.x >> 2;
    const int b     = tcol >> 5;
    const int lane  = threadIdx.x & 31, wy = threadIdx.x >> 5;
    const int t     = ((tcol & 31) << 5) + lane;
    const long base = (long)b * BNT_T + t;

    float mx = -INFINITY, s = 0.f;
    const int n0 = split * (NT_ / 4);
#pragma unroll 4
    for (int n = n0 + wy; n < n0 + NT_ / 4; n += 8) {
        float v = logits[base + (long)n * T_];
        if (v > mx) { s = s * __expf(mx - v) + 1.f; mx = v; }
        else        { s += __expf(v - mx); }
    }
    __shared__ float shm[8][32], shs[8][32];
    shm[wy][lane] = mx; shs[wy][lane] = s;
    __syncthreads();
    if (wy == 0) {
        float M = -INFINITY, S = 0.f;
#pragma unroll
        for (int w = 0; w < 8; ++w) {
            float m2 = shm[w][lane], s2 = shs[w][lane];
            if (m2 > M) { S = S * __expf(M - m2) + s2; M = m2; }
            else        { S += s2 * __expf(m2 - M); }
        }
        int idx = b * T_ + t;
        pm[idx * 4 + split] = M;
        ps[idx * 4 + split] = S;
    }
}

__global__ void ls_combine_kernel(const float* __restrict__ pm,
                                  const float* __restrict__ ps,
                                  float* __restrict__ z)
{
    int idx = blockIdx.x * 256 + threadIdx.x;
    if (idx >= BT_) return;
    float M = -INFINITY, S = 0.f;
#pragma unroll
    for (int k = 0; k < 4; ++k) {
        float m2 = pm[idx * 4 + k], s2 = ps[idx * 4 + k];
        if (m2 > M) { S = S * expf(M - m2) + s2; M = m2; }
        else        { S += s2 * expf(m2 - M); }
    }
    z[idx] = M + logf(S);
}

__global__ void ls_write_kernel(const float* __restrict__ logits,
                                const float* __restrict__ z,
                                float* __restrict__ out)
{
    long i4 = (long)blockIdx.x * 256 + threadIdx.x;
    long f  = i4 << 2;
    int  t  = (int)(f & (T_ - 1));
    int  b  = (f >= BNT_T) ? 1 : 0;
    float4 v  = *(const float4*)(logits + f);
    float4 zz = *(const float4*)(z + b * T_ + t);
    float4 o;
    o.x = v.x - zz.x; o.y = v.y - zz.y; o.z = v.z - zz.z; o.w = v.w - zz.w;
    *(float4*)(out + f) = o;
}

// ---------------------------------------------------------------------------
// Host-side launch helpers
// ---------------------------------------------------------------------------
static inline void gemm(int Mtiles, int Ntiles, int K,
                        const float* Ah, const float* Al, int lda,
                        const float* Bh, const float* Bl, int ldb,
                        float* C, float* Ch, float* Cl, int ldc,
                        const float* bias,
                        float alpha, int relu, int causal,
                        int batches = 1, int innerCnt = 1,
                        long aO = 0, long aI = 0, long bO = 0, long bI = 0,
                        long cO = 0, long cI = 0)
{
    dim3 grid(Ntiles, Mtiles, batches), blk(256);
    gemm_tc<<<grid, blk, SMEM_BYTES>>>(K, Ah, Al, lda, Bh, Bl, ldb,
                                       C, Ch, Cl, ldc, bias,
                                       alpha, relu, causal, innerCnt,
                                       aO, aI, bO, bI, cO, cI);
}

static inline void transp(const float* in, float* oh, float* ol, int R, int C)
{
    dim3 g(C / 32, R / 32), b(32, 8);
    transpose_k<<<g, b>>>(in, oh, ol, R, C);
}

extern "C" void kernel_launch(void* const* d_in, const int* in_sizes, int n_in,
                              void* d_out, int out_size)
{
    const int*   x    = (const int*)  d_in[0];
    const float* tok  = (const float*)d_in[1];
    const float* pos  = (const float*)d_in[2];
    const float* Wq   = (const float*)d_in[3];
    const float* Wk   = (const float*)d_in[4];
    const float* Wv   = (const float*)d_in[5];
    const float* Wu   = (const float*)d_in[6];
    const float* bu   = (const float*)d_in[7];
    const float* g1   = (const float*)d_in[8];
    const float* b1n  = (const float*)d_in[9];
    const float* g2   = (const float*)d_in[10];
    const float* b2n  = (const float*)d_in[11];
    const float* W1   = (const float*)d_in[12];
    const float* bf1  = (const float*)d_in[13];
    const float* W2   = (const float*)d_in[14];
    const float* bf2  = (const float*)d_in[15];
    const float* Wp   = (const float*)d_in[16];
    const float* bp   = (const float*)d_in[17];
    float* out = (float*)d_out;

    cudaFuncSetAttribute(gemm_tc, cudaFuncAttributeMaxDynamicSharedMemorySize,
                         SMEM_BYTES);

    float *h, *hh, *hl, *tmp, *qh, *ql, *kh, *kl, *vth, *vtl, *oh, *ol;
    float *att, *ath, *atl, *ffh, *ffl, *logits, *pm, *ps, *z;
    cudaGetSymbolAddress((void**)&h,    g_h);
    cudaGetSymbolAddress((void**)&hh,   g_h_hi);
    cudaGetSymbolAddress((void**)&hl,   g_h_lo);
    cudaGetSymbolAddress((void**)&tmp,  g_tmp);
    cudaGetSymbolAddress((void**)&qh,   g_q_hi);
    cudaGetSymbolAddress((void**)&ql,   g_q_lo);
    cudaGetSymbolAddress((void**)&kh,   g_k_hi);
    cudaGetSymbolAddress((void**)&kl,   g_k_lo);
    cudaGetSymbolAddress((void**)&vth,  g_vt_hi);
    cudaGetSymbolAddress((void**)&vtl,  g_vt_lo);
    cudaGetSymbolAddress((void**)&oh,   g_o_hi);
    cudaGetSymbolAddress((void**)&ol,   g_o_lo);
    cudaGetSymbolAddress((void**)&att,  g_att);
    cudaGetSymbolAddress((void**)&ath,  g_at_hi);
    cudaGetSymbolAddress((void**)&atl,  g_at_lo);
    cudaGetSymbolAddress((void**)&ffh,  g_ff_hi);
    cudaGetSymbolAddress((void**)&ffl,  g_ff_lo);
    cudaGetSymbolAddress((void**)&logits, g_logits);
    cudaGetSymbolAddress((void**)&pm,   g_pm);
    cudaGetSymbolAddress((void**)&ps,   g_ps);
    cudaGetSymbolAddress((void**)&z,    g_z);

    float *WqTh, *WqTl, *WkTh, *WkTl, *WvTh, *WvTl, *WuTh, *WuTl;
    float *W1Th, *W1Tl, *W2Th, *W2Tl, *WpTh, *WpTl;
    cudaGetSymbolAddress((void**)&WqTh, g_WqT_hi);
    cudaGetSymbolAddress((void**)&WqTl, g_WqT_lo);
    cudaGetSymbolAddress((void**)&WkTh, g_WkT_hi);
    cudaGetSymbolAddress((void**)&WkTl, g_WkT_lo);
    cudaGetSymbolAddress((void**)&WvTh, g_WvT_hi);
    cudaGetSymbolAddress((void**)&WvTl, g_WvT_lo);
    cudaGetSymbolAddress((void**)&WuTh, g_WuT_hi);
    cudaGetSymbolAddress((void**)&WuTl, g_WuT_lo);
    cudaGetSymbolAddress((void**)&W1Th, g_W1T_hi);
    cudaGetSymbolAddress((void**)&W1Tl, g_W1T_lo);
    cudaGetSymbolAddress((void**)&W2Th, g_W2T_hi);
    cudaGetSymbolAddress((void**)&W2Tl, g_W2T_lo);
    cudaGetSymbolAddress((void**)&WpTh, g_WpT_hi);
    cudaGetSymbolAddress((void**)&WpTl, g_WpT_lo);

    // Weight transposes + hi/lo split (once per launch)
    for (int l = 0; l < L_; ++l) {
        transp(Wq + (long)l * E_ * HE_, WqTh + (long)l * HE_ * E_,
               WqTl + (long)l * HE_ * E_, E_,  HE_);
        transp(Wk + (long)l * E_ * HE_, WkTh + (long)l * HE_ * E_,
               WkTl + (long)l * HE_ * E_, E_,  HE_);
        transp(Wv + (long)l * E_ * HE_, WvTh + (long)l * HE_ * E_,
               WvTl + (long)l * HE_ * E_, E_,  HE_);
        transp(Wu + (long)l * HE_ * E_, WuTh + (long)l * E_ * HE_,
               WuTl + (long)l * E_ * HE_, HE_, E_);
        transp(W1 + (long)l * E_ * FF_, W1Th + (long)l * FF_ * E_,
               W1Tl + (long)l * FF_ * E_, E_,  FF_);
        transp(W2 + (long)l * FF_ * E_, W2Th + (long)l * E_ * FF_,
               W2Tl + (long)l * E_ * FF_, FF_, E_);
    }
    transp(Wp, WpTh, WpTl, E_, NT_);

    embed_kernel<<<(BT_ * E_) / 256, 256>>>(x, tok, pos, h, hh, hl);

    const float qs = 0.21022410381342863f;   // 512^(-1/4)

    for (int l = 0; l < L_; ++l) {
        const long wqo = (long)l * HE_ * E_;
        const long wuo = (long)l * E_ * HE_;
        const long w1o = (long)l * FF_ * E_;
        const long w2o = (long)l * E_ * FF_;
        const float* bu_l  = bu  + (long)l * E_;
        const float* g1_l  = g1  + (long)l * E_;
        const float* b1_l  = b1n + (long)l * E_;
        const float* g2_l  = g2  + (long)l * E_;
        const float* b2_l  = b2n + (long)l * E_;
        const float* bf1_l = bf1 + (long)l * FF_;
        const float* bf2_l = bf2 + (long)l * E_;

        // q = qs * h @ Wq ; k = qs * h @ Wk  -> pairs
        gemm(16, 32, E_, hh, hl, E_, WqTh + wqo, WqTl + wqo, E_,
             nullptr, qh, ql, HE_, nullptr, qs, 0, 0);
        gemm(16, 32, E_, hh, hl, E_, WkTh + wqo, WkTl + wqo, E_,
             nullptr, kh, kl, HE_, nullptr, qs, 0, 0);
        // Vt (HE x BT) = WvT @ h^T -> pair
        gemm(32, 16, E_, WvTh + wqo, WvTl + wqo, E_, hh, hl, E_,
             nullptr, vth, vtl, BT_, nullptr, 1.f, 0, 0);

        // scores: att = q_bh @ k_bh^T (plain), causal tile skip
        gemm(8, 8, E_, qh, ql, HE_, kh, kl, HE_,
             att, nullptr, nullptr, T_, nullptr, 1.f, 0, 1,
             B_ * H_, H_,
             (long)T_ * HE_, (long)E_,
             (long)T_ * HE_, (long)E_,
             (long)H_ * T_ * T_, (long)T_ * T_);

        softmax_causal_kernel<<<B_ * H_ * T_, 128>>>(att, ath, atl);

        // o = att @ V -> pair
        gemm(8, 4, T_, ath, atl, T_, vth, vtl, BT_,
             nullptr, oh, ol, HE_, nullptr, 1.f, 0, 0,
             B_ * H_, H_,
             (long)H_ * T_ * T_, (long)T_ * T_,
             (long)T_,           (long)E_ * BT_,
             (long)T_ * HE_,     (long)E_);

        // unify heads + bias -> plain tmp
        gemm(16, 4, HE_, oh, ol, HE_, WuTh + wuo, WuTl + wuo, HE_,
             tmp, nullptr, nullptr, E_, bu_l, 1.f, 0, 0);
        add_ln_kernel<<<BT_, 128>>>(tmp, h, hh, hl, g1_l, b1_l);

        // FFN
        gemm(16, 16, E_, hh, hl, E_, W1Th + w1o, W1Tl + w1o, E_,
             nullptr, ffh, ffl, FF_, bf1_l, 1.f, 1, 0);
        gemm(16, 4, FF_, ffh, ffl, FF_, W2Th + w2o, W2Tl + w2o, FF_,
             tmp, nullptr, nullptr, E_, bf2_l, 1.f, 0, 0);
        add_ln_kernel<<<BT_, 128>>>(tmp, h, hh, hl, g2_l, b2_l);
    }

    // emb_mean / emb_max (flattened after the log_softmax block)
    if ((long)out_size >= LOGITS_N + 2L * B_ * E_) {
        emb_stats_kernel<<<dim3(B_, E_ / 32), 256>>>(
            h, out + LOGITS_N, out + LOGITS_N + B_ * E_);
    }

    // vocab projection: (2048,512) @ (512,32000) + bp -> plain logits
    gemm(16, NT_ / 128, E_, hh, hl, E_, WpTh, WpTl, E_,
         logits, nullptr, nullptr, NT_, bp, 1.f, 0, 0);

    // log_softmax over axis 1 of the raw (B, NT, T) reshape
    ls_partial_kernel<<<256, 256>>>(logits, pm, ps);
    ls_combine_kernel<<<(BT_ + 255) / 256, 256>>>(pm, ps, z);
    ls_write_kernel<<<(int)(LOGITS_N / 4 / 256), 256>>>(logits, z, out);
}

// round 9
// speedup vs baseline: 3.4109x; 1.4640x over previous
#include <cuda_runtime.h>
#include <cuda_bf16.h>
#include <math.h>
#include <stdint.h>

// Arch gate: tcgen05 PTX is only legal on the sm_103a arch-specific target.
#if defined(__CUDA_ARCH__) && (__CUDA_ARCH__ >= 1000) && \
    (defined(__CUDA_ARCH_FEAT_SM103_ALL) || defined(__CUDA_ARCH_SPECIFIC__) || \
     defined(__CUDA_ARCH_FEAT_SM100_ALL))
#define TC_OK 1
#else
#define TC_OK 0
#endif

typedef __nv_bfloat16 bf16;

// ---------------------------------------------------------------------------
// Problem dims
// ---------------------------------------------------------------------------
static constexpr int B_  = 2;
static constexpr int T_  = 1024;
static constexpr int E_  = 512;
static constexpr int H_  = 8;
static constexpr int L_  = 4;
static constexpr int NT_ = 32000;
static constexpr int FF_ = 2048;
static constexpr int BT_ = B_ * T_;        // 2048
static constexpr int HE_ = H_ * E_;        // 4096
static constexpr long LOGITS_N = (long)BT_ * NT_;
static constexpr long BNT_T    = (long)NT_ * T_;

// ---------------------------------------------------------------------------
// Scratch (device globals; no allocation allowed).
// GEMM operands live as pre-split bf16 hi/lo planes (identical layouts).
// ---------------------------------------------------------------------------
__device__ float g_h    [BT_ * E_];
__device__ bf16  g_h_hi [BT_ * E_];
__device__ bf16  g_h_lo [BT_ * E_];
__device__ float g_tmp  [BT_ * E_];
__device__ bf16  g_q_hi [BT_ * HE_];
__device__ bf16  g_q_lo [BT_ * HE_];
__device__ bf16  g_k_hi [BT_ * HE_];
__device__ bf16  g_k_lo [BT_ * HE_];
__device__ bf16  g_vt_hi[(size_t)HE_ * BT_];
__device__ bf16  g_vt_lo[(size_t)HE_ * BT_];
__device__ bf16  g_o_hi [BT_ * HE_];
__device__ bf16  g_o_lo [BT_ * HE_];
__device__ float g_att  [(size_t)B_ * H_ * T_ * T_];
__device__ bf16  g_at_hi[(size_t)B_ * H_ * T_ * T_];
__device__ bf16  g_at_lo[(size_t)B_ * H_ * T_ * T_];
__device__ bf16  g_ff_hi[BT_ * FF_];
__device__ bf16  g_ff_lo[BT_ * FF_];
__device__ float g_logits[(size_t)BT_ * NT_];
__device__ float g_pm   [BT_ * 4];
__device__ float g_ps   [BT_ * 4];
__device__ float g_z    [BT_];

// Transposed, pre-split weights
__device__ bf16 g_WqT_hi[(size_t)L_ * HE_ * E_];
__device__ bf16 g_WqT_lo[(size_t)L_ * HE_ * E_];
__device__ bf16 g_WkT_hi[(size_t)L_ * HE_ * E_];
__device__ bf16 g_WkT_lo[(size_t)L_ * HE_ * E_];
__device__ bf16 g_WvT_hi[(size_t)L_ * HE_ * E_];
__device__ bf16 g_WvT_lo[(size_t)L_ * HE_ * E_];
__device__ bf16 g_WuT_hi[(size_t)L_ * E_ * HE_];
__device__ bf16 g_WuT_lo[(size_t)L_ * E_ * HE_];
__device__ bf16 g_W1T_hi[(size_t)L_ * FF_ * E_];
__device__ bf16 g_W1T_lo[(size_t)L_ * FF_ * E_];
__device__ bf16 g_W2T_hi[(size_t)L_ * E_ * FF_];
__device__ bf16 g_W2T_lo[(size_t)L_ * E_ * FF_];
__device__ bf16 g_WpT_hi[(size_t)NT_ * E_];
__device__ bf16 g_WpT_lo[(size_t)NT_ * E_];

// ---------------------------------------------------------------------------
// Helpers
// ---------------------------------------------------------------------------
__device__ __forceinline__ uint32_t smem_u32(const void* p) {
    uint32_t a;
    asm("{ .reg .u64 t; cvta.to.shared.u64 t, %1; cvt.u32.u64 %0, t; }"
        : "=r"(a) : "l"(p));
    return a;
}
// bf16 2-term split: hi = bf16(v), lo = bf16(v - hi).
__device__ __forceinline__ void split2b(float v, bf16& hi, bf16& lo) {
    hi = __float2bfloat16(v);
    lo = __float2bfloat16(v - __bfloat162float(hi));
}

#if TC_OK
__device__ __forceinline__ int elect1() {
    uint32_t p;
    asm volatile("{\n .reg .pred p;\n elect.sync _|p, 0xFFFFFFFF;\n selp.b32 %0,1,0,p;\n}"
                 : "=r"(p));
    return (int)p;
}
__device__ __forceinline__ uint64_t mkdesc(uint32_t addr) {
    const uint64_t base = (uint64_t(2) << 61) | (uint64_t(1) << 46)
                        | (uint64_t(64) << 32) | (uint64_t(1) << 16);
    return base | ((uint64_t)(addr >> 4) & 0x3FFF);
}
__device__ __forceinline__ void mbar_wait(uint32_t mbar, int parity) {
    asm volatile(
        "{\n\t.reg .pred P;\n\t"
        "W_%=:\n\t"
        "mbarrier.try_wait.parity.acquire.cta.shared::cta.b64 P, [%0], %1, 0x989680;\n\t"
        "@P bra.uni D_%=;\n\t"
        "bra.uni W_%=;\n\t"
        "D_%=:\n\t}"
        :: "r"(mbar), "r"(parity) : "memory");
}
__device__ __forceinline__ void mma_bf16(uint32_t d, uint64_t ad, uint64_t bd,
                                         uint32_t idesc, uint32_t en) {
    asm volatile(
        "{\n .reg .pred p;\n setp.ne.u32 p, %4, 0;\n"
        " tcgen05.mma.cta_group::1.kind::f16 [%0], %1, %2, %3, {%5,%5,%5,%5}, p;\n}"
        :: "r"(d), "l"(ad), "l"(bd), "r"(idesc), "r"(en), "r"(0u) : "memory");
}
__device__ __forceinline__ void cp16(uint32_t dst, const void* src) {
    asm volatile("cp.async.cg.shared.global [%0], [%1], 16;"
                 :: "r"(dst), "l"(src) : "memory");
}

#define LDTM_X32(r, addr) \
    asm volatile( \
        "tcgen05.ld.sync.aligned.32x32b.x32.b32 " \
        "{%0, %1, %2, %3, %4, %5, %6, %7, " \
        " %8, %9, %10, %11, %12, %13, %14, %15, " \
        " %16, %17, %18, %19, %20, %21, %22, %23, " \
        " %24, %25, %26, %27, %28, %29, %30, %31}, [%32];" \
        : "=r"((r)[0]),  "=r"((r)[1]),  "=r"((r)[2]),  "=r"((r)[3]), \
          "=r"((r)[4]),  "=r"((r)[5]),  "=r"((r)[6]),  "=r"((r)[7]), \
          "=r"((r)[8]),  "=r"((r)[9]),  "=r"((r)[10]), "=r"((r)[11]), \
          "=r"((r)[12]), "=r"((r)[13]), "=r"((r)[14]), "=r"((r)[15]), \
          "=r"((r)[16]), "=r"((r)[17]), "=r"((r)[18]), "=r"((r)[19]), \
          "=r"((r)[20]), "=r"((r)[21]), "=r"((r)[22]), "=r"((r)[23]), \
          "=r"((r)[24]), "=r"((r)[25]), "=r"((r)[26]), "=r"((r)[27]), \
          "=r"((r)[28]), "=r"((r)[29]), "=r"((r)[30]), "=r"((r)[31]) \
        : "r"(addr))
#endif  // TC_OK

// idesc kind::f16: dtype=F32(1<<4), atype=BF16(1<<7), btype=BF16(1<<10),
// N=128 (16<<17), M=128 (8<<24)
static constexpr uint32_t IDESC_BF16 =
    (1u << 4) | (1u << 7) | (1u << 10) | (16u << 17) | (8u << 24);

// SMEM: [0] tmem ptr, [16/24/32] mbarriers; 3 stages of 64KB:
// per stage: A_hi(16K) A_lo(16K) B_hi(16K) B_lo(16K); rows are 128B = 64 bf16.
static constexpr int STAGE_BYTES = 65536;
static constexpr int SMEM_BYTES  = 1024 + 3 * STAGE_BYTES;   // 197632

// ---------------------------------------------------------------------------
// NT-GEMM on bf16 hi/lo planes:
//   C[m][n] = alpha * sum_k A[m][k]*B[n][k] + bias[n]   (3x bf16, fp32 acc)
// cp.async 3-stage pipeline, K-chunks of 64. Requires K % 64 == 0.
// ---------------------------------------------------------------------------
__global__ __launch_bounds__(256, 1)
void gemm_tc(int K,
             const bf16* __restrict__ Ah, const bf16* __restrict__ Al, int lda,
             const bf16* __restrict__ Bh, const bf16* __restrict__ Bl, int ldb,
             float* __restrict__ C, bf16* __restrict__ Ch, bf16* __restrict__ Cl,
             int ldc,
             const float* __restrict__ bias,
             float alpha, int doRelu, int causal, int innerCnt,
             long aO, long aI, long bO, long bI, long cO, long cI)
{
    const int bx = blockIdx.x, by = blockIdx.y;
    if (causal && bx > by) return;
    {
        const int bz = blockIdx.z;
        const int oz = bz / innerCnt, iz = bz - oz * innerCnt;
        const long ao = (long)oz * aO + (long)iz * aI;
        const long bo = (long)oz * bO + (long)iz * bI;
        const long co = (long)oz * cO + (long)iz * cI;
        Ah += ao; Al += ao; Bh += bo; Bl += bo;
        if (C)  C  += co;
        if (Ch) { Ch += co; Cl += co; }
    }
    extern __shared__ char smem[];
    const int tid = threadIdx.x;

#if TC_OK
    const uint32_t sb = smem_u32(smem);
    const int wid = tid >> 5, lane = tid & 31;

    if (wid == 0) {
        asm volatile("tcgen05.alloc.cta_group::1.sync.aligned.shared::cta.b32 [%0], %1;"
                     :: "r"(sb), "r"(128u) : "memory");
        asm volatile("tcgen05.relinquish_alloc_permit.cta_group::1.sync.aligned;");
    }
    if (tid == 0) {
        asm volatile("mbarrier.init.shared.b64 [%0], 1;" :: "r"(sb + 16) : "memory");
        asm volatile("mbarrier.init.shared.b64 [%0], 1;" :: "r"(sb + 24) : "memory");
        asm volatile("mbarrier.init.shared.b64 [%0], 1;" :: "r"(sb + 32) : "memory");
    }

    const bf16* Aph = Ah + (long)(by * 128) * lda;
    const bf16* Apl = Al + (long)(by * 128) * lda;
    const bf16* Bph = Bh + (long)(bx * 128) * ldb;
    const bf16* Bpl = Bl + (long)(bx * 128) * ldb;

    // per-thread coords: plane = 128 rows x 128B (64 bf16); 1024 slots of 16B.
    int rr[4], ce[4];
    uint32_t sw[4];
#pragma unroll
    for (int i = 0; i < 4; ++i) {
        int f = tid + i * 256;
        rr[i] = f >> 3;                 // row 0..127
        ce[i] = (f & 7) << 3;           // element col 0..56 (8 bf16 per 16B)
        uint32_t off = (uint32_t)(rr[i] * 128 + (f & 7) * 16);
        sw[i] = off ^ ((off >> 3) & 0x70u);
    }

    auto issue_chunk = [&](int c2, int s) {
        const long kc = (long)c2 << 6;   // K-chunk of 64
        const uint32_t st = sb + 1024u + (uint32_t)s * (uint32_t)STAGE_BYTES;
#pragma unroll
        for (int i = 0; i < 4; ++i) {
            const long ai = (long)rr[i] * lda + kc + ce[i];
            const long bi = (long)rr[i] * ldb + kc + ce[i];
            cp16(st + sw[i],          Aph + ai);
            cp16(st + 16384 + sw[i],  Apl + ai);
            cp16(st + 32768 + sw[i],  Bph + bi);
            cp16(st + 49152 + sw[i],  Bpl + bi);
        }
        asm volatile("cp.async.commit_group;" ::: "memory");
    };

    const int nch = K >> 6;   // >= 8 for all our GEMMs
    issue_chunk(0, 0);
    issue_chunk(1, 1);
    __syncthreads();
    uint32_t tmem;
    asm volatile("ld.shared.b32 %0, [%1];" : "=r"(tmem) : "r"(sb));

    int ph[3] = {0, 0, 0};
    for (int c2 = 0; c2 < nch; ++c2) {
        const int s = c2 % 3;
        if (c2 + 1 < nch) asm volatile("cp.async.wait_group 1;" ::: "memory");
        else              asm volatile("cp.async.wait_group 0;" ::: "memory");
        asm volatile("fence.proxy.async.shared::cta;" ::: "memory");
        __syncthreads();

        if (wid == 0 && elect1()) {
            const uint32_t st = sb + 1024u + (uint32_t)s * (uint32_t)STAGE_BYTES;
            uint64_t dAh = mkdesc(st), dAl = dAh + 1024;          // +16KB
            uint64_t dBh = mkdesc(st + 32768), dBl = dBh + 1024;
#pragma unroll
            for (int ks = 0; ks < 4; ++ks) {   // K=16 bf16 per MMA step
                uint64_t o = (uint64_t)(ks * 2);   // 32B per step
                mma_bf16(tmem, dAh + o, dBh + o, IDESC_BF16, (c2 == 0 && ks == 0) ? 0u : 1u);
                mma_bf16(tmem, dAh + o, dBl + o, IDESC_BF16, 1u);
                mma_bf16(tmem, dAl + o, dBh + o, IDESC_BF16, 1u);
            }
            asm volatile(
                "tcgen05.commit.cta_group::1.mbarrier::arrive::one.shared::cluster.b64 [%0];"
                :: "r"(sb + 16 + 8 * s) : "memory");
        }

        if (c2 + 2 < nch) {
            const int sn = (c2 + 2) % 3;
            if (c2 >= 1) { mbar_wait(sb + 16 + 8 * sn, ph[sn]); ph[sn] ^= 1; }
            issue_chunk(c2 + 2, sn);
        }
    }
    {
        const int sl = (nch - 1) % 3;
        mbar_wait(sb + 16 + 8 * sl, ph[sl]);
    }
    asm volatile("tcgen05.fence::after_thread_sync;" ::: "memory");

    // Epilogue: warps 0-3 read D cols 0..63, warps 4-7 cols 64..127.
    const int sub = wid & 3, half = wid >> 2;
    const uint32_t woff = (uint32_t)sub << 21;
    const int m = by * 128 + sub * 32 + lane;
    const float* bp2 = bias ? (bias + (long)bx * 128) : nullptr;
#pragma unroll
    for (int blk = 0; blk < 2; ++blk) {
        const int c0 = half * 64 + blk * 32;
        uint32_t r[32];
        LDTM_X32(r, tmem + woff + (uint32_t)c0);
        asm volatile("tcgen05.wait::ld.sync.aligned;" ::: "memory");
        const long crow = (long)m * ldc + bx * 128 + c0;
#pragma unroll
        for (int j = 0; j < 8; ++j) {
            float4 bv = make_float4(0.f, 0.f, 0.f, 0.f);
            if (bp2) bv = *(const float4*)(bp2 + c0 + j * 4);
            float4 o;
            o.x = fmaf(__uint_as_float(r[j * 4 + 0]), alpha, bv.x);
            o.y = fmaf(__uint_as_float(r[j * 4 + 1]), alpha, bv.y);
            o.z = fmaf(__uint_as_float(r[j * 4 + 2]), alpha, bv.z);
            o.w = fmaf(__uint_as_float(r[j * 4 + 3]), alpha, bv.w);
            if (doRelu) {
                o.x = fmaxf(o.x, 0.f); o.y = fmaxf(o.y, 0.f);
                o.z = fmaxf(o.z, 0.f); o.w = fmaxf(o.w, 0.f);
            }
            if (C) *(float4*)(C + crow + j * 4) = o;
            if (Ch) {
                bf16 h4[4], l4[4];
                split2b(o.x, h4[0], l4[0]); split2b(o.y, h4[1], l4[1]);
                split2b(o.z, h4[2], l4[2]); split2b(o.w, h4[3], l4[3]);
                uint2 hv, lv;
                hv.x = (uint32_t)__bfloat16_as_ushort(h4[0])
                     | ((uint32_t)__bfloat16_as_ushort(h4[1]) << 16);
                hv.y = (uint32_t)__bfloat16_as_ushort(h4[2])
                     | ((uint32_t)__bfloat16_as_ushort(h4[3]) << 16);
                lv.x = (uint32_t)__bfloat16_as_ushort(l4[0])
                     | ((uint32_t)__bfloat16_as_ushort(l4[1]) << 16);
                lv.y = (uint32_t)__bfloat16_as_ushort(l4[2])
                     | ((uint32_t)__bfloat16_as_ushort(l4[3]) << 16);
                *(uint2*)(Ch + crow + j * 4) = hv;
                *(uint2*)(Cl + crow + j * 4) = lv;
            }
        }
    }
    __syncthreads();
    if (wid == 0) {
        asm volatile("tcgen05.dealloc.cta_group::1.sync.aligned.b32 %0, %1;"
                     :: "r"(tmem), "r"(128u));
    }

#else  // ------- FFMA fallback (portable compile pass only; never selected) ---

    float (*As)[132] = (float(*)[132])(smem);
    float (*Bs)[132] = (float(*)[132])(smem + 16 * 132 * sizeof(float));

    const int arow = tid >> 2;
    const int akv  = (tid & 3) << 2;
    const bf16* Aph = Ah + (long)(by * 128 + arow) * lda + akv;
    const bf16* Apl = Al + (long)(by * 128 + arow) * lda + akv;
    const bf16* Bph = Bh + (long)(bx * 128 + arow) * ldb + akv;
    const bf16* Bpl = Bl + (long)(bx * 128 + arow) * ldb + akv;

    float acc[8][8];
#pragma unroll
    for (int i = 0; i < 8; ++i)
#pragma unroll
        for (int j = 0; j < 8; ++j) acc[i][j] = 0.f;

    const int tx = tid & 15, ty = tid >> 4;
    const int m0 = ty << 2, n0 = tx << 2;

    auto rec4 = [](const bf16* ph, const bf16* pl, float* o) {
#pragma unroll
        for (int j = 0; j < 4; ++j)
            o[j] = __bfloat162float(ph[j]) + __bfloat162float(pl[j]);
    };

    const int ntiles = K >> 4;
    for (int t = 0; t < ntiles; ++t) {
        float a0[4], a1[4], b0[4], b1[4];
        rec4(Aph, Apl, a0);
        rec4(Aph + (long)64 * lda, Apl + (long)64 * lda, a1);
        rec4(Bph, Bpl, b0);
        rec4(Bph + (long)64 * ldb, Bpl + (long)64 * ldb, b1);
        __syncthreads();
#pragma unroll
        for (int j = 0; j < 4; ++j) {
            As[akv + j][arow]      = a0[j];
            As[akv + j][arow + 64] = a1[j];
            Bs[akv + j][arow]      = b0[j];
            Bs[akv + j][arow + 64] = b1[j];
        }
        __syncthreads();
#pragma unroll
        for (int k = 0; k < 16; ++k) {
            float4 av0 = *(const float4*)&As[k][m0];
            float4 av1 = *(const float4*)&As[k][m0 + 64];
            float4 bv0 = *(const float4*)&Bs[k][n0];
            float4 bv1 = *(const float4*)&Bs[k][n0 + 64];
            float av[8] = {av0.x, av0.y, av0.z, av0.w, av1.x, av1.y, av1.z, av1.w};
            float bv[8] = {bv0.x, bv0.y, bv0.z, bv0.w, bv1.x, bv1.y, bv1.z, bv1.w};
#pragma unroll
            for (int i = 0; i < 8; ++i)
#pragma unroll
                for (int j = 0; j < 8; ++j)
                    acc[i][j] = fmaf(av[i], bv[j], acc[i][j]);
        }
        Aph += 16; Apl += 16; Bph += 16; Bpl += 16;
    }

    float bvv[8];
#pragma unroll
    for (int j = 0; j < 8; ++j) {
        int n = bx * 128 + n0 + ((j < 4) ? j : (64 + j - 4));
        bvv[j] = bias ? bias[n] : 0.f;
    }
#pragma unroll
    for (int i = 0; i < 8; ++i) {
        int m = by * 128 + m0 + ((i < 4) ? i : (64 + i - 4));
#pragma unroll
        for (int j = 0; j < 8; ++j) {
            float v = fmaf(acc[i][j], alpha, bvv[j]);
            v = doRelu ? fmaxf(v, 0.f) : v;
            int n = n0 + ((j < 4) ? j : (64 + j - 4));
            long idx = (long)m * ldc + bx * 128 + n;
            if (C) C[idx] = v;
            if (Ch) { bf16 hi, lo; split2b(v, hi, lo); Ch[idx] = hi; Cl[idx] = lo; }
        }
    }
#endif  // TC_OK
}

// ---------------------------------------------------------------------------
// 32x32 tiled transpose emitting bf16 hi/lo planes: outT (C x R) = in (R x C)^T
// ---------------------------------------------------------------------------
__global__ void transpose_k(const float* __restrict__ in,
                            bf16* __restrict__ oh, bf16* __restrict__ ol,
                            int R, int Cc)
{
    __shared__ float t[32][33];
    const int c0 = blockIdx.x * 32, r0 = blockIdx.y * 32;
    const int x = threadIdx.x, y = threadIdx.y;
#pragma unroll
    for (int i = 0; i < 32; i += 8)
        t[y + i][x] = in[(long)(r0 + y + i) * Cc + c0 + x];
    __syncthreads();
#pragma unroll
    for (int i = 0; i < 32; i += 8) {
        float v = t[x][y + i];
        bf16 hi, lo; split2b(v, hi, lo);
        long idx = (long)(c0 + y + i) * R + r0 + x;
        oh[idx] = hi; ol[idx] = lo;
    }
}

// ---------------------------------------------------------------------------
// Elementwise kernels
// ---------------------------------------------------------------------------
__global__ void embed_kernel(const int* __restrict__ x,
                             const float* __restrict__ tok,
                             const float* __restrict__ pos,
                             float* __restrict__ h,
                             bf16* __restrict__ hh, bf16* __restrict__ hl)
{
    int idx = blockIdx.x * 256 + threadIdx.x;
    int bt  = idx >> 9;
    int e   = idx & 511;
    int token = x[bt];
    float v = tok[(long)token * E_ + e] + pos[((bt & (T_ - 1)) << 9) + e];
    h[idx] = v;
    bf16 hi, lo; split2b(v, hi, lo);
    hh[idx] = hi; hl[idx] = lo;
}

// Causal softmax: reads plain scores, writes bf16 hi/lo planes (zeros above diag).
__global__ void softmax_causal_kernel(const float* __restrict__ att,
                                      bf16* __restrict__ ah,
                                      bf16* __restrict__ al)
{
    const int i = blockIdx.x & (T_ - 1);
    const long base = (long)blockIdx.x * T_;
    const float* row = att + base;
    const int n = i + 1;
    const int tid = threadIdx.x, lane = tid & 31, w = tid >> 5;
    __shared__ float redm[4], reds[4];

    float mx = -INFINITY;
    for (int j = tid; j < n; j += 128) mx = fmaxf(mx, row[j]);
#pragma unroll
    for (int o = 16; o > 0; o >>= 1) mx = fmaxf(mx, __shfl_xor_sync(0xffffffffu, mx, o));
    if (lane == 0) redm[w] = mx;
    __syncthreads();
    mx = fmaxf(fmaxf(redm[0], redm[1]), fmaxf(redm[2], redm[3]));

    float s = 0.f;
    for (int j = tid; j < n; j += 128) s += expf(row[j] - mx);
#pragma unroll
    for (int o = 16; o > 0; o >>= 1) s += __shfl_xor_sync(0xffffffffu, s, o);
    if (lane == 0) reds[w] = s;
    __syncthreads();
    s = reds[0] + reds[1] + reds[2] + reds[3];

    const float inv = 1.f / s;
    for (int j = tid; j < T_; j += 128) {
        float p = (j < n) ? expf(row[j] - mx) * inv : 0.f;
        bf16 hi, lo; split2b(p, hi, lo);
        ah[base + j] = hi; al[base + j] = lo;
    }
}

__global__ void add_ln_kernel(const float* __restrict__ a,
                              float* __restrict__ h,
                              bf16* __restrict__ hh, bf16* __restrict__ hl,
                              const float* __restrict__ gam,
                              const float* __restrict__ bet)
{
    const long row = blockIdx.x;
    const float* ar = a + row * E_;
    float* hr = h + row * E_;
    const int tid = threadIdx.x, lane = tid & 31, w = tid >> 5;
    __shared__ float r1[4], r2[4];

    float x[4];
    float s = 0.f;
#pragma unroll
    for (int i = 0; i < 4; ++i) {
        int e = tid + i * 128;
        x[i] = ar[e] + hr[e];
        s += x[i];
    }
#pragma unroll
    for (int o = 16; o > 0; o >>= 1) s += __shfl_xor_sync(0xffffffffu, s, o);
    if (lane == 0) r1[w] = s;
    __syncthreads();
    const float m = (r1[0] + r1[1] + r1[2] + r1[3]) * (1.f / E_);

    float d2 = 0.f;
#pragma unroll
    for (int i = 0; i < 4; ++i) { float d = x[i] - m; d2 += d * d; }
#pragma unroll
    for (int o = 16; o > 0; o >>= 1) d2 += __shfl_xor_sync(0xffffffffu, d2, o);
    if (lane == 0) r2[w] = d2;
    __syncthreads();
    const float var = (r2[0] + r2[1] + r2[2] + r2[3]) * (1.f / E_);
    const float r = rsqrtf(var + 1e-5f);

#pragma unroll
    for (int i = 0; i < 4; ++i) {
        int e = tid + i * 128;
        float y = (x[i] - m) * r * gam[e] + bet[e];
        hr[e] = y;
        bf16 hi, lo; split2b(y, hi, lo);
        hh[row * E_ + e] = hi; hl[row * E_ + e] = lo;
    }
}

__global__ void emb_stats_kernel(const float* __restrict__ h,
                                 float* __restrict__ omean,
                                 float* __restrict__ omax)
{
    const int b = blockIdx.x, e = blockIdx.y * 32 + (threadIdx.x & 31);
    const int lane = threadIdx.x & 31, wy = threadIdx.x >> 5;
    __shared__ float ss[8][32], sm[8][32];
    float s = 0.f, m = -INFINITY;
    for (int t = wy; t < T_; t += 8) {
        float v = h[((long)(b * T_ + t)) * E_ + e];
        s += v; m = fmaxf(m, v);
    }
    ss[wy][lane] = s; sm[wy][lane] = m;
    __syncthreads();
    if (wy == 0) {
        float S = 0.f, M = -INFINITY;
#pragma unroll
        for (int w = 0; w < 8; ++w) { S += ss[w][lane]; M = fmaxf(M, sm[w][lane]); }
        omean[b * E_ + e] = S * (1.f / T_);
        omax [b * E_ + e] = M;
    }
}

__global__ void ls_partial_kernel(const float* __restrict__ logits,
                                  float* __restrict__ pm,
                                  float* __restrict__ ps)
{
    const int split = blockIdx.x & 3;
    const int tcol  = blockIdx.x >> 2;
    const int b     = tcol >> 5;
    const int lane  = threadIdx.x & 31, wy = threadIdx.x >> 5;
    const int t     = ((tcol & 31) << 5) + lane;
    const long base = (long)b * BNT_T + t;

    float mx = -INFINITY, s = 0.f;
    const int n0 = split * (NT_ / 4);
#pragma unroll 4
    for (int n = n0 + wy; n < n0 + NT_ / 4; n += 8) {
        float v = logits[base + (long)n * T_];
        if (v > mx) { s = s * __expf(mx - v) + 1.f; mx = v; }
        else        { s += __expf(v - mx); }
    }
    __shared__ float shm[8][32], shs[8][32];
    shm[wy][lane] = mx; shs[wy][lane] = s;
    __syncthreads();
    if (wy == 0) {
        float M = -INFINITY, S = 0.f;
#pragma unroll
        for (int w = 0; w < 8; ++w) {
            float m2 = shm[w][lane], s2 = shs[w][lane];
            if (m2 > M) { S = S * __expf(M - m2) + s2; M = m2; }
            else        { S += s2 * __expf(m2 - M); }
        }
        int idx = b * T_ + t;
        pm[idx * 4 + split] = M;
        ps[idx * 4 + split] = S;
    }
}

__global__ void ls_combine_kernel(const float* __restrict__ pm,
                                  const float* __restrict__ ps,
                                  float* __restrict__ z)
{
    int idx = blockIdx.x * 256 + threadIdx.x;
    if (idx >= BT_) return;
    float M = -INFINITY, S = 0.f;
#pragma unroll
    for (int k = 0; k < 4; ++k) {
        float m2 = pm[idx * 4 + k], s2 = ps[idx * 4 + k];
        if (m2 > M) { S = S * expf(M - m2) + s2; M = m2; }
        else        { S += s2 * expf(m2 - M); }
    }
    z[idx] = M + logf(S);
}

__global__ void ls_write_kernel(const float* __restrict__ logits,
                                const float* __restrict__ z,
                                float* __restrict__ out)
{
    long i4 = (long)blockIdx.x * 256 + threadIdx.x;
    long f  = i4 << 2;
    int  t  = (int)(f & (T_ - 1));
    int  b  = (f >= BNT_T) ? 1 : 0;
    float4 v  = *(const float4*)(logits + f);
    float4 zz = *(const float4*)(z + b * T_ + t);
    float4 o;
    o.x = v.x - zz.x; o.y = v.y - zz.y; o.z = v.z - zz.z; o.w = v.w - zz.w;
    *(float4*)(out + f) = o;
}

// ---------------------------------------------------------------------------
// Host-side launch helpers
// ---------------------------------------------------------------------------
static inline void gemm(int Mtiles, int Ntiles, int K,
                        const bf16* Ah, const bf16* Al, int lda,
                        const bf16* Bh, const bf16* Bl, int ldb,
                        float* C, bf16* Ch, bf16* Cl, int ldc,
                        const float* bias,
                        float alpha, int relu, int causal,
                        int batches = 1, int innerCnt = 1,
                        long aO = 0, long aI = 0, long bO = 0, long bI = 0,
                        long cO = 0, long cI = 0)
{
    dim3 grid(Ntiles, Mtiles, batches), blk(256);
    gemm_tc<<<grid, blk, SMEM_BYTES>>>(K, Ah, Al, lda, Bh, Bl, ldb,
                                       C, Ch, Cl, ldc, bias,
                                       alpha, relu, causal, innerCnt,
                                       aO, aI, bO, bI, cO, cI);
}

static inline void transp(const float* in, bf16* oh, bf16* ol, int R, int C)
{
    dim3 g(C / 32, R / 32), b(32, 8);
    transpose_k<<<g, b>>>(in, oh, ol, R, C);
}

extern "C" void kernel_launch(void* const* d_in, const int* in_sizes, int n_in,
                              void* d_out, int out_size)
{
    const int*   x    = (const int*)  d_in[0];
    const float* tok  = (const float*)d_in[1];
    const float* pos  = (const float*)d_in[2];
    const float* Wq   = (const float*)d_in[3];
    const float* Wk   = (const float*)d_in[4];
    const float* Wv   = (const float*)d_in[5];
    const float* Wu   = (const float*)d_in[6];
    const float* bu   = (const float*)d_in[7];
    const float* g1   = (const float*)d_in[8];
    const float* b1n  = (const float*)d_in[9];
    const float* g2   = (const float*)d_in[10];
    const float* b2n  = (const float*)d_in[11];
    const float* W1   = (const float*)d_in[12];
    const float* bf1  = (const float*)d_in[13];
    const float* W2   = (const float*)d_in[14];
    const float* bf2  = (const float*)d_in[15];
    const float* Wp   = (const float*)d_in[16];
    const float* bp   = (const float*)d_in[17];
    float* out = (float*)d_out;

    cudaFuncSetAttribute(gemm_tc, cudaFuncAttributeMaxDynamicSharedMemorySize,
                         SMEM_BYTES);

    float *h, *tmp, *att, *logits, *pm, *ps, *z;
    bf16 *hh, *hl, *qh, *ql, *kh, *kl, *vth, *vtl, *oh, *ol, *ath, *atl, *ffh, *ffl;
    cudaGetSymbolAddress((void**)&h,    g_h);
    cudaGetSymbolAddress((void**)&hh,   g_h_hi);
    cudaGetSymbolAddress((void**)&hl,   g_h_lo);
    cudaGetSymbolAddress((void**)&tmp,  g_tmp);
    cudaGetSymbolAddress((void**)&qh,   g_q_hi);
    cudaGetSymbolAddress((void**)&ql,   g_q_lo);
    cudaGetSymbolAddress((void**)&kh,   g_k_hi);
    cudaGetSymbolAddress((void**)&kl,   g_k_lo);
    cudaGetSymbolAddress((void**)&vth,  g_vt_hi);
    cudaGetSymbolAddress((void**)&vtl,  g_vt_lo);
    cudaGetSymbolAddress((void**)&oh,   g_o_hi);
    cudaGetSymbolAddress((void**)&ol,   g_o_lo);
    cudaGetSymbolAddress((void**)&att,  g_att);
    cudaGetSymbolAddress((void**)&ath,  g_at_hi);
    cudaGetSymbolAddress((void**)&atl,  g_at_lo);
    cudaGetSymbolAddress((void**)&ffh,  g_ff_hi);
    cudaGetSymbolAddress((void**)&ffl,  g_ff_lo);
    cudaGetSymbolAddress((void**)&logits, g_logits);
    cudaGetSymbolAddress((void**)&pm,   g_pm);
    cudaGetSymbolAddress((void**)&ps,   g_ps);
    cudaGetSymbolAddress((void**)&z,    g_z);

    bf16 *WqTh, *WqTl, *WkTh, *WkTl, *WvTh, *WvTl, *WuTh, *WuTl;
    bf16 *W1Th, *W1Tl, *W2Th, *W2Tl, *WpTh, *WpTl;
    cudaGetSymbolAddress((void**)&WqTh, g_WqT_hi);
    cudaGetSymbolAddress((void**)&WqTl, g_WqT_lo);
    cudaGetSymbolAddress((void**)&WkTh, g_WkT_hi);
    cudaGetSymbolAddress((void**)&WkTl, g_WkT_lo);
    cudaGetSymbolAddress((void**)&WvTh, g_WvT_hi);
    cudaGetSymbolAddress((void**)&WvTl, g_WvT_lo);
    cudaGetSymbolAddress((void**)&WuTh, g_WuT_hi);
    cudaGetSymbolAddress((void**)&WuTl, g_WuT_lo);
    cudaGetSymbolAddress((void**)&W1Th, g_W1T_hi);
    cudaGetSymbolAddress((void**)&W1Tl, g_W1T_lo);
    cudaGetSymbolAddress((void**)&W2Th, g_W2T_hi);
    cudaGetSymbolAddress((void**)&W2Tl, g_W2T_lo);
    cudaGetSymbolAddress((void**)&WpTh, g_WpT_hi);
    cudaGetSymbolAddress((void**)&WpTl, g_WpT_lo);

    // Weight transposes + bf16 hi/lo split (once per launch)
    for (int l = 0; l < L_; ++l) {
        transp(Wq + (long)l * E_ * HE_, WqTh + (long)l * HE_ * E_,
               WqTl + (long)l * HE_ * E_, E_,  HE_);
        transp(Wk + (long)l * E_ * HE_, WkTh + (long)l * HE_ * E_,
               WkTl + (long)l * HE_ * E_, E_,  HE_);
        transp(Wv + (long)l * E_ * HE_, WvTh + (long)l * HE_ * E_,
               WvTl + (long)l * HE_ * E_, E_,  HE_);
        transp(Wu + (long)l * HE_ * E_, WuTh + (long)l * E_ * HE_,
               WuTl + (long)l * E_ * HE_, HE_, E_);
        transp(W1 + (long)l * E_ * FF_, W1Th + (long)l * FF_ * E_,
               W1Tl + (long)l * FF_ * E_, E_,  FF_);
        transp(W2 + (long)l * FF_ * E_, W2Th + (long)l * E_ * FF_,
               W2Tl + (long)l * E_ * FF_, FF_, E_);
    }
    transp(Wp, WpTh, WpTl, E_, NT_);

    embed_kernel<<<(BT_ * E_) / 256, 256>>>(x, tok, pos, h, hh, hl);

    const float qs = 0.21022410381342863f;   // 512^(-1/4)

    for (int l = 0; l < L_; ++l) {
        const long wqo = (long)l * HE_ * E_;
        const long wuo = (long)l * E_ * HE_;
        const long w1o = (long)l * FF_ * E_;
        const long w2o = (long)l * E_ * FF_;
        const float* bu_l  = bu  + (long)l * E_;
        const float* g1_l  = g1  + (long)l * E_;
        const float* b1_l  = b1n + (long)l * E_;
        const float* g2_l  = g2  + (long)l * E_;
        const float* b2_l  = b2n + (long)l * E_;
        const float* bf1_l = bf1 + (long)l * FF_;
        const float* bf2_l = bf2 + (long)l * E_;

        // q = qs * h @ Wq ; k = qs * h @ Wk  -> pairs
        gemm(16, 32, E_, hh, hl, E_, WqTh + wqo, WqTl + wqo, E_,
             nullptr, qh, ql, HE_, nullptr, qs, 0, 0);
        gemm(16, 32, E_, hh, hl, E_, WkTh + wqo, WkTl + wqo, E_,
             nullptr, kh, kl, HE_, nullptr, qs, 0, 0);
        // Vt (HE x BT) = WvT @ h^T -> pair
        gemm(32, 16, E_, WvTh + wqo, WvTl + wqo, E_, hh, hl, E_,
             nullptr, vth, vtl, BT_, nullptr, 1.f, 0, 0);

        // scores: att = q_bh @ k_bh^T (plain), causal tile skip
        gemm(8, 8, E_, qh, ql, HE_, kh, kl, HE_,
             att, nullptr, nullptr, T_, nullptr, 1.f, 0, 1,
             B_ * H_, H_,
             (long)T_ * HE_, (long)E_,
             (long)T_ * HE_, (long)E_,
             (long)H_ * T_ * T_, (long)T_ * T_);

        softmax_causal_kernel<<<B_ * H_ * T_, 128>>>(att, ath, atl);

        // o = att @ V -> pair
        gemm(8, 4, T_, ath, atl, T_, vth, vtl, BT_,
             nullptr, oh, ol, HE_, nullptr, 1.f, 0, 0,
             B_ * H_, H_,
             (long)H_ * T_ * T_, (long)T_ * T_,
             (long)T_,           (long)E_ * BT_,
             (long)T_ * HE_,     (long)E_);

        // unify heads + bias -> plain tmp
        gemm(16, 4, HE_, oh, ol, HE_, WuTh + wuo, WuTl + wuo, HE_,
             tmp, nullptr, nullptr, E_, bu_l, 1.f, 0, 0);
        add_ln_kernel<<<BT_, 128>>>(tmp, h, hh, hl, g1_l, b1_l);

        // FFN
        gemm(16, 16, E_, hh, hl, E_, W1Th + w1o, W1Tl + w1o, E_,
             nullptr, ffh, ffl, FF_, bf1_l, 1.f, 1, 0);
        gemm(16, 4, FF_, ffh, ffl, FF_, W2Th + w2o, W2Tl + w2o, FF_,
             tmp, nullptr, nullptr, E_, bf2_l, 1.f, 0, 0);
        add_ln_kernel<<<BT_, 128>>>(tmp, h, hh, hl, g2_l, b2_l);
    }

    // emb_mean / emb_max (flattened after the log_softmax block)
    if ((long)out_size >= LOGITS_N + 2L * B_ * E_) {
        emb_stats_kernel<<<dim3(B_, E_ / 32), 256>>>(
            h, out + LOGITS_N, out + LOGITS_N + B_ * E_);
    }

    // vocab projection: (2048,512) @ (512,32000) + bp -> plain logits
    gemm(16, NT_ / 128, E_, hh, hl, E_, WpTh, WpTl, E_,
         logits, nullptr, nullptr, NT_, bp, 1.f, 0, 0);

    // log_softmax over axis 1 of the raw (B, NT, T) reshape
    ls_partial_kernel<<<256, 256>>>(logits, pm, ps);
    ls_combine_kernel<<<(BT_ + 255) / 256, 256>>>(pm, ps, z);
    ls_write_kernel<<<(int)(LOGITS_N / 4 / 256), 256>>>(logits, z, out);
}

// round 10
// speedup vs baseline: 3.8033x; 1.1151x over previous
#include <cuda_runtime.h>
#include <cuda_bf16.h>
#include <math.h>
#include <stdint.h>

// Arch gate: tcgen05 PTX is only legal on the sm_103a arch-specific target.
#if defined(__CUDA_ARCH__) && (__CUDA_ARCH__ >= 1000) && \
    (defined(__CUDA_ARCH_FEAT_SM103_ALL) || defined(__CUDA_ARCH_SPECIFIC__) || \
     defined(__CUDA_ARCH_FEAT_SM100_ALL))
#define TC_OK 1
#else
#define TC_OK 0
#endif

typedef __nv_bfloat16 bf16;

// ---------------------------------------------------------------------------
// Problem dims
// ---------------------------------------------------------------------------
static constexpr int B_  = 2;
static constexpr int T_  = 1024;
static constexpr int E_  = 512;
static constexpr int H_  = 8;
static constexpr int L_  = 4;
static constexpr int NT_ = 32000;
static constexpr int FF_ = 2048;
static constexpr int BT_ = B_ * T_;        // 2048
static constexpr int HE_ = H_ * E_;        // 4096
static constexpr long LOGITS_N = (long)BT_ * NT_;
static constexpr long BNT_T    = (long)NT_ * T_;

// ---------------------------------------------------------------------------
// Scratch (device globals; no allocation allowed).
// ---------------------------------------------------------------------------
__device__ float g_h    [BT_ * E_];
__device__ bf16  g_h_hi [BT_ * E_];
__device__ bf16  g_h_lo [BT_ * E_];
__device__ bf16  g_q_hi [BT_ * HE_];
__device__ bf16  g_q_lo [BT_ * HE_];
__device__ bf16  g_k_hi [BT_ * HE_];
__device__ bf16  g_k_lo [BT_ * HE_];
__device__ bf16  g_vt_hi[(size_t)HE_ * BT_];
__device__ bf16  g_vt_lo[(size_t)HE_ * BT_];
__device__ bf16  g_o_hi [BT_ * HE_];
__device__ bf16  g_o_lo [BT_ * HE_];
__device__ float g_att  [(size_t)B_ * H_ * T_ * T_];   // scores, then split-K partials
__device__ bf16  g_at_hi[(size_t)B_ * H_ * T_ * T_];
__device__ bf16  g_at_lo[(size_t)B_ * H_ * T_ * T_];
__device__ bf16  g_ff_hi[BT_ * FF_];
__device__ bf16  g_ff_lo[BT_ * FF_];
__device__ float g_logits[(size_t)BT_ * NT_];
__device__ float g_pm   [BT_ * 4];
__device__ float g_ps   [BT_ * 4];
__device__ float g_z    [BT_];

// Transposed, pre-split weights
__device__ bf16 g_WqT_hi[(size_t)L_ * HE_ * E_];
__device__ bf16 g_WqT_lo[(size_t)L_ * HE_ * E_];
__device__ bf16 g_WkT_hi[(size_t)L_ * HE_ * E_];
__device__ bf16 g_WkT_lo[(size_t)L_ * HE_ * E_];
__device__ bf16 g_WvT_hi[(size_t)L_ * HE_ * E_];
__device__ bf16 g_WvT_lo[(size_t)L_ * HE_ * E_];
__device__ bf16 g_WuT_hi[(size_t)L_ * E_ * HE_];
__device__ bf16 g_WuT_lo[(size_t)L_ * E_ * HE_];
__device__ bf16 g_W1T_hi[(size_t)L_ * FF_ * E_];
__device__ bf16 g_W1T_lo[(size_t)L_ * FF_ * E_];
__device__ bf16 g_W2T_hi[(size_t)L_ * E_ * FF_];
__device__ bf16 g_W2T_lo[(size_t)L_ * E_ * FF_];
__device__ bf16 g_WpT_hi[(size_t)NT_ * E_];
__device__ bf16 g_WpT_lo[(size_t)NT_ * E_];

// ---------------------------------------------------------------------------
// Helpers
// ---------------------------------------------------------------------------
__device__ __forceinline__ uint32_t smem_u32(const void* p) {
    uint32_t a;
    asm("{ .reg .u64 t; cvta.to.shared.u64 t, %1; cvt.u32.u64 %0, t; }"
        : "=r"(a) : "l"(p));
    return a;
}
__device__ __forceinline__ void split2b(float v, bf16& hi, bf16& lo) {
    hi = __float2bfloat16(v);
    lo = __float2bfloat16(v - __bfloat162float(hi));
}

#if TC_OK
__device__ __forceinline__ int elect1() {
    uint32_t p;
    asm volatile("{\n .reg .pred p;\n elect.sync _|p, 0xFFFFFFFF;\n selp.b32 %0,1,0,p;\n}"
                 : "=r"(p));
    return (int)p;
}
__device__ __forceinline__ uint64_t mkdesc(uint32_t addr) {
    const uint64_t base = (uint64_t(2) << 61) | (uint64_t(1) << 46)
                        | (uint64_t(64) << 32) | (uint64_t(1) << 16);
    return base | ((uint64_t)(addr >> 4) & 0x3FFF);
}
__device__ __forceinline__ void mbar_wait(uint32_t mbar, int parity) {
    asm volatile(
        "{\n\t.reg .pred P;\n\t"
        "W_%=:\n\t"
        "mbarrier.try_wait.parity.acquire.cta.shared::cta.b64 P, [%0], %1, 0x989680;\n\t"
        "@P bra.uni D_%=;\n\t"
        "bra.uni W_%=;\n\t"
        "D_%=:\n\t}"
        :: "r"(mbar), "r"(parity) : "memory");
}
__device__ __forceinline__ void mma_bf16(uint32_t d, uint64_t ad, uint64_t bd,
                                         uint32_t idesc, uint32_t en) {
    asm volatile(
        "{\n .reg .pred p;\n setp.ne.u32 p, %4, 0;\n"
        " tcgen05.mma.cta_group::1.kind::f16 [%0], %1, %2, %3, {%5,%5,%5,%5}, p;\n}"
        :: "r"(d), "l"(ad), "l"(bd), "r"(idesc), "r"(en), "r"(0u) : "memory");
}
__device__ __forceinline__ void cp16(uint32_t dst, const void* src) {
    asm volatile("cp.async.cg.shared.global [%0], [%1], 16;"
                 :: "r"(dst), "l"(src) : "memory");
}

#define LDTM_X32(r, addr) \
    asm volatile( \
        "tcgen05.ld.sync.aligned.32x32b.x32.b32 " \
        "{%0, %1, %2, %3, %4, %5, %6, %7, " \
        " %8, %9, %10, %11, %12, %13, %14, %15, " \
        " %16, %17, %18, %19, %20, %21, %22, %23, " \
        " %24, %25, %26, %27, %28, %29, %30, %31}, [%32];" \
        : "=r"((r)[0]),  "=r"((r)[1]),  "=r"((r)[2]),  "=r"((r)[3]), \
          "=r"((r)[4]),  "=r"((r)[5]),  "=r"((r)[6]),  "=r"((r)[7]), \
          "=r"((r)[8]),  "=r"((r)[9]),  "=r"((r)[10]), "=r"((r)[11]), \
          "=r"((r)[12]), "=r"((r)[13]), "=r"((r)[14]), "=r"((r)[15]), \
          "=r"((r)[16]), "=r"((r)[17]), "=r"((r)[18]), "=r"((r)[19]), \
          "=r"((r)[20]), "=r"((r)[21]), "=r"((r)[22]), "=r"((r)[23]), \
          "=r"((r)[24]), "=r"((r)[25]), "=r"((r)[26]), "=r"((r)[27]), \
          "=r"((r)[28]), "=r"((r)[29]), "=r"((r)[30]), "=r"((r)[31]) \
        : "r"(addr))
#endif  // TC_OK

// idesc kind::f16: dtype=F32(1<<4), atype=BF16(1<<7), btype=BF16(1<<10),
// N=256 (32<<17), M=128 (8<<24)
static constexpr uint32_t IDESC_BF16_256 =
    (1u << 4) | (1u << 7) | (1u << 10) | (32u << 17) | (8u << 24);

// SMEM: [0] tmem ptr, [16/24] mbarriers; 2 stages of 96KB:
// per stage: A_hi(16K) A_lo(16K) B_hi(32K) B_lo(32K); rows 128B = 64 bf16.
static constexpr int STAGE_BYTES = 98304;
static constexpr int SMEM_BYTES  = 1024 + 2 * STAGE_BYTES;   // 197632

// ---------------------------------------------------------------------------
// NT-GEMM (128x256 tile) on bf16 hi/lo planes:
//   C[m][n] = alpha * sum_k A[m][k]*B[n][k] + bias[n]   (3x bf16, fp32 acc)
// cp.async 2-stage pipeline, K-chunks of 64. Requires K % 64 == 0, N % 256 == 0.
// ---------------------------------------------------------------------------
__global__ __launch_bounds__(256, 1)
void gemm_tc(int K,
             const bf16* __restrict__ Ah, const bf16* __restrict__ Al, int lda,
             const bf16* __restrict__ Bh, const bf16* __restrict__ Bl, int ldb,
             float* __restrict__ C, bf16* __restrict__ Ch, bf16* __restrict__ Cl,
             int ldc,
             const float* __restrict__ bias,
             float alpha, int doRelu, int causal, int innerCnt,
             long aO, long aI, long bO, long bI, long cO, long cI)
{
    const int bx = blockIdx.x, by = blockIdx.y;
    if (causal && 2 * bx > by) return;
    {
        const int bz = blockIdx.z;
        const int oz = bz / innerCnt, iz = bz - oz * innerCnt;
        const long ao = (long)oz * aO + (long)iz * aI;
        const long bo = (long)oz * bO + (long)iz * bI;
        const long co = (long)oz * cO + (long)iz * cI;
        Ah += ao; Al += ao; Bh += bo; Bl += bo;
        if (C)  C  += co;
        if (Ch) { Ch += co; Cl += co; }
    }
    extern __shared__ char smem[];
    const int tid = threadIdx.x;

#if TC_OK
    const uint32_t sb = smem_u32(smem);
    const int wid = tid >> 5, lane = tid & 31;

    if (wid == 0) {
        asm volatile("tcgen05.alloc.cta_group::1.sync.aligned.shared::cta.b32 [%0], %1;"
                     :: "r"(sb), "r"(256u) : "memory");
        asm volatile("tcgen05.relinquish_alloc_permit.cta_group::1.sync.aligned;");
    }
    if (tid == 0) {
        asm volatile("mbarrier.init.shared.b64 [%0], 1;" :: "r"(sb + 16) : "memory");
        asm volatile("mbarrier.init.shared.b64 [%0], 1;" :: "r"(sb + 24) : "memory");
    }

    const bf16* Aph = Ah + (long)(by * 128) * lda;
    const bf16* Apl = Al + (long)(by * 128) * lda;
    const bf16* Bph = Bh + (long)(bx * 256) * ldb;
    const bf16* Bpl = Bl + (long)(bx * 256) * ldb;

    // per-thread slots: A plane 1024 x 16B, B plane 2048 x 16B
    auto issue_chunk = [&](int c2, int s) {
        const long kc = (long)c2 << 6;   // 64 bf16 per chunk
        const uint32_t st = sb + 1024u + (uint32_t)s * (uint32_t)STAGE_BYTES;
#pragma unroll
        for (int i = 0; i < 4; ++i) {    // A planes
            int slot = tid + i * 256;
            int row = slot >> 3, c16 = slot & 7;
            uint32_t off = (uint32_t)(row * 128 + c16 * 16);
            uint32_t sw  = off ^ ((off >> 3) & 0x70u);
            const long g = (long)row * lda + kc + c16 * 8;
            cp16(st + sw,         Aph + g);
            cp16(st + 16384 + sw, Apl + g);
        }
#pragma unroll
        for (int i = 0; i < 8; ++i) {    // B planes (256 rows)
            int slot = tid + i * 256;
            int row = slot >> 3, c16 = slot & 7;
            uint32_t off = (uint32_t)(row * 128 + c16 * 16);
            uint32_t sw  = off ^ ((off >> 3) & 0x70u);
            const long g = (long)row * ldb + kc + c16 * 8;
            cp16(st + 32768 + sw, Bph + g);
            cp16(st + 65536 + sw, Bpl + g);
        }
        asm volatile("cp.async.commit_group;" ::: "memory");
    };

    const int nch = K >> 6;   // >= 8 for all our GEMMs
    issue_chunk(0, 0);
    issue_chunk(1, 1);
    __syncthreads();
    uint32_t tmem;
    asm volatile("ld.shared.b32 %0, [%1];" : "=r"(tmem) : "r"(sb));

    int ph[2] = {0, 0};
    for (int c2 = 0; c2 < nch; ++c2) {
        const int s = c2 & 1;
        if (c2 + 1 < nch) asm volatile("cp.async.wait_group 1;" ::: "memory");
        else              asm volatile("cp.async.wait_group 0;" ::: "memory");
        asm volatile("fence.proxy.async.shared::cta;" ::: "memory");
        __syncthreads();

        if (wid == 0 && elect1()) {
            const uint32_t st = sb + 1024u + (uint32_t)s * (uint32_t)STAGE_BYTES;
            uint64_t dAh = mkdesc(st), dAl = dAh + 1024;            // +16KB
            uint64_t dBh = mkdesc(st + 32768), dBl = dBh + 2048;    // +32KB
#pragma unroll
            for (int ks = 0; ks < 4; ++ks) {   // K=16 bf16 per MMA step
                uint64_t o = (uint64_t)(ks * 2);   // 32B per step
                mma_bf16(tmem, dAh + o, dBh + o, IDESC_BF16_256, (c2 == 0 && ks == 0) ? 0u : 1u);
                mma_bf16(tmem, dAh + o, dBl + o, IDESC_BF16_256, 1u);
                mma_bf16(tmem, dAl + o, dBh + o, IDESC_BF16_256, 1u);
            }
            asm volatile(
                "tcgen05.commit.cta_group::1.mbarrier::arrive::one.shared::cluster.b64 [%0];"
                :: "r"(sb + 16 + 8 * s) : "memory");
        }

        // Refill stage s with chunk c2+2: wait this chunk's MMA first.
        if (c2 + 2 < nch) {
            mbar_wait(sb + 16 + 8 * s, ph[s]); ph[s] ^= 1;
            issue_chunk(c2 + 2, s);
        }
    }
    {
        const int sl = (nch - 1) & 1;
        mbar_wait(sb + 16 + 8 * sl, ph[sl]);
    }
    asm volatile("tcgen05.fence::after_thread_sync;" ::: "memory");

    // Epilogue: warps 0-3 cols 0..127, warps 4-7 cols 128..255.
    const int sub = wid & 3, half = wid >> 2;
    const uint32_t woff = (uint32_t)sub << 21;
    const int m = by * 128 + sub * 32 + lane;
    const float* bp2 = bias ? (bias + (long)bx * 256) : nullptr;
#pragma unroll
    for (int blk = 0; blk < 4; ++blk) {
        const int c0 = half * 128 + blk * 32;
        uint32_t r[32];
        LDTM_X32(r, tmem + woff + (uint32_t)c0);
        asm volatile("tcgen05.wait::ld.sync.aligned;" ::: "memory");
        const long crow = (long)m * ldc + bx * 256 + c0;
#pragma unroll
        for (int j = 0; j < 8; ++j) {
            float4 bv = make_float4(0.f, 0.f, 0.f, 0.f);
            if (bp2) bv = *(const float4*)(bp2 + c0 + j * 4);
            float4 o;
            o.x = fmaf(__uint_as_float(r[j * 4 + 0]), alpha, bv.x);
            o.y = fmaf(__uint_as_float(r[j * 4 + 1]), alpha, bv.y);
            o.z = fmaf(__uint_as_float(r[j * 4 + 2]), alpha, bv.z);
            o.w = fmaf(__uint_as_float(r[j * 4 + 3]), alpha, bv.w);
            if (doRelu) {
                o.x = fmaxf(o.x, 0.f); o.y = fmaxf(o.y, 0.f);
                o.z = fmaxf(o.z, 0.f); o.w = fmaxf(o.w, 0.f);
            }
            if (C) *(float4*)(C + crow + j * 4) = o;
            if (Ch) {
                bf16 h4[4], l4[4];
                split2b(o.x, h4[0], l4[0]); split2b(o.y, h4[1], l4[1]);
                split2b(o.z, h4[2], l4[2]); split2b(o.w, h4[3], l4[3]);
                uint2 hv, lv;
                hv.x = (uint32_t)__bfloat16_as_ushort(h4[0])
                     | ((uint32_t)__bfloat16_as_ushort(h4[1]) << 16);
                hv.y = (uint32_t)__bfloat16_as_ushort(h4[2])
                     | ((uint32_t)__bfloat16_as_ushort(h4[3]) << 16);
                lv.x = (uint32_t)__bfloat16_as_ushort(l4[0])
                     | ((uint32_t)__bfloat16_as_ushort(l4[1]) << 16);
                lv.y = (uint32_t)__bfloat16_as_ushort(l4[2])
                     | ((uint32_t)__bfloat16_as_ushort(l4[3]) << 16);
                *(uint2*)(Ch + crow + j * 4) = hv;
                *(uint2*)(Cl + crow + j * 4) = lv;
            }
        }
    }
    __syncthreads();
    if (wid == 0) {
        asm volatile("tcgen05.dealloc.cta_group::1.sync.aligned.b32 %0, %1;"
                     :: "r"(tmem), "r"(256u));
    }

#else  // ------- FFMA fallback (portable compile pass only; never selected) ---

    float (*As)[132] = (float(*)[132])(smem);
    float (*Bs)[132] = (float(*)[132])(smem + 16 * 132 * sizeof(float));

    const int arow = tid >> 2;
    const int akv  = (tid & 3) << 2;
    const int tx = tid & 15, ty = tid >> 4;
    const int m0 = ty << 2, n0 = tx << 2;

    auto rec4 = [](const bf16* ph2, const bf16* pl2, float* o) {
#pragma unroll
        for (int j = 0; j < 4; ++j)
            o[j] = __bfloat162float(ph2[j]) + __bfloat162float(pl2[j]);
    };

    for (int hh2 = 0; hh2 < 2; ++hh2) {
        const int bxe = bx * 2 + hh2;
        if (causal && bxe > by) continue;

        const bf16* Aph = Ah + (long)(by * 128 + arow) * lda + akv;
        const bf16* Apl = Al + (long)(by * 128 + arow) * lda + akv;
        const bf16* Bph = Bh + (long)(bxe * 128 + arow) * ldb + akv;
        const bf16* Bpl = Bl + (long)(bxe * 128 + arow) * ldb + akv;

        float acc[8][8];
#pragma unroll
        for (int i = 0; i < 8; ++i)
#pragma unroll
            for (int j = 0; j < 8; ++j) acc[i][j] = 0.f;

        const int ntiles = K >> 4;
        for (int t = 0; t < ntiles; ++t) {
            float a0[4], a1[4], b0[4], b1[4];
            rec4(Aph, Apl, a0);
            rec4(Aph + (long)64 * lda, Apl + (long)64 * lda, a1);
            rec4(Bph, Bpl, b0);
            rec4(Bph + (long)64 * ldb, Bpl + (long)64 * ldb, b1);
            __syncthreads();
#pragma unroll
            for (int j = 0; j < 4; ++j) {
                As[akv + j][arow]      = a0[j];
                As[akv + j][arow + 64] = a1[j];
                Bs[akv + j][arow]      = b0[j];
                Bs[akv + j][arow + 64] = b1[j];
            }
            __syncthreads();
#pragma unroll
            for (int k = 0; k < 16; ++k) {
                float4 av0 = *(const float4*)&As[k][m0];
                float4 av1 = *(const float4*)&As[k][m0 + 64];
                float4 bv0 = *(const float4*)&Bs[k][n0];
                float4 bv1 = *(const float4*)&Bs[k][n0 + 64];
                float av[8] = {av0.x, av0.y, av0.z, av0.w, av1.x, av1.y, av1.z, av1.w};
                float bv[8] = {bv0.x, bv0.y, bv0.z, bv0.w, bv1.x, bv1.y, bv1.z, bv1.w};
#pragma unroll
                for (int i = 0; i < 8; ++i)
#pragma unroll
                    for (int j = 0; j < 8; ++j)
                        acc[i][j] = fmaf(av[i], bv[j], acc[i][j]);
            }
            Aph += 16; Apl += 16; Bph += 16; Bpl += 16;
        }

#pragma unroll
        for (int i = 0; i < 8; ++i) {
            int m = by * 128 + m0 + ((i < 4) ? i : (64 + i - 4));
#pragma unroll
            for (int j = 0; j < 8; ++j) {
                int n = bxe * 128 + n0 + ((j < 4) ? j : (64 + j - 4));
                float bb = bias ? bias[n] : 0.f;
                float v = fmaf(acc[i][j], alpha, bb);
                v = doRelu ? fmaxf(v, 0.f) : v;
                long idx = (long)m * ldc + n;
                if (C) C[idx] = v;
                if (Ch) { bf16 hi, lo; split2b(v, hi, lo); Ch[idx] = hi; Cl[idx] = lo; }
            }
        }
        __syncthreads();
    }
#endif  // TC_OK
}

// ---------------------------------------------------------------------------
// 32x32 tiled transpose emitting bf16 hi/lo planes
// ---------------------------------------------------------------------------
__global__ void transpose_k(const float* __restrict__ in,
                            bf16* __restrict__ oh, bf16* __restrict__ ol,
                            int R, int Cc)
{
    __shared__ float t[32][33];
    const int c0 = blockIdx.x * 32, r0 = blockIdx.y * 32;
    const int x = threadIdx.x, y = threadIdx.y;
#pragma unroll
    for (int i = 0; i < 32; i += 8)
        t[y + i][x] = in[(long)(r0 + y + i) * Cc + c0 + x];
    __syncthreads();
#pragma unroll
    for (int i = 0; i < 32; i += 8) {
        float v = t[x][y + i];
        bf16 hi, lo; split2b(v, hi, lo);
        long idx = (long)(c0 + y + i) * R + r0 + x;
        oh[idx] = hi; ol[idx] = lo;
    }
}

// ---------------------------------------------------------------------------
// Elementwise kernels
// ---------------------------------------------------------------------------
__global__ void embed_kernel(const int* __restrict__ x,
                             const float* __restrict__ tok,
                             const float* __restrict__ pos,
                             float* __restrict__ h,
                             bf16* __restrict__ hh, bf16* __restrict__ hl)
{
    int idx = blockIdx.x * 256 + threadIdx.x;
    int bt  = idx >> 9;
    int e   = idx & 511;
    int token = x[bt];
    float v = tok[(long)token * E_ + e] + pos[((bt & (T_ - 1)) << 9) + e];
    h[idx] = v;
    bf16 hi, lo; split2b(v, hi, lo);
    hh[idx] = hi; hl[idx] = lo;
}

__global__ void softmax_causal_kernel(const float* __restrict__ att,
                                      bf16* __restrict__ ah,
                                      bf16* __restrict__ al)
{
    const int i = blockIdx.x & (T_ - 1);
    const long base = (long)blockIdx.x * T_;
    const float* row = att + base;
    const int n = i + 1;
    const int tid = threadIdx.x, lane = tid & 31, w = tid >> 5;
    __shared__ float redm[4], reds[4];

    float mx = -INFINITY;
    for (int j = tid; j < n; j += 128) mx = fmaxf(mx, row[j]);
#pragma unroll
    for (int o = 16; o > 0; o >>= 1) mx = fmaxf(mx, __shfl_xor_sync(0xffffffffu, mx, o));
    if (lane == 0) redm[w] = mx;
    __syncthreads();
    mx = fmaxf(fmaxf(redm[0], redm[1]), fmaxf(redm[2], redm[3]));

    float s = 0.f;
    for (int j = tid; j < n; j += 128) s += expf(row[j] - mx);
#pragma unroll
    for (int o = 16; o > 0; o >>= 1) s += __shfl_xor_sync(0xffffffffu, s, o);
    if (lane == 0) reds[w] = s;
    __syncthreads();
    s = reds[0] + reds[1] + reds[2] + reds[3];

    const float inv = 1.f / s;
    for (int j = tid; j < T_; j += 128) {
        float p = (j < n) ? expf(row[j] - mx) * inv : 0.f;
        bf16 hi, lo; split2b(p, hi, lo);
        ah[base + j] = hi; al[base + j] = lo;
    }
}

// Residual add + LN; `parts` holds 4 split-K partials (stride pstride); bias added here.
__global__ void add_ln_kernel(const float* __restrict__ parts, long pstride,
                              const float* __restrict__ bias,
                              float* __restrict__ h,
                              bf16* __restrict__ hh, bf16* __restrict__ hl,
                              const float* __restrict__ gam,
                              const float* __restrict__ bet)
{
    const long row = blockIdx.x;
    float* hr = h + row * E_;
    const int tid = threadIdx.x, lane = tid & 31, w = tid >> 5;
    __shared__ float r1[4], r2[4];

    float x[4];
    float s = 0.f;
#pragma unroll
    for (int i = 0; i < 4; ++i) {
        int e = tid + i * 128;
        long idx = row * E_ + e;
        float a = parts[idx] + parts[pstride + idx]
                + parts[2 * pstride + idx] + parts[3 * pstride + idx]
                + bias[e];
        x[i] = a + hr[e];
        s += x[i];
    }
#pragma unroll
    for (int o = 16; o > 0; o >>= 1) s += __shfl_xor_sync(0xffffffffu, s, o);
    if (lane == 0) r1[w] = s;
    __syncthreads();
    const float m = (r1[0] + r1[1] + r1[2] + r1[3]) * (1.f / E_);

    float d2 = 0.f;
#pragma unroll
    for (int i = 0; i < 4; ++i) { float d = x[i] - m; d2 += d * d; }
#pragma unroll
    for (int o = 16; o > 0; o >>= 1) d2 += __shfl_xor_sync(0xffffffffu, d2, o);
    if (lane == 0) r2[w] = d2;
    __syncthreads();
    const float var = (r2[0] + r2[1] + r2[2] + r2[3]) * (1.f / E_);
    const float r = rsqrtf(var + 1e-5f);

#pragma unroll
    for (int i = 0; i < 4; ++i) {
        int e = tid + i * 128;
        float y = (x[i] - m) * r * gam[e] + bet[e];
        hr[e] = y;
        bf16 hi, lo; split2b(y, hi, lo);
        hh[row * E_ + e] = hi; hl[row * E_ + e] = lo;
    }
}

__global__ void emb_stats_kernel(const float* __restrict__ h,
                                 float* __restrict__ omean,
                                 float* __restrict__ omax)
{
    const int b = blockIdx.x, e = blockIdx.y * 32 + (threadIdx.x & 31);
    const int lane = threadIdx.x & 31, wy = threadIdx.x >> 5;
    __shared__ float ss[8][32], sm[8][32];
    float s = 0.f, m = -INFINITY;
    for (int t = wy; t < T_; t += 8) {
        float v = h[((long)(b * T_ + t)) * E_ + e];
        s += v; m = fmaxf(m, v);
    }
    ss[wy][lane] = s; sm[wy][lane] = m;
    __syncthreads();
    if (wy == 0) {
        float S = 0.f, M = -INFINITY;
#pragma unroll
        for (int w = 0; w < 8; ++w) { S += ss[w][lane]; M = fmaxf(M, sm[w][lane]); }
        omean[b * E_ + e] = S * (1.f / T_);
        omax [b * E_ + e] = M;
    }
}

__global__ void ls_partial_kernel(const float* __restrict__ logits,
                                  float* __restrict__ pm,
                                  float* __restrict__ ps)
{
    const int split = blockIdx.x & 3;
    const int tcol  = blockIdx.x >> 2;
    const int b     = tcol >> 5;
    const int lane  = threadIdx.x & 31, wy = threadIdx.x >> 5;
    const int t     = ((tcol & 31) << 5) + lane;
    const long base = (long)b * BNT_T + t;

    float mx = -INFINITY, s = 0.f;
    const int n0 = split * (NT_ / 4);
#pragma unroll 4
    for (int n = n0 + wy; n < n0 + NT_ / 4; n += 8) {
        float v = logits[base + (long)n * T_];
        if (v > mx) { s = s * __expf(mx - v) + 1.f; mx = v; }
        else        { s += __expf(v - mx); }
    }
    __shared__ float shm[8][32], shs[8][32];
    shm[wy][lane] = mx; shs[wy][lane] = s;
    __syncthreads();
    if (wy == 0) {
        float M = -INFINITY, S = 0.f;
#pragma unroll
        for (int w = 0; w < 8; ++w) {
            float m2 = shm[w][lane], s2 = shs[w][lane];
            if (m2 > M) { S = S * __expf(M - m2) + s2; M = m2; }
            else        { S += s2 * __expf(m2 - M); }
        }
        int idx = b * T_ + t;
        pm[idx * 4 + split] = M;
        ps[idx * 4 + split] = S;
    }
}

__global__ void ls_combine_kernel(const float* __restrict__ pm,
                                  const float* __restrict__ ps,
                                  float* __restrict__ z)
{
    int idx = blockIdx.x * 256 + threadIdx.x;
    if (idx >= BT_) return;
    float M = -INFINITY, S = 0.f;
#pragma unroll
    for (int k = 0; k < 4; ++k) {
        float m2 = pm[idx * 4 + k], s2 = ps[idx * 4 + k];
        if (m2 > M) { S = S * expf(M - m2) + s2; M = m2; }
        else        { S += s2 * expf(m2 - M); }
    }
    z[idx] = M + logf(S);
}

__global__ void ls_write_kernel(const float* __restrict__ logits,
                                const float* __restrict__ z,
                                float* __restrict__ out)
{
    long i4 = (long)blockIdx.x * 256 + threadIdx.x;
    long f  = i4 << 2;
    int  t  = (int)(f & (T_ - 1));
    int  b  = (f >= BNT_T) ? 1 : 0;
    float4 v  = *(const float4*)(logits + f);
    float4 zz = *(const float4*)(z + b * T_ + t);
    float4 o;
    o.x = v.x - zz.x; o.y = v.y - zz.y; o.z = v.z - zz.z; o.w = v.w - zz.w;
    *(float4*)(out + f) = o;
}

// ---------------------------------------------------------------------------
// Host-side launch helpers
// ---------------------------------------------------------------------------
static inline void gemm(int Mtiles, int Ntiles256, int K,
                        const bf16* Ah, const bf16* Al, int lda,
                        const bf16* Bh, const bf16* Bl, int ldb,
                        float* C, bf16* Ch, bf16* Cl, int ldc,
                        const float* bias,
                        float alpha, int relu, int causal,
                        int batches = 1, int innerCnt = 1,
                        long aO = 0, long aI = 0, long bO = 0, long bI = 0,
                        long cO = 0, long cI = 0)
{
    dim3 grid(Ntiles256, Mtiles, batches), blk(256);
    gemm_tc<<<grid, blk, SMEM_BYTES>>>(K, Ah, Al, lda, Bh, Bl, ldb,
                                       C, Ch, Cl, ldc, bias,
                                       alpha, relu, causal, innerCnt,
                                       aO, aI, bO, bI, cO, cI);
}

static inline void transp(const float* in, bf16* oh, bf16* ol, int R, int C)
{
    dim3 g(C / 32, R / 32), b(32, 8);
    transpose_k<<<g, b>>>(in, oh, ol, R, C);
}

extern "C" void kernel_launch(void* const* d_in, const int* in_sizes, int n_in,
                              void* d_out, int out_size)
{
    const int*   x    = (const int*)  d_in[0];
    const float* tok  = (const float*)d_in[1];
    const float* pos  = (const float*)d_in[2];
    const float* Wq   = (const float*)d_in[3];
    const float* Wk   = (const float*)d_in[4];
    const float* Wv   = (const float*)d_in[5];
    const float* Wu   = (const float*)d_in[6];
    const float* bu   = (const float*)d_in[7];
    const float* g1   = (const float*)d_in[8];
    const float* b1n  = (const float*)d_in[9];
    const float* g2   = (const float*)d_in[10];
    const float* b2n  = (const float*)d_in[11];
    const float* W1   = (const float*)d_in[12];
    const float* bf1  = (const float*)d_in[13];
    const float* W2   = (const float*)d_in[14];
    const float* bf2  = (const float*)d_in[15];
    const float* Wp   = (const float*)d_in[16];
    const float* bp   = (const float*)d_in[17];
    float* out = (float*)d_out;

    cudaFuncSetAttribute(gemm_tc, cudaFuncAttributeMaxDynamicSharedMemorySize,
                         SMEM_BYTES);

    float *h, *att, *logits, *pm, *ps, *z;
    bf16 *hh, *hl, *qh, *ql, *kh, *kl, *vth, *vtl, *oh, *ol, *ath, *atl, *ffh, *ffl;
    cudaGetSymbolAddress((void**)&h,    g_h);
    cudaGetSymbolAddress((void**)&hh,   g_h_hi);
    cudaGetSymbolAddress((void**)&hl,   g_h_lo);
    cudaGetSymbolAddress((void**)&qh,   g_q_hi);
    cudaGetSymbolAddress((void**)&ql,   g_q_lo);
    cudaGetSymbolAddress((void**)&kh,   g_k_hi);
    cudaGetSymbolAddress((void**)&kl,   g_k_lo);
    cudaGetSymbolAddress((void**)&vth,  g_vt_hi);
    cudaGetSymbolAddress((void**)&vtl,  g_vt_lo);
    cudaGetSymbolAddress((void**)&oh,   g_o_hi);
    cudaGetSymbolAddress((void**)&ol,   g_o_lo);
    cudaGetSymbolAddress((void**)&att,  g_att);
    cudaGetSymbolAddress((void**)&ath,  g_at_hi);
    cudaGetSymbolAddress((void**)&atl,  g_at_lo);
    cudaGetSymbolAddress((void**)&ffh,  g_ff_hi);
    cudaGetSymbolAddress((void**)&ffl,  g_ff_lo);
    cudaGetSymbolAddress((void**)&logits, g_logits);
    cudaGetSymbolAddress((void**)&pm,   g_pm);
    cudaGetSymbolAddress((void**)&ps,   g_ps);
    cudaGetSymbolAddress((void**)&z,    g_z);

    bf16 *WqTh, *WqTl, *WkTh, *WkTl, *WvTh, *WvTl, *WuTh, *WuTl;
    bf16 *W1Th, *W1Tl, *W2Th, *W2Tl, *WpTh, *WpTl;
    cudaGetSymbolAddress((void**)&WqTh, g_WqT_hi);
    cudaGetSymbolAddress((void**)&WqTl, g_WqT_lo);
    cudaGetSymbolAddress((void**)&WkTh, g_WkT_hi);
    cudaGetSymbolAddress((void**)&WkTl, g_WkT_lo);
    cudaGetSymbolAddress((void**)&WvTh, g_WvT_hi);
    cudaGetSymbolAddress((void**)&WvTl, g_WvT_lo);
    cudaGetSymbolAddress((void**)&WuTh, g_WuT_hi);
    cudaGetSymbolAddress((void**)&WuTl, g_WuT_lo);
    cudaGetSymbolAddress((void**)&W1Th, g_W1T_hi);
    cudaGetSymbolAddress((void**)&W1Tl, g_W1T_lo);
    cudaGetSymbolAddress((void**)&W2Th, g_W2T_hi);
    cudaGetSymbolAddress((void**)&W2Tl, g_W2T_lo);
    cudaGetSymbolAddress((void**)&WpTh, g_WpT_hi);
    cudaGetSymbolAddress((void**)&WpTl, g_WpT_lo);

    // Weight transposes + bf16 hi/lo split (once per launch)
    for (int l = 0; l < L_; ++l) {
        transp(Wq + (long)l * E_ * HE_, WqTh + (long)l * HE_ * E_,
               WqTl + (long)l * HE_ * E_, E_,  HE_);
        transp(Wk + (long)l * E_ * HE_, WkTh + (long)l * HE_ * E_,
               WkTl + (long)l * HE_ * E_, E_,  HE_);
        transp(Wv + (long)l * E_ * HE_, WvTh + (long)l * HE_ * E_,
               WvTl + (long)l * HE_ * E_, E_,  HE_);
        transp(Wu + (long)l * HE_ * E_, WuTh + (long)l * E_ * HE_,
               WuTl + (long)l * E_ * HE_, HE_, E_);
        transp(W1 + (long)l * E_ * FF_, W1Th + (long)l * FF_ * E_,
               W1Tl + (long)l * FF_ * E_, E_,  FF_);
        transp(W2 + (long)l * FF_ * E_, W2Th + (long)l * E_ * FF_,
               W2Tl + (long)l * E_ * FF_, FF_, E_);
    }
    transp(Wp, WpTh, WpTl, E_, NT_);

    embed_kernel<<<(BT_ * E_) / 256, 256>>>(x, tok, pos, h, hh, hl);

    const float qs = 0.21022410381342863f;   // 512^(-1/4)
    const long PS = (long)BT_ * E_;           // split-K partial stride

    for (int l = 0; l < L_; ++l) {
        const long wqo = (long)l * HE_ * E_;
        const long wuo = (long)l * E_ * HE_;
        const long w1o = (long)l * FF_ * E_;
        const long w2o = (long)l * E_ * FF_;
        const float* bu_l  = bu  + (long)l * E_;
        const float* g1_l  = g1  + (long)l * E_;
        const float* b1_l  = b1n + (long)l * E_;
        const float* g2_l  = g2  + (long)l * E_;
        const float* b2_l  = b2n + (long)l * E_;
        const float* bf1_l = bf1 + (long)l * FF_;
        const float* bf2_l = bf2 + (long)l * E_;

        // q = qs * h @ Wq ; k = qs * h @ Wk  -> pairs  (N=4096: 16 tiles)
        gemm(16, 16, E_, hh, hl, E_, WqTh + wqo, WqTl + wqo, E_,
             nullptr, qh, ql, HE_, nullptr, qs, 0, 0);
        gemm(16, 16, E_, hh, hl, E_, WkTh + wqo, WkTl + wqo, E_,
             nullptr, kh, kl, HE_, nullptr, qs, 0, 0);
        // Vt (HE x BT) = WvT @ h^T -> pair  (N=2048: 8 tiles)
        gemm(32, 8, E_, WvTh + wqo, WvTl + wqo, E_, hh, hl, E_,
             nullptr, vth, vtl, BT_, nullptr, 1.f, 0, 0);

        // scores: att = q_bh @ k_bh^T (plain), causal tile skip (N=1024: 4 tiles)
        gemm(8, 4, E_, qh, ql, HE_, kh, kl, HE_,
             att, nullptr, nullptr, T_, nullptr, 1.f, 0, 1,
             B_ * H_, H_,
             (long)T_ * HE_, (long)E_,
             (long)T_ * HE_, (long)E_,
             (long)H_ * T_ * T_, (long)T_ * T_);

        softmax_causal_kernel<<<B_ * H_ * T_, 128>>>(att, ath, atl);

        // o = att @ V -> pair  (N=512 per head: 2 tiles)
        gemm(8, 2, T_, ath, atl, T_, vth, vtl, BT_,
             nullptr, oh, ol, HE_, nullptr, 1.f, 0, 0,
             B_ * H_, H_,
             (long)H_ * T_ * T_, (long)T_ * T_,
             (long)T_,           (long)E_ * BT_,
             (long)T_ * HE_,     (long)E_);

        // unify heads: split-K=4 partials into att scratch (bias in add_ln)
        gemm(16, 2, HE_ / 4, oh, ol, HE_, WuTh + wuo, WuTl + wuo, HE_,
             att, nullptr, nullptr, E_, nullptr, 1.f, 0, 0,
             4, 4, 0, (long)(HE_ / 4), 0, (long)(HE_ / 4), 0, PS);
        add_ln_kernel<<<BT_, 128>>>(att, PS, bu_l, h, hh, hl, g1_l, b1_l);

        // FFN
        gemm(16, 8, E_, hh, hl, E_, W1Th + w1o, W1Tl + w1o, E_,
             nullptr, ffh, ffl, FF_, bf1_l, 1.f, 1, 0);
        gemm(16, 2, FF_ / 4, ffh, ffl, FF_, W2Th + w2o, W2Tl + w2o, FF_,
             att, nullptr, nullptr, E_, nullptr, 1.f, 0, 0,
             4, 4, 0, (long)(FF_ / 4), 0, (long)(FF_ / 4), 0, PS);
        add_ln_kernel<<<BT_, 128>>>(att, PS, bf2_l, h, hh, hl, g2_l, b2_l);
    }

    // emb_mean / emb_max (flattened after the log_softmax block)
    if ((long)out_size >= LOGITS_N + 2L * B_ * E_) {
        emb_stats_kernel<<<dim3(B_, E_ / 32), 256>>>(
            h, out + LOGITS_N, out + LOGITS_N + B_ * E_);
    }

    // vocab projection: N=32000 -> 125 tiles
    gemm(16, NT_ / 256, E_, hh, hl, E_, WpTh, WpTl, E_,
         logits, nullptr, nullptr, NT_, bp, 1.f, 0, 0);

    // log_softmax over axis 1 of the raw (B, NT, T) reshape
    ls_partial_kernel<<<256, 256>>>(logits, pm, ps);
    ls_combine_kernel<<<(BT_ + 255) / 256, 256>>>(pm, ps, z);
    ls_write_kernel<<<(int)(LOGITS_N / 4 / 256), 256>>>(logits, z, out);
}

// round 11
// speedup vs baseline: 3.8388x; 1.0093x over previous
#include <cuda_runtime.h>
#include <cuda_bf16.h>
#include <math.h>
#include <stdint.h>

// Arch gate: tcgen05 PTX is only legal on the sm_103a arch-specific target.
#if defined(__CUDA_ARCH__) && (__CUDA_ARCH__ >= 1000) && \
    (defined(__CUDA_ARCH_FEAT_SM103_ALL) || defined(__CUDA_ARCH_SPECIFIC__) || \
     defined(__CUDA_ARCH_FEAT_SM100_ALL))
#define TC_OK 1
#else
#define TC_OK 0
#endif

typedef __nv_bfloat16 bf16;

// ---------------------------------------------------------------------------
// Problem dims
// ---------------------------------------------------------------------------
static constexpr int B_  = 2;
static constexpr int T_  = 1024;
static constexpr int E_  = 512;
static constexpr int H_  = 8;
static constexpr int L_  = 4;
static constexpr int NT_ = 32000;
static constexpr int FF_ = 2048;
static constexpr int BT_ = B_ * T_;        // 2048
static constexpr int HE_ = H_ * E_;        // 4096
static constexpr long LOGITS_N = (long)BT_ * NT_;
static constexpr long BNT_T    = (long)NT_ * T_;

// ---------------------------------------------------------------------------
// Scratch (device globals; no allocation allowed).
// ---------------------------------------------------------------------------
__device__ float g_h    [BT_ * E_];
__device__ bf16  g_h_hi [BT_ * E_];
__device__ bf16  g_h_lo [BT_ * E_];
__device__ bf16  g_qk_hi[(size_t)2 * BT_ * HE_];   // q then k
__device__ bf16  g_qk_lo[(size_t)2 * BT_ * HE_];
__device__ bf16  g_vt_hi[(size_t)HE_ * BT_];
__device__ bf16  g_vt_lo[(size_t)HE_ * BT_];
__device__ bf16  g_o_hi [BT_ * HE_];
__device__ bf16  g_o_lo [BT_ * HE_];
__device__ float g_att  [(size_t)B_ * H_ * T_ * T_];   // scores, then split-K partials
__device__ bf16  g_at_hi[(size_t)B_ * H_ * T_ * T_];
__device__ bf16  g_at_lo[(size_t)B_ * H_ * T_ * T_];
__device__ bf16  g_ff_hi[BT_ * FF_];
__device__ bf16  g_ff_lo[BT_ * FF_];
__device__ float g_logits[(size_t)BT_ * NT_];
__device__ float g_pm   [BT_ * 4];
__device__ float g_ps   [BT_ * 4];
__device__ float g_z    [BT_];

// Transposed, pre-split weights. Wq/Wk combined: [s][l][HE][E], s=0:q, s=1:k.
__device__ bf16 g_WqkT_hi[(size_t)2 * L_ * HE_ * E_];
__device__ bf16 g_WqkT_lo[(size_t)2 * L_ * HE_ * E_];
__device__ bf16 g_WvT_hi[(size_t)L_ * HE_ * E_];
__device__ bf16 g_WvT_lo[(size_t)L_ * HE_ * E_];
__device__ bf16 g_WuT_hi[(size_t)L_ * E_ * HE_];
__device__ bf16 g_WuT_lo[(size_t)L_ * E_ * HE_];
__device__ bf16 g_W1T_hi[(size_t)L_ * FF_ * E_];
__device__ bf16 g_W1T_lo[(size_t)L_ * FF_ * E_];
__device__ bf16 g_W2T_hi[(size_t)L_ * E_ * FF_];
__device__ bf16 g_W2T_lo[(size_t)L_ * E_ * FF_];
__device__ bf16 g_WpT_hi[(size_t)NT_ * E_];
__device__ bf16 g_WpT_lo[(size_t)NT_ * E_];

// ---------------------------------------------------------------------------
// Helpers
// ---------------------------------------------------------------------------
__device__ __forceinline__ uint32_t smem_u32(const void* p) {
    uint32_t a;
    asm("{ .reg .u64 t; cvta.to.shared.u64 t, %1; cvt.u32.u64 %0, t; }"
        : "=r"(a) : "l"(p));
    return a;
}
__device__ __forceinline__ void split2b(float v, bf16& hi, bf16& lo) {
    hi = __float2bfloat16(v);
    lo = __float2bfloat16(v - __bfloat162float(hi));
}

#if TC_OK
__device__ __forceinline__ int elect1() {
    uint32_t p;
    asm volatile("{\n .reg .pred p;\n elect.sync _|p, 0xFFFFFFFF;\n selp.b32 %0,1,0,p;\n}"
                 : "=r"(p));
    return (int)p;
}
__device__ __forceinline__ uint64_t mkdesc(uint32_t addr) {
    const uint64_t base = (uint64_t(2) << 61) | (uint64_t(1) << 46)
                        | (uint64_t(64) << 32) | (uint64_t(1) << 16);
    return base | ((uint64_t)(addr >> 4) & 0x3FFF);
}
__device__ __forceinline__ void mbar_wait(uint32_t mbar, int parity) {
    asm volatile(
        "{\n\t.reg .pred P;\n\t"
        "W_%=:\n\t"
        "mbarrier.try_wait.parity.acquire.cta.shared::cta.b64 P, [%0], %1, 0x989680;\n\t"
        "@P bra.uni D_%=;\n\t"
        "bra.uni W_%=;\n\t"
        "D_%=:\n\t}"
        :: "r"(mbar), "r"(parity) : "memory");
}
__device__ __forceinline__ void mma_bf16(uint32_t d, uint64_t ad, uint64_t bd,
                                         uint32_t idesc, uint32_t en) {
    asm volatile(
        "{\n .reg .pred p;\n setp.ne.u32 p, %4, 0;\n"
        " tcgen05.mma.cta_group::1.kind::f16 [%0], %1, %2, %3, {%5,%5,%5,%5}, p;\n}"
        :: "r"(d), "l"(ad), "l"(bd), "r"(idesc), "r"(en), "r"(0u) : "memory");
}
__device__ __forceinline__ void cp16(uint32_t dst, const void* src) {
    asm volatile("cp.async.cg.shared.global [%0], [%1], 16;"
                 :: "r"(dst), "l"(src) : "memory");
}

#define LDTM_X32(r, addr) \
    asm volatile( \
        "tcgen05.ld.sync.aligned.32x32b.x32.b32 " \
        "{%0, %1, %2, %3, %4, %5, %6, %7, " \
        " %8, %9, %10, %11, %12, %13, %14, %15, " \
        " %16, %17, %18, %19, %20, %21, %22, %23, " \
        " %24, %25, %26, %27, %28, %29, %30, %31}, [%32];" \
        : "=r"((r)[0]),  "=r"((r)[1]),  "=r"((r)[2]),  "=r"((r)[3]), \
          "=r"((r)[4]),  "=r"((r)[5]),  "=r"((r)[6]),  "=r"((r)[7]), \
          "=r"((r)[8]),  "=r"((r)[9]),  "=r"((r)[10]), "=r"((r)[11]), \
          "=r"((r)[12]), "=r"((r)[13]), "=r"((r)[14]), "=r"((r)[15]), \
          "=r"((r)[16]), "=r"((r)[17]), "=r"((r)[18]), "=r"((r)[19]), \
          "=r"((r)[20]), "=r"((r)[21]), "=r"((r)[22]), "=r"((r)[23]), \
          "=r"((r)[24]), "=r"((r)[25]), "=r"((r)[26]), "=r"((r)[27]), \
          "=r"((r)[28]), "=r"((r)[29]), "=r"((r)[30]), "=r"((r)[31]) \
        : "r"(addr))
#endif  // TC_OK

// idesc kind::f16: dtype=F32(1<<4), atype=BF16(1<<7), btype=BF16(1<<10),
// N=256 (32<<17), M=128 (8<<24)
static constexpr uint32_t IDESC_BF16_256 =
    (1u << 4) | (1u << 7) | (1u << 10) | (32u << 17) | (8u << 24);

// SMEM: [0] tmem ptr, [16/24] mbarriers; 2 stages of 96KB:
// per stage: A_hi(16K) A_lo(16K) B_hi(32K) B_lo(32K); rows 128B = 64 bf16.
static constexpr int STAGE_BYTES = 98304;
static constexpr int SMEM_BYTES  = 1024 + 2 * STAGE_BYTES;   // 197632

// ---------------------------------------------------------------------------
// NT-GEMM (128x256 tile) on bf16 hi/lo planes:
//   C[m][n] = alpha * sum_k A[m][k]*B[n][k] + bias[n]   (3x bf16, fp32 acc)
// cp.async 2-stage pipeline, K-chunks of 64. Requires K % 64 == 0, N % 256 == 0.
// ---------------------------------------------------------------------------
__global__ __launch_bounds__(256, 1)
void gemm_tc(int K,
             const bf16* __restrict__ Ah, const bf16* __restrict__ Al, int lda,
             const bf16* __restrict__ Bh, const bf16* __restrict__ Bl, int ldb,
             float* __restrict__ C, bf16* __restrict__ Ch, bf16* __restrict__ Cl,
             int ldc,
             const float* __restrict__ bias,
             float alpha, int doRelu, int causal, int innerCnt,
             long aO, long aI, long bO, long bI, long cO, long cI)
{
    const int bx = blockIdx.x, by = blockIdx.y;
    if (causal && 2 * bx > by) return;
    {
        const int bz = blockIdx.z;
        const int oz = bz / innerCnt, iz = bz - oz * innerCnt;
        const long ao = (long)oz * aO + (long)iz * aI;
        const long bo = (long)oz * bO + (long)iz * bI;
        const long co = (long)oz * cO + (long)iz * cI;
        Ah += ao; Al += ao; Bh += bo; Bl += bo;
        if (C)  C  += co;
        if (Ch) { Ch += co; Cl += co; }
    }
    extern __shared__ char smem[];
    const int tid = threadIdx.x;

#if TC_OK
    const uint32_t sb = smem_u32(smem);
    const int wid = tid >> 5, lane = tid & 31;

    if (wid == 0) {
        asm volatile("tcgen05.alloc.cta_group::1.sync.aligned.shared::cta.b32 [%0], %1;"
                     :: "r"(sb), "r"(256u) : "memory");
        asm volatile("tcgen05.relinquish_alloc_permit.cta_group::1.sync.aligned;");
    }
    if (tid == 0) {
        asm volatile("mbarrier.init.shared.b64 [%0], 1;" :: "r"(sb + 16) : "memory");
        asm volatile("mbarrier.init.shared.b64 [%0], 1;" :: "r"(sb + 24) : "memory");
    }

    const bf16* Aph = Ah + (long)(by * 128) * lda;
    const bf16* Apl = Al + (long)(by * 128) * lda;
    const bf16* Bph = Bh + (long)(bx * 256) * ldb;
    const bf16* Bpl = Bl + (long)(bx * 256) * ldb;

    // per-thread slots: A plane 1024 x 16B, B plane 2048 x 16B
    auto issue_chunk = [&](int c2, int s) {
        const long kc = (long)c2 << 6;   // 64 bf16 per chunk
        const uint32_t st = sb + 1024u + (uint32_t)s * (uint32_t)STAGE_BYTES;
#pragma unroll
        for (int i = 0; i < 4; ++i) {    // A planes
            int slot = tid + i * 256;
            int row = slot >> 3, c16 = slot & 7;
            uint32_t off = (uint32_t)(row * 128 + c16 * 16);
            uint32_t sw  = off ^ ((off >> 3) & 0x70u);
            const long g = (long)row * lda + kc + c16 * 8;
            cp16(st + sw,         Aph + g);
            cp16(st + 16384 + sw, Apl + g);
        }
#pragma unroll
        for (int i = 0; i < 8; ++i) {    // B planes (256 rows)
            int slot = tid + i * 256;
            int row = slot >> 3, c16 = slot & 7;
            uint32_t off = (uint32_t)(row * 128 + c16 * 16);
            uint32_t sw  = off ^ ((off >> 3) & 0x70u);
            const long g = (long)row * ldb + kc + c16 * 8;
            cp16(st + 32768 + sw, Bph + g);
            cp16(st + 65536 + sw, Bpl + g);
        }
        asm volatile("cp.async.commit_group;" ::: "memory");
    };

    const int nch = K >> 6;   // >= 2 for all our GEMMs
    issue_chunk(0, 0);
    issue_chunk(1, 1);
    __syncthreads();
    uint32_t tmem;
    asm volatile("ld.shared.b32 %0, [%1];" : "=r"(tmem) : "r"(sb));

    int ph[2] = {0, 0};
    for (int c2 = 0; c2 < nch; ++c2) {
        const int s = c2 & 1;
        if (c2 + 1 < nch) asm volatile("cp.async.wait_group 1;" ::: "memory");
        else              asm volatile("cp.async.wait_group 0;" ::: "memory");
        asm volatile("fence.proxy.async.shared::cta;" ::: "memory");
        __syncthreads();

        if (wid == 0 && elect1()) {
            const uint32_t st = sb + 1024u + (uint32_t)s * (uint32_t)STAGE_BYTES;
            uint64_t dAh = mkdesc(st), dAl = dAh + 1024;            // +16KB
            uint64_t dBh = mkdesc(st + 32768), dBl = dBh + 2048;    // +32KB
#pragma unroll
            for (int ks = 0; ks < 4; ++ks) {   // K=16 bf16 per MMA step
                uint64_t o = (uint64_t)(ks * 2);   // 32B per step
                mma_bf16(tmem, dAh + o, dBh + o, IDESC_BF16_256, (c2 == 0 && ks == 0) ? 0u : 1u);
                mma_bf16(tmem, dAh + o, dBl + o, IDESC_BF16_256, 1u);
                mma_bf16(tmem, dAl + o, dBh + o, IDESC_BF16_256, 1u);
            }
            asm volatile(
                "tcgen05.commit.cta_group::1.mbarrier::arrive::one.shared::cluster.b64 [%0];"
                :: "r"(sb + 16 + 8 * s) : "memory");
        }

        // Refill stage s with chunk c2+2: wait this chunk's MMA first.
        if (c2 + 2 < nch) {
            mbar_wait(sb + 16 + 8 * s, ph[s]); ph[s] ^= 1;
            issue_chunk(c2 + 2, s);
        }
    }
    {
        const int sl = (nch - 1) & 1;
        mbar_wait(sb + 16 + 8 * sl, ph[sl]);
    }
    asm volatile("tcgen05.fence::after_thread_sync;" ::: "memory");

    // Epilogue: warps 0-3 cols 0..127, warps 4-7 cols 128..255.
    const int sub = wid & 3, half = wid >> 2;
    const uint32_t woff = (uint32_t)sub << 21;
    const int m = by * 128 + sub * 32 + lane;
    const float* bp2 = bias ? (bias + (long)bx * 256) : nullptr;
#pragma unroll
    for (int blk = 0; blk < 4; ++blk) {
        const int c0 = half * 128 + blk * 32;
        uint32_t r[32];
        LDTM_X32(r, tmem + woff + (uint32_t)c0);
        asm volatile("tcgen05.wait::ld.sync.aligned;" ::: "memory");
        const long crow = (long)m * ldc + bx * 256 + c0;
#pragma unroll
        for (int j = 0; j < 8; ++j) {
            float4 bv = make_float4(0.f, 0.f, 0.f, 0.f);
            if (bp2) bv = *(const float4*)(bp2 + c0 + j * 4);
            float4 o;
            o.x = fmaf(__uint_as_float(r[j * 4 + 0]), alpha, bv.x);
            o.y = fmaf(__uint_as_float(r[j * 4 + 1]), alpha, bv.y);
            o.z = fmaf(__uint_as_float(r[j * 4 + 2]), alpha, bv.z);
            o.w = fmaf(__uint_as_float(r[j * 4 + 3]), alpha, bv.w);
            if (doRelu) {
                o.x = fmaxf(o.x, 0.f); o.y = fmaxf(o.y, 0.f);
                o.z = fmaxf(o.z, 0.f); o.w = fmaxf(o.w, 0.f);
            }
            if (C) *(float4*)(C + crow + j * 4) = o;
            if (Ch) {
                bf16 h4[4], l4[4];
                split2b(o.x, h4[0], l4[0]); split2b(o.y, h4[1], l4[1]);
                split2b(o.z, h4[2], l4[2]); split2b(o.w, h4[3], l4[3]);
                uint2 hv, lv;
                hv.x = (uint32_t)__bfloat16_as_ushort(h4[0])
                     | ((uint32_t)__bfloat16_as_ushort(h4[1]) << 16);
                hv.y = (uint32_t)__bfloat16_as_ushort(h4[2])
                     | ((uint32_t)__bfloat16_as_ushort(h4[3]) << 16);
                lv.x = (uint32_t)__bfloat16_as_ushort(l4[0])
                     | ((uint32_t)__bfloat16_as_ushort(l4[1]) << 16);
                lv.y = (uint32_t)__bfloat16_as_ushort(l4[2])
                     | ((uint32_t)__bfloat16_as_ushort(l4[3]) << 16);
                *(uint2*)(Ch + crow + j * 4) = hv;
                *(uint2*)(Cl + crow + j * 4) = lv;
            }
        }
    }
    __syncthreads();
    if (wid == 0) {
        asm volatile("tcgen05.dealloc.cta_group::1.sync.aligned.b32 %0, %1;"
                     :: "r"(tmem), "r"(256u));
    }

#else  // ------- FFMA fallback (portable compile pass only; never selected) ---

    float (*As)[132] = (float(*)[132])(smem);
    float (*Bs)[132] = (float(*)[132])(smem + 16 * 132 * sizeof(float));

    const int arow = tid >> 2;
    const int akv  = (tid & 3) << 2;
    const int tx = tid & 15, ty = tid >> 4;
    const int m0 = ty << 2, n0 = tx << 2;

    auto rec4 = [](const bf16* ph2, const bf16* pl2, float* o) {
#pragma unroll
        for (int j = 0; j < 4; ++j)
            o[j] = __bfloat162float(ph2[j]) + __bfloat162float(pl2[j]);
    };

    for (int hh2 = 0; hh2 < 2; ++hh2) {
        const int bxe = bx * 2 + hh2;
        if (causal && bxe > by) continue;

        const bf16* Aph = Ah + (long)(by * 128 + arow) * lda + akv;
        const bf16* Apl = Al + (long)(by * 128 + arow) * lda + akv;
        const bf16* Bph = Bh + (long)(bxe * 128 + arow) * ldb + akv;
        const bf16* Bpl = Bl + (long)(bxe * 128 + arow) * ldb + akv;

        float acc[8][8];
#pragma unroll
        for (int i = 0; i < 8; ++i)
#pragma unroll
            for (int j = 0; j < 8; ++j) acc[i][j] = 0.f;

        const int ntiles = K >> 4;
        for (int t = 0; t < ntiles; ++t) {
            float a0[4], a1[4], b0[4], b1[4];
            rec4(Aph, Apl, a0);
            rec4(Aph + (long)64 * lda, Apl + (long)64 * lda, a1);
            rec4(Bph, Bpl, b0);
            rec4(Bph + (long)64 * ldb, Bpl + (long)64 * ldb, b1);
            __syncthreads();
#pragma unroll
            for (int j = 0; j < 4; ++j) {
                As[akv + j][arow]      = a0[j];
                As[akv + j][arow + 64] = a1[j];
                Bs[akv + j][arow]      = b0[j];
                Bs[akv + j][arow + 64] = b1[j];
            }
            __syncthreads();
#pragma unroll
            for (int k = 0; k < 16; ++k) {
                float4 av0 = *(const float4*)&As[k][m0];
                float4 av1 = *(const float4*)&As[k][m0 + 64];
                float4 bv0 = *(const float4*)&Bs[k][n0];
                float4 bv1 = *(const float4*)&Bs[k][n0 + 64];
                float av[8] = {av0.x, av0.y, av0.z, av0.w, av1.x, av1.y, av1.z, av1.w};
                float bv[8] = {bv0.x, bv0.y, bv0.z, bv0.w, bv1.x, bv1.y, bv1.z, bv1.w};
#pragma unroll
                for (int i = 0; i < 8; ++i)
#pragma unroll
                    for (int j = 0; j < 8; ++j)
                        acc[i][j] = fmaf(av[i], bv[j], acc[i][j]);
            }
            Aph += 16; Apl += 16; Bph += 16; Bpl += 16;
        }

#pragma unroll
        for (int i = 0; i < 8; ++i) {
            int m = by * 128 + m0 + ((i < 4) ? i : (64 + i - 4));
#pragma unroll
            for (int j = 0; j < 8; ++j) {
                int n = bxe * 128 + n0 + ((j < 4) ? j : (64 + j - 4));
                float bb = bias ? bias[n] : 0.f;
                float v = fmaf(acc[i][j], alpha, bb);
                v = doRelu ? fmaxf(v, 0.f) : v;
                long idx = (long)m * ldc + n;
                if (C) C[idx] = v;
                if (Ch) { bf16 hi, lo; split2b(v, hi, lo); Ch[idx] = hi; Cl[idx] = lo; }
            }
        }
        __syncthreads();
    }
#endif  // TC_OK
}

// ---------------------------------------------------------------------------
// 32x32 tiled transpose emitting bf16 hi/lo planes; batched over blockIdx.z.
// ---------------------------------------------------------------------------
__global__ void transpose_k(const float* __restrict__ in,
                            bf16* __restrict__ oh, bf16* __restrict__ ol,
                            int R, int Cc, long inStride, long outStride)
{
    in += (long)blockIdx.z * inStride;
    oh += (long)blockIdx.z * outStride;
    ol += (long)blockIdx.z * outStride;
    __shared__ float t[32][33];
    const int c0 = blockIdx.x * 32, r0 = blockIdx.y * 32;
    const int x = threadIdx.x, y = threadIdx.y;
#pragma unroll
    for (int i = 0; i < 32; i += 8)
        t[y + i][x] = in[(long)(r0 + y + i) * Cc + c0 + x];
    __syncthreads();
#pragma unroll
    for (int i = 0; i < 32; i += 8) {
        float v = t[x][y + i];
        bf16 hi, lo; split2b(v, hi, lo);
        long idx = (long)(c0 + y + i) * R + r0 + x;
        oh[idx] = hi; ol[idx] = lo;
    }
}

// ---------------------------------------------------------------------------
// Elementwise kernels
// ---------------------------------------------------------------------------
__global__ void embed_kernel(const int* __restrict__ x,
                             const float* __restrict__ tok,
                             const float* __restrict__ pos,
                             float* __restrict__ h,
                             bf16* __restrict__ hh, bf16* __restrict__ hl)
{
    int idx = blockIdx.x * 256 + threadIdx.x;
    int bt  = idx >> 9;
    int e   = idx & 511;
    int token = x[bt];
    float v = tok[(long)token * E_ + e] + pos[((bt & (T_ - 1)) << 9) + e];
    h[idx] = v;
    bf16 hi, lo; split2b(v, hi, lo);
    hh[idx] = hi; hl[idx] = lo;
}

__global__ void softmax_causal_kernel(const float* __restrict__ att,
                                      bf16* __restrict__ ah,
                                      bf16* __restrict__ al)
{
    const int i = blockIdx.x & (T_ - 1);
    const long base = (long)blockIdx.x * T_;
    const float* row = att + base;
    const int n = i + 1;
    const int tid = threadIdx.x, lane = tid & 31, w = tid >> 5;
    __shared__ float redm[4], reds[4];

    float mx = -INFINITY;
    for (int j = tid; j < n; j += 128) mx = fmaxf(mx, row[j]);
#pragma unroll
    for (int o = 16; o > 0; o >>= 1) mx = fmaxf(mx, __shfl_xor_sync(0xffffffffu, mx, o));
    if (lane == 0) redm[w] = mx;
    __syncthreads();
    mx = fmaxf(fmaxf(redm[0], redm[1]), fmaxf(redm[2], redm[3]));

    float s = 0.f;
    for (int j = tid; j < n; j += 128) s += expf(row[j] - mx);
#pragma unroll
    for (int o = 16; o > 0; o >>= 1) s += __shfl_xor_sync(0xffffffffu, s, o);
    if (lane == 0) reds[w] = s;
    __syncthreads();
    s = reds[0] + reds[1] + reds[2] + reds[3];

    const float inv = 1.f / s;
    for (int j = tid; j < T_; j += 128) {
        float p = (j < n) ? expf(row[j] - mx) * inv : 0.f;
        bf16 hi, lo; split2b(p, hi, lo);
        ah[base + j] = hi; al[base + j] = lo;
    }
}

// Residual add + LN; `parts` holds 4 split-K partials (stride pstride); bias added here.
__global__ void add_ln_kernel(const float* __restrict__ parts, long pstride,
                              const float* __restrict__ bias,
                              float* __restrict__ h,
                              bf16* __restrict__ hh, bf16* __restrict__ hl,
                              const float* __restrict__ gam,
                              const float* __restrict__ bet)
{
    const long row = blockIdx.x;
    float* hr = h + row * E_;
    const int tid = threadIdx.x, lane = tid & 31, w = tid >> 5;
    __shared__ float r1[4], r2[4];

    float x[4];
    float s = 0.f;
#pragma unroll
    for (int i = 0; i < 4; ++i) {
        int e = tid + i * 128;
        long idx = row * E_ + e;
        float a = parts[idx] + parts[pstride + idx]
                + parts[2 * pstride + idx] + parts[3 * pstride + idx]
                + bias[e];
        x[i] = a + hr[e];
        s += x[i];
    }
#pragma unroll
    for (int o = 16; o > 0; o >>= 1) s += __shfl_xor_sync(0xffffffffu, s, o);
    if (lane == 0) r1[w] = s;
    __syncthreads();
    const float m = (r1[0] + r1[1] + r1[2] + r1[3]) * (1.f / E_);

    float d2 = 0.f;
#pragma unroll
    for (int i = 0; i < 4; ++i) { float d = x[i] - m; d2 += d * d; }
#pragma unroll
    for (int o = 16; o > 0; o >>= 1) d2 += __shfl_xor_sync(0xffffffffu, d2, o);
    if (lane == 0) r2[w] = d2;
    __syncthreads();
    const float var = (r2[0] + r2[1] + r2[2] + r2[3]) * (1.f / E_);
    const float r = rsqrtf(var + 1e-5f);

#pragma unroll
    for (int i = 0; i < 4; ++i) {
        int e = tid + i * 128;
        float y = (x[i] - m) * r * gam[e] + bet[e];
        hr[e] = y;
        bf16 hi, lo; split2b(y, hi, lo);
        hh[row * E_ + e] = hi; hl[row * E_ + e] = lo;
    }
}

__global__ void emb_stats_kernel(const float* __restrict__ h,
                                 float* __restrict__ omean,
                                 float* __restrict__ omax)
{
    const int b = blockIdx.x, e = blockIdx.y * 32 + (threadIdx.x & 31);
    const int lane = threadIdx.x & 31, wy = threadIdx.x >> 5;
    __shared__ float ss[8][32], sm[8][32];
    float s = 0.f, m = -INFINITY;
    for (int t = wy; t < T_; t += 8) {
        float v = h[((long)(b * T_ + t)) * E_ + e];
        s += v; m = fmaxf(m, v);
    }
    ss[wy][lane] = s; sm[wy][lane] = m;
    __syncthreads();
    if (wy == 0) {
        float S = 0.f, M = -INFINITY;
#pragma unroll
        for (int w = 0; w < 8; ++w) { S += ss[w][lane]; M = fmaxf(M, sm[w][lane]); }
        omean[b * E_ + e] = S * (1.f / T_);
        omax [b * E_ + e] = M;
    }
}

__global__ void ls_partial_kernel(const float* __restrict__ logits,
                                  float* __restrict__ pm,
                                  float* __restrict__ ps)
{
    const int split = blockIdx.x & 3;
    const int tcol  = blockIdx.x >> 2;
    const int b     = tcol >> 5;
    const int lane  = threadIdx.x & 31, wy = threadIdx.x >> 5;
    const int t     = ((tcol & 31) << 5) + lane;
    const long base = (long)b * BNT_T + t;

    float mx = -INFINITY, s = 0.f;
    const int n0 = split * (NT_ / 4);
#pragma unroll 4
    for (int n = n0 + wy; n < n0 + NT_ / 4; n += 8) {
        float v = logits[base + (long)n * T_];
        if (v > mx) { s = s * __expf(mx - v) + 1.f; mx = v; }
        else        { s += __expf(v - mx); }
    }
    __shared__ float shm[8][32], shs[8][32];
    shm[wy][lane] = mx; shs[wy][lane] = s;
    __syncthreads();
    if (wy == 0) {
        float M = -INFINITY, S = 0.f;
#pragma unroll
        for (int w = 0; w < 8; ++w) {
            float m2 = shm[w][lane], s2 = shs[w][lane];
            if (m2 > M) { S = S * __expf(M - m2) + s2; M = m2; }
            else        { S += s2 * __expf(m2 - M); }
        }
        int idx = b * T_ + t;
        pm[idx * 4 + split] = M;
        ps[idx * 4 + split] = S;
    }
}

__global__ void ls_combine_kernel(const float* __restrict__ pm,
                                  const float* __restrict__ ps,
                                  float* __restrict__ z)
{
    int idx = blockIdx.x * 256 + threadIdx.x;
    if (idx >= BT_) return;
    float M = -INFINITY, S = 0.f;
#pragma unroll
    for (int k = 0; k < 4; ++k) {
        float m2 = pm[idx * 4 + k], s2 = ps[idx * 4 + k];
        if (m2 > M) { S = S * expf(M - m2) + s2; M = m2; }
        else        { S += s2 * expf(m2 - M); }
    }
    z[idx] = M + logf(S);
}

__global__ void ls_write_kernel(const float* __restrict__ logits,
                                const float* __restrict__ z,
                                float* __restrict__ out)
{
    long i4 = (long)blockIdx.x * 256 + threadIdx.x;
    long f  = i4 << 2;
    int  t  = (int)(f & (T_ - 1));
    int  b  = (f >= BNT_T) ? 1 : 0;
    float4 v  = *(const float4*)(logits + f);
    float4 zz = *(const float4*)(z + b * T_ + t);
    float4 o;
    o.x = v.x - zz.x; o.y = v.y - zz.y; o.z = v.z - zz.z; o.w = v.w - zz.w;
    *(float4*)(out + f) = o;
}

// ---------------------------------------------------------------------------
// Host-side launch helpers
// ---------------------------------------------------------------------------
static inline void gemm(int Mtiles, int Ntiles256, int K,
                        const bf16* Ah, const bf16* Al, int lda,
                        const bf16* Bh, const bf16* Bl, int ldb,
                        float* C, bf16* Ch, bf16* Cl, int ldc,
                        const float* bias,
                        float alpha, int relu, int causal,
                        int batches = 1, int innerCnt = 1,
                        long aO = 0, long aI = 0, long bO = 0, long bI = 0,
                        long cO = 0, long cI = 0)
{
    dim3 grid(Ntiles256, Mtiles, batches), blk(256);
    gemm_tc<<<grid, blk, SMEM_BYTES>>>(K, Ah, Al, lda, Bh, Bl, ldb,
                                       C, Ch, Cl, ldc, bias,
                                       alpha, relu, causal, innerCnt,
                                       aO, aI, bO, bI, cO, cI);
}

static inline void transp(const float* in, bf16* oh, bf16* ol, int R, int C,
                          int batch = 1, long inStride = 0, long outStride = 0)
{
    dim3 g(C / 32, R / 32, batch), b(32, 8);
    transpose_k<<<g, b>>>(in, oh, ol, R, C, inStride, outStride);
}

extern "C" void kernel_launch(void* const* d_in, const int* in_sizes, int n_in,
                              void* d_out, int out_size)
{
    const int*   x    = (const int*)  d_in[0];
    const float* tok  = (const float*)d_in[1];
    const float* pos  = (const float*)d_in[2];
    const float* Wq   = (const float*)d_in[3];
    const float* Wk   = (const float*)d_in[4];
    const float* Wv   = (const float*)d_in[5];
    const float* Wu   = (const float*)d_in[6];
    const float* bu   = (const float*)d_in[7];
    const float* g1   = (const float*)d_in[8];
    const float* b1n  = (const float*)d_in[9];
    const float* g2   = (const float*)d_in[10];
    const float* b2n  = (const float*)d_in[11];
    const float* W1   = (const float*)d_in[12];
    const float* bf1  = (const float*)d_in[13];
    const float* W2   = (const float*)d_in[14];
    const float* bf2  = (const float*)d_in[15];
    const float* Wp   = (const float*)d_in[16];
    const float* bp   = (const float*)d_in[17];
    float* out = (float*)d_out;

    cudaFuncSetAttribute(gemm_tc, cudaFuncAttributeMaxDynamicSharedMemorySize,
                         SMEM_BYTES);

    float *h, *att, *logits, *pm, *ps, *z;
    bf16 *hh, *hl, *qkh, *qkl, *vth, *vtl, *oh, *ol, *ath, *atl, *ffh, *ffl;
    cudaGetSymbolAddress((void**)&h,    g_h);
    cudaGetSymbolAddress((void**)&hh,   g_h_hi);
    cudaGetSymbolAddress((void**)&hl,   g_h_lo);
    cudaGetSymbolAddress((void**)&qkh,  g_qk_hi);
    cudaGetSymbolAddress((void**)&qkl,  g_qk_lo);
    cudaGetSymbolAddress((void**)&vth,  g_vt_hi);
    cudaGetSymbolAddress((void**)&vtl,  g_vt_lo);
    cudaGetSymbolAddress((void**)&oh,   g_o_hi);
    cudaGetSymbolAddress((void**)&ol,   g_o_lo);
    cudaGetSymbolAddress((void**)&att,  g_att);
    cudaGetSymbolAddress((void**)&ath,  g_at_hi);
    cudaGetSymbolAddress((void**)&atl,  g_at_lo);
    cudaGetSymbolAddress((void**)&ffh,  g_ff_hi);
    cudaGetSymbolAddress((void**)&ffl,  g_ff_lo);
    cudaGetSymbolAddress((void**)&logits, g_logits);
    cudaGetSymbolAddress((void**)&pm,   g_pm);
    cudaGetSymbolAddress((void**)&ps,   g_ps);
    cudaGetSymbolAddress((void**)&z,    g_z);

    bf16 *WqkTh, *WqkTl, *WvTh, *WvTl, *WuTh, *WuTl;
    bf16 *W1Th, *W1Tl, *W2Th, *W2Tl, *WpTh, *WpTl;
    cudaGetSymbolAddress((void**)&WqkTh, g_WqkT_hi);
    cudaGetSymbolAddress((void**)&WqkTl, g_WqkT_lo);
    cudaGetSymbolAddress((void**)&WvTh, g_WvT_hi);
    cudaGetSymbolAddress((void**)&WvTl, g_WvT_lo);
    cudaGetSymbolAddress((void**)&WuTh, g_WuT_hi);
    cudaGetSymbolAddress((void**)&WuTl, g_WuT_lo);
    cudaGetSymbolAddress((void**)&W1Th, g_W1T_hi);
    cudaGetSymbolAddress((void**)&W1Tl, g_W1T_lo);
    cudaGetSymbolAddress((void**)&W2Th, g_W2T_hi);
    cudaGetSymbolAddress((void**)&W2Tl, g_W2T_lo);
    cudaGetSymbolAddress((void**)&WpTh, g_WpT_hi);
    cudaGetSymbolAddress((void**)&WpTl, g_WpT_lo);

    // Weight transposes + bf16 hi/lo split, batched over L (7 launches total).
    const long wQK = (long)HE_ * E_;
    transp(Wq, WqkTh,            WqkTl,            E_,  HE_, L_, (long)E_ * HE_, wQK);
    transp(Wk, WqkTh + L_ * wQK, WqkTl + L_ * wQK, E_,  HE_, L_, (long)E_ * HE_, wQK);
    transp(Wv, WvTh, WvTl, E_,  HE_, L_, (long)E_ * HE_, wQK);
    transp(Wu, WuTh, WuTl, HE_, E_,  L_, (long)HE_ * E_, (long)E_ * HE_);
    transp(W1, W1Th, W1Tl, E_,  FF_, L_, (long)E_ * FF_, (long)FF_ * E_);
    transp(W2, W2Th, W2Tl, FF_, E_,  L_, (long)FF_ * E_, (long)E_ * FF_);
    transp(Wp, WpTh, WpTl, E_,  NT_, 1, 0, 0);

    embed_kernel<<<(BT_ * E_) / 256, 256>>>(x, tok, pos, h, hh, hl);

    const float qs = 0.21022410381342863f;   // 512^(-1/4)
    const long PS  = (long)BT_ * E_;          // split-K partial stride
    const long QKS = (long)BT_ * HE_;         // q->k output stride

    for (int l = 0; l < L_; ++l) {
        const long wqo = (long)l * HE_ * E_;
        const long wuo = (long)l * E_ * HE_;
        const long w1o = (long)l * FF_ * E_;
        const long w2o = (long)l * E_ * FF_;
        const float* bu_l  = bu  + (long)l * E_;
        const float* g1_l  = g1  + (long)l * E_;
        const float* b1_l  = b1n + (long)l * E_;
        const float* g2_l  = g2  + (long)l * E_;
        const float* b2_l  = b2n + (long)l * E_;
        const float* bf1_l = bf1 + (long)l * FF_;
        const float* bf2_l = bf2 + (long)l * E_;

        // q and k in ONE batched launch (batch 0 -> q, batch 1 -> k)
        gemm(16, 16, E_, hh, hl, E_, WqkTh + wqo, WqkTl + wqo, E_,
             nullptr, qkh, qkl, HE_, nullptr, qs, 0, 0,
             2, 1,
             0, 0,
             (long)L_ * wQK, 0,
             QKS, 0);
        // Vt (HE x BT) = WvT @ h^T -> pair
        gemm(32, 8, E_, WvTh + wqo, WvTl + wqo, E_, hh, hl, E_,
             nullptr, vth, vtl, BT_, nullptr, 1.f, 0, 0);

        // scores: att = q_bh @ k_bh^T (plain), causal tile skip
        gemm(8, 4, E_, qkh, qkl, HE_, qkh + QKS, qkl + QKS, HE_,
             att, nullptr, nullptr, T_, nullptr, 1.f, 0, 1,
             B_ * H_, H_,
             (long)T_ * HE_, (long)E_,
             (long)T_ * HE_, (long)E_,
             (long)H_ * T_ * T_, (long)T_ * T_);

        softmax_causal_kernel<<<B_ * H_ * T_, 128>>>(att, ath, atl);

        // o = att @ V -> pair
        gemm(8, 2, T_, ath, atl, T_, vth, vtl, BT_,
             nullptr, oh, ol, HE_, nullptr, 1.f, 0, 0,
             B_ * H_, H_,
             (long)H_ * T_ * T_, (long)T_ * T_,
             (long)T_,           (long)E_ * BT_,
             (long)T_ * HE_,     (long)E_);

        // unify heads: split-K=4 partials into att scratch (bias in add_ln)
        gemm(16, 2, HE_ / 4, oh, ol, HE_, WuTh + wuo, WuTl + wuo, HE_,
             att, nullptr, nullptr, E_, nullptr, 1.f, 0, 0,
             4, 4, 0, (long)(HE_ / 4), 0, (long)(HE_ / 4), 0, PS);
        add_ln_kernel<<<BT_, 128>>>(att, PS, bu_l, h, hh, hl, g1_l, b1_l);

        // FFN
        gemm(16, 8, E_, hh, hl, E_, W1Th + w1o, W1Tl + w1o, E_,
             nullptr, ffh, ffl, FF_, bf1_l, 1.f, 1, 0);
        gemm(16, 2, FF_ / 4, ffh, ffl, FF_, W2Th + w2o, W2Tl + w2o, FF_,
             att, nullptr, nullptr, E_, nullptr, 1.f, 0, 0,
             4, 4, 0, (long)(FF_ / 4), 0, (long)(FF_ / 4), 0, PS);
        add_ln_kernel<<<BT_, 128>>>(att, PS, bf2_l, h, hh, hl, g2_l, b2_l);
    }

    // emb_mean / emb_max (flattened after the log_softmax block)
    if ((long)out_size >= LOGITS_N + 2L * B_ * E_) {
        emb_stats_kernel<<<dim3(B_, E_ / 32), 256>>>(
            h, out + LOGITS_N, out + LOGITS_N + B_ * E_);
    }

    // vocab projection: N=32000 -> 125 tiles
    gemm(16, NT_ / 256, E_, hh, hl, E_, WpTh, WpTl, E_,
         logits, nullptr, nullptr, NT_, bp, 1.f, 0, 0);

    // log_softmax over axis 1 of the raw (B, NT, T) reshape
    ls_partial_kernel<<<256, 256>>>(logits, pm, ps);
    ls_combine_kernel<<<(BT_ + 255) / 256, 256>>>(pm, ps, z);
    ls_write_kernel<<<(int)(LOGITS_N / 4 / 256), 256>>>(logits, z, out);
}